// round 1
// baseline (speedup 1.0000x reference)
#include <cuda_runtime.h>

#define B_ROWS 65536
#define TILE   128

// f-features scratch: 65536 x 57 fp32 (~15 MB). Static __device__ array per rules.
__device__ float g_f[B_ROWS * 57];

// ---------------------------------------------------------------------------
// Kernel 1: fused C-MLP (4->128->3), N-MLP (54->128->54), F-MLP (57->128->57)
// One CTA = 128 rows, one thread = one row. Weights staged in SMEM transposed
// so inner-loop weight loads are warp-uniform (broadcast) vectorized LDS.
// ---------------------------------------------------------------------------
__global__ __launch_bounds__(128) void k_features(
    const float* __restrict__ x,
    const float* __restrict__ Cw1, const float* __restrict__ Cb1,
    const float* __restrict__ Cw2, const float* __restrict__ Cb2,
    const float* __restrict__ Nw1, const float* __restrict__ Nb1,
    const float* __restrict__ Nw2, const float* __restrict__ Nb2,
    const float* __restrict__ Fw1, const float* __restrict__ Fb1,
    const float* __restrict__ Fw2, const float* __restrict__ Fb2)
{
    extern __shared__ float sm[];
    float* xs   = sm;            // 128*60  (x tile, row-major, pad 60)
    float* fb   = xs + 7680;     // 128*60  (f = [c(3), n(54)] per row)
    float* w1t  = fb + 7680;     // 128*60  (layer-1 weights, transposed [j][k])
    float* w2s  = w1t + 7680;    // 128*60  (layer-2 weights, [j][m])
    float* cw1t = w2s + 7680;    // 128*4
    float* cw2  = cw1t + 512;    // 128*4
    float* cb1  = cw2 + 512;     // 128
    float* cb2  = cb1 + 128;     // 4
    float* b1s  = cb2 + 4;       // 128
    float* b2s  = b1s + 128;     // 60

    const int tid  = threadIdx.x;
    const int row0 = blockIdx.x * TILE;

    // ---- Phase A: load x tile + C weights + N weights ----
    for (int i = tid; i < TILE * 58; i += 128) {
        int r = i / 58, k = i - r * 58;
        xs[r * 60 + k] = x[(row0 + r) * 58 + k];
    }
    for (int i = tid; i < 4 * 128; i += 128) {          // C_w1 (4,128) -> [j][k]
        int k = i >> 7, j = i & 127;
        cw1t[j * 4 + k] = Cw1[i];
    }
    for (int i = tid; i < 128 * 3; i += 128) {          // C_w2 (128,3) -> [j][m] pad4
        int j = i / 3, m = i - j * 3;
        cw2[j * 4 + m] = Cw2[i];
    }
    cb1[tid] = Cb1[tid];
    if (tid < 4) cb2[tid] = (tid < 3) ? Cb2[tid] : 0.f;
    for (int i = tid; i < 54 * 128; i += 128) {         // N_w1 (54,128) -> [j][k]
        int k = i >> 7, j = i & 127;
        w1t[j * 60 + k] = Nw1[i];
    }
    for (int i = tid; i < 128 * 54; i += 128) {         // N_w2 (128,54) -> [j][m]
        int j = i / 54, m = i - j * 54;
        w2s[j * 60 + m] = Nw2[i];
    }
    b1s[tid] = Nb1[tid];
    if (tid < 54) b2s[tid] = Nb2[tid];
    __syncthreads();

    // ---- Stage C ----
    {
        float cx0 = xs[tid * 60 + 0], cx1 = xs[tid * 60 + 1];
        float cx2 = xs[tid * 60 + 2], cx3 = xs[tid * 60 + 3];
        float c0 = cb2[0], c1 = cb2[1], c2 = cb2[2];
        for (int j = 0; j < 128; ++j) {
            const float* w = &cw1t[j * 4];
            float h = cb1[j] + cx0 * w[0] + cx1 * w[1] + cx2 * w[2] + cx3 * w[3];
            h = fmaxf(h, 0.f);
            const float* w2 = &cw2[j * 4];
            c0 += h * w2[0]; c1 += h * w2[1]; c2 += h * w2[2];
        }
        fb[tid * 60 + 0] = c0; fb[tid * 60 + 1] = c1; fb[tid * 60 + 2] = c2;
    }

    // ---- Stage N ----
    {
        float nin[54];
#pragma unroll
        for (int k = 0; k < 54; ++k) nin[k] = xs[tid * 60 + 4 + k];
        float acc[54];
#pragma unroll
        for (int m = 0; m < 54; ++m) acc[m] = b2s[m];
        for (int j = 0; j < 128; ++j) {
            const float* w = &w1t[j * 60];
            float h0 = 0.f, h1 = 0.f, h2 = 0.f, h3 = 0.f;
#pragma unroll
            for (int k = 0; k < 52; k += 4) {
                h0 += nin[k] * w[k];     h1 += nin[k + 1] * w[k + 1];
                h2 += nin[k + 2] * w[k + 2]; h3 += nin[k + 3] * w[k + 3];
            }
            h0 += nin[52] * w[52];
            h1 += nin[53] * w[53];
            float h = fmaxf((h0 + h1) + (h2 + h3) + b1s[j], 0.f);
            const float* w2 = &w2s[j * 60];
#pragma unroll
            for (int m = 0; m < 54; ++m) acc[m] += h * w2[m];
        }
#pragma unroll
        for (int m = 0; m < 54; ++m) fb[tid * 60 + 3 + m] = acc[m];
    }
    __syncthreads();

    // ---- Load F weights (reuse w1t / w2s buffers) ----
    for (int i = tid; i < 57 * 128; i += 128) {         // F_w1 (57,128) -> [j][k]
        int k = i >> 7, j = i & 127;
        w1t[j * 60 + k] = Fw1[i];
    }
    for (int i = tid; i < 128 * 57; i += 128) {         // F_w2 (128,57) -> [j][m]
        int j = i / 57, m = i - j * 57;
        w2s[j * 60 + m] = Fw2[i];
    }
    b1s[tid] = Fb1[tid];
    if (tid < 57) b2s[tid] = Fb2[tid];
    __syncthreads();

    // ---- Stage F ----
    {
        float fin[57];
#pragma unroll
        for (int k = 0; k < 57; ++k) fin[k] = fb[tid * 60 + k];
        float acc[57];
#pragma unroll
        for (int m = 0; m < 57; ++m) acc[m] = b2s[m];
        for (int j = 0; j < 128; ++j) {
            const float* w = &w1t[j * 60];
            float h0 = 0.f, h1 = 0.f, h2 = 0.f, h3 = 0.f;
#pragma unroll
            for (int k = 0; k < 56; k += 4) {
                h0 += fin[k] * w[k];     h1 += fin[k + 1] * w[k + 1];
                h2 += fin[k + 2] * w[k + 2]; h3 += fin[k + 3] * w[k + 3];
            }
            h0 += fin[56] * w[56];
            float h = fmaxf((h0 + h1) + (h2 + h3) + b1s[j], 0.f);
            const float* w2 = &w2s[j * 60];
#pragma unroll
            for (int m = 0; m < 57; ++m) acc[m] += h * w2[m];
        }
        // stage result into xs (no longer needed) for coalesced global write
#pragma unroll
        for (int m = 0; m < 57; ++m) xs[tid * 60 + m] = acc[m];
    }
    __syncthreads();
    for (int i = tid; i < TILE * 57; i += 128) {
        int r = i / 57, m = i - r * 57;
        g_f[(row0 + r) * 57 + m] = xs[r * 60 + m];
    }
}

// ---------------------------------------------------------------------------
// Kernel 2: O stage. grid = (512 row tiles, 6 branch groups of 9).
// f row lives in registers; per-branch W1 (57x128) staged transposed in SMEM
// (uniform broadcast LDS.128 in the dot loop -> 4 FMAs per load).
// Softmax over 3 logits, output staged in SMEM, written coalesced.
// ---------------------------------------------------------------------------
__global__ __launch_bounds__(128) void k_branches(
    const float* __restrict__ Ow1, const float* __restrict__ Ob1,
    const float* __restrict__ Ow2, const float* __restrict__ Ob2,
    float* __restrict__ out)
{
    extern __shared__ float sm[];
    float* fs  = sm;           // 128*57
    float* w1t = fs + 7296;    // 128*60
    float* w2s = w1t + 7680;   // 128*4
    float* b1s = w2s + 512;    // 128
    float* b2s = b1s + 128;    // 4
    float* ob  = b2s + 4;      // 128*28 (27 outputs per row, pad 28)

    const int tid  = threadIdx.x;
    const int row0 = blockIdx.x * TILE;
    const int g    = blockIdx.y;   // 0..5
    const int n0   = g * 9;

    for (int i = tid; i < TILE * 57; i += 128) fs[i] = g_f[row0 * 57 + i];
    __syncthreads();

    float fin[57];
#pragma unroll
    for (int k = 0; k < 57; ++k) fin[k] = fs[tid * 57 + k];

    for (int nb = 0; nb < 9; ++nb) {
        const int n = n0 + nb;
        // stage branch weights: O_w1[n] (57,128) -> w1t[j][k]
        for (int i = tid; i < 57 * 128; i += 128) {
            int k = i >> 7, j = i & 127;
            w1t[j * 60 + k] = Ow1[n * 7296 + i];
        }
        for (int i = tid; i < 128 * 3; i += 128) {   // O_w2[n] (128,3) -> [j][m] pad4
            int j = i / 3, m = i - j * 3;
            w2s[j * 4 + m] = Ow2[n * 384 + i];
        }
        b1s[tid] = Ob1[n * 128 + tid];
        if (tid < 4) b2s[tid] = (tid < 3) ? Ob2[n * 3 + tid] : 0.f;
        __syncthreads();

        float l0 = b2s[0], l1 = b2s[1], l2 = b2s[2];
        for (int j = 0; j < 128; ++j) {
            const float* w = &w1t[j * 60];
            float h0 = 0.f, h1 = 0.f, h2 = 0.f, h3 = 0.f;
#pragma unroll
            for (int k = 0; k < 56; k += 4) {
                h0 += fin[k] * w[k];     h1 += fin[k + 1] * w[k + 1];
                h2 += fin[k + 2] * w[k + 2]; h3 += fin[k + 3] * w[k + 3];
            }
            h0 += fin[56] * w[56];
            float h = fmaxf((h0 + h1) + (h2 + h3) + b1s[j], 0.f);
            const float* w2 = &w2s[j * 4];
            l0 += h * w2[0]; l1 += h * w2[1]; l2 += h * w2[2];
        }
        // softmax over 3
        float mx = fmaxf(l0, fmaxf(l1, l2));
        float e0 = __expf(l0 - mx), e1 = __expf(l1 - mx), e2 = __expf(l2 - mx);
        float inv = 1.f / (e0 + e1 + e2);
        ob[tid * 28 + nb * 3 + 0] = e0 * inv;
        ob[tid * 28 + nb * 3 + 1] = e1 * inv;
        ob[tid * 28 + nb * 3 + 2] = e2 * inv;
        __syncthreads();   // protect w1t/w2s reuse AND ob completion
    }

    // coalesced output write: 27 contiguous floats per row per group
    for (int i = tid; i < TILE * 27; i += 128) {
        int r = i / 27, c = i - r * 27;
        out[(row0 + r) * 162 + g * 27 + c] = ob[r * 28 + c];
    }
}

// ---------------------------------------------------------------------------
extern "C" void kernel_launch(void* const* d_in, const int* in_sizes, int n_in,
                              void* d_out, int out_size)
{
    const float* x   = (const float*)d_in[0];
    const float* Cw1 = (const float*)d_in[1];
    const float* Cb1 = (const float*)d_in[2];
    const float* Cw2 = (const float*)d_in[3];
    const float* Cb2 = (const float*)d_in[4];
    const float* Nw1 = (const float*)d_in[5];
    const float* Nb1 = (const float*)d_in[6];
    const float* Nw2 = (const float*)d_in[7];
    const float* Nb2 = (const float*)d_in[8];
    const float* Fw1 = (const float*)d_in[9];
    const float* Fb1 = (const float*)d_in[10];
    const float* Fw2 = (const float*)d_in[11];
    const float* Fb2 = (const float*)d_in[12];
    const float* Ow1 = (const float*)d_in[13];
    const float* Ob1 = (const float*)d_in[14];
    const float* Ow2 = (const float*)d_in[15];
    const float* Ob2 = (const float*)d_in[16];
    float* out = (float*)d_out;

    const size_t smem1 = 32064 * sizeof(float);   // 128256 B
    const size_t smem2 = 19204 * sizeof(float);   //  76816 B
    cudaFuncSetAttribute(k_features, cudaFuncAttributeMaxDynamicSharedMemorySize, (int)smem1);
    cudaFuncSetAttribute(k_branches, cudaFuncAttributeMaxDynamicSharedMemorySize, (int)smem2);

    k_features<<<B_ROWS / TILE, 128, smem1>>>(
        x, Cw1, Cb1, Cw2, Cb2, Nw1, Nb1, Nw2, Nb2, Fw1, Fb1, Fw2, Fb2);

    dim3 grid2(B_ROWS / TILE, 6);
    k_branches<<<grid2, 128, smem2>>>(Ow1, Ob1, Ow2, Ob2, out);
}

// round 2
// speedup vs baseline: 1.6145x; 1.6145x over previous
#include <cuda_runtime.h>

#define B_ROWS 65536
#define TILE   128

typedef unsigned long long u64;

__device__ __forceinline__ u64 pk2(float lo, float hi) {
    u64 r; asm("mov.b64 %0, {%1, %2};" : "=l"(r) : "f"(lo), "f"(hi)); return r;
}
__device__ __forceinline__ void up2(u64 v, float& lo, float& hi) {
    asm("mov.b64 {%0, %1}, %2;" : "=f"(lo), "=f"(hi) : "l"(v));
}
__device__ __forceinline__ void ffma2(u64& d, u64 a, u64 b) {
    asm("fma.rn.f32x2 %0, %1, %2, %0;" : "+l"(d) : "l"(a), "l"(b));
}

// f-features scratch: 65536 x 60 fp32 (padded stride for aligned float4 loads).
__device__ float g_f[B_ROWS * 60];

// ---------------------------------------------------------------------------
// Kernel 1: fused C-MLP (4->128->3), N-MLP (54->128->54), F-MLP (57->128->57)
// One CTA = 128 rows, one thread = one row (unchanged from R1 except g_f stride).
// ---------------------------------------------------------------------------
__global__ __launch_bounds__(128) void k_features(
    const float* __restrict__ x,
    const float* __restrict__ Cw1, const float* __restrict__ Cb1,
    const float* __restrict__ Cw2, const float* __restrict__ Cb2,
    const float* __restrict__ Nw1, const float* __restrict__ Nb1,
    const float* __restrict__ Nw2, const float* __restrict__ Nb2,
    const float* __restrict__ Fw1, const float* __restrict__ Fb1,
    const float* __restrict__ Fw2, const float* __restrict__ Fb2)
{
    extern __shared__ float sm[];
    float* xs   = sm;            // 128*60
    float* fb   = xs + 7680;     // 128*60
    float* w1t  = fb + 7680;     // 128*60
    float* w2s  = w1t + 7680;    // 128*60
    float* cw1t = w2s + 7680;    // 128*4
    float* cw2  = cw1t + 512;    // 128*4
    float* cb1  = cw2 + 512;     // 128
    float* cb2  = cb1 + 128;     // 4
    float* b1s  = cb2 + 4;       // 128
    float* b2s  = b1s + 128;     // 60

    const int tid  = threadIdx.x;
    const int row0 = blockIdx.x * TILE;

    for (int i = tid; i < TILE * 58; i += 128) {
        int r = i / 58, k = i - r * 58;
        xs[r * 60 + k] = x[(row0 + r) * 58 + k];
    }
    for (int i = tid; i < 4 * 128; i += 128) {
        int k = i >> 7, j = i & 127;
        cw1t[j * 4 + k] = Cw1[i];
    }
    for (int i = tid; i < 128 * 3; i += 128) {
        int j = i / 3, m = i - j * 3;
        cw2[j * 4 + m] = Cw2[i];
    }
    cb1[tid] = Cb1[tid];
    if (tid < 4) cb2[tid] = (tid < 3) ? Cb2[tid] : 0.f;
    for (int i = tid; i < 54 * 128; i += 128) {
        int k = i >> 7, j = i & 127;
        w1t[j * 60 + k] = Nw1[i];
    }
    for (int i = tid; i < 128 * 54; i += 128) {
        int j = i / 54, m = i - j * 54;
        w2s[j * 60 + m] = Nw2[i];
    }
    b1s[tid] = Nb1[tid];
    if (tid < 54) b2s[tid] = Nb2[tid];
    __syncthreads();

    // ---- Stage C ----
    {
        float cx0 = xs[tid * 60 + 0], cx1 = xs[tid * 60 + 1];
        float cx2 = xs[tid * 60 + 2], cx3 = xs[tid * 60 + 3];
        float c0 = cb2[0], c1 = cb2[1], c2 = cb2[2];
        for (int j = 0; j < 128; ++j) {
            const float* w = &cw1t[j * 4];
            float h = cb1[j] + cx0 * w[0] + cx1 * w[1] + cx2 * w[2] + cx3 * w[3];
            h = fmaxf(h, 0.f);
            const float* w2 = &cw2[j * 4];
            c0 += h * w2[0]; c1 += h * w2[1]; c2 += h * w2[2];
        }
        fb[tid * 60 + 0] = c0; fb[tid * 60 + 1] = c1; fb[tid * 60 + 2] = c2;
    }

    // ---- Stage N ----
    {
        float nin[54];
#pragma unroll
        for (int k = 0; k < 54; ++k) nin[k] = xs[tid * 60 + 4 + k];
        float acc[54];
#pragma unroll
        for (int m = 0; m < 54; ++m) acc[m] = b2s[m];
        for (int j = 0; j < 128; ++j) {
            const float* w = &w1t[j * 60];
            float h0 = 0.f, h1 = 0.f, h2 = 0.f, h3 = 0.f;
#pragma unroll
            for (int k = 0; k < 52; k += 4) {
                h0 += nin[k] * w[k];         h1 += nin[k + 1] * w[k + 1];
                h2 += nin[k + 2] * w[k + 2]; h3 += nin[k + 3] * w[k + 3];
            }
            h0 += nin[52] * w[52];
            h1 += nin[53] * w[53];
            float h = fmaxf((h0 + h1) + (h2 + h3) + b1s[j], 0.f);
            const float* w2 = &w2s[j * 60];
#pragma unroll
            for (int m = 0; m < 54; ++m) acc[m] += h * w2[m];
        }
#pragma unroll
        for (int m = 0; m < 54; ++m) fb[tid * 60 + 3 + m] = acc[m];
    }
    __syncthreads();

    for (int i = tid; i < 57 * 128; i += 128) {
        int k = i >> 7, j = i & 127;
        w1t[j * 60 + k] = Fw1[i];
    }
    for (int i = tid; i < 128 * 57; i += 128) {
        int j = i / 57, m = i - j * 57;
        w2s[j * 60 + m] = Fw2[i];
    }
    b1s[tid] = Fb1[tid];
    if (tid < 57) b2s[tid] = Fb2[tid];
    __syncthreads();

    // ---- Stage F ----
    {
        float fin[57];
#pragma unroll
        for (int k = 0; k < 57; ++k) fin[k] = fb[tid * 60 + k];
        float acc[57];
#pragma unroll
        for (int m = 0; m < 57; ++m) acc[m] = b2s[m];
        for (int j = 0; j < 128; ++j) {
            const float* w = &w1t[j * 60];
            float h0 = 0.f, h1 = 0.f, h2 = 0.f, h3 = 0.f;
#pragma unroll
            for (int k = 0; k < 56; k += 4) {
                h0 += fin[k] * w[k];         h1 += fin[k + 1] * w[k + 1];
                h2 += fin[k + 2] * w[k + 2]; h3 += fin[k + 3] * w[k + 3];
            }
            h0 += fin[56] * w[56];
            float h = fmaxf((h0 + h1) + (h2 + h3) + b1s[j], 0.f);
            const float* w2 = &w2s[j * 60];
#pragma unroll
            for (int m = 0; m < 57; ++m) acc[m] += h * w2[m];
        }
#pragma unroll
        for (int m = 0; m < 57; ++m) xs[tid * 60 + m] = acc[m];
    }
    __syncthreads();
    for (int i = tid; i < TILE * 57; i += 128) {
        int r = i / 57, m = i - r * 57;
        g_f[(row0 + r) * 60 + m] = xs[r * 60 + m];
    }
}

// ---------------------------------------------------------------------------
// Kernel 2: O stage, v2.
// 2 rows per thread (fin in registers, packed f32x2 k-pairs), f32x2 FMAs.
// CTA = 128 threads = 256 rows; grid = (256 row tiles, 6 branch groups of 9).
// Per hidden unit j: 15 LDS (14x LDS.128 + LDS.64) feed 58 FFMA2 (2 rows).
// ---------------------------------------------------------------------------
__global__ __launch_bounds__(128) void k_branches(
    const float* __restrict__ Ow1, const float* __restrict__ Ob1,
    const float* __restrict__ Ow2, const float* __restrict__ Ob2,
    float* __restrict__ out)
{
    extern __shared__ float sm[];
    float* w1t = sm;            // 128*60 (layer-1 weights [j][k], k 57..59 zero)
    float* w2s = w1t + 7680;    // 128*4
    float* b1s = w2s + 512;     // 128
    float* ob  = b1s + 128;     // 256*27
    // total 15232 floats = 60928 B

    const int tid  = threadIdx.x;
    const int row0 = blockIdx.x * 256;
    const int g    = blockIdx.y;      // 0..5
    const int n0   = g * 9;
    const int rA   = row0 + tid;
    const int rB   = rA + 128;

    // fin for both rows -> packed f32x2 registers (29 pairs each, last padded 0)
    u64 fa[29], fbp[29];
    {
        const float4* pa = (const float4*)(g_f + rA * 60);
        const float4* pb = (const float4*)(g_f + rB * 60);
#pragma unroll
        for (int i = 0; i < 14; ++i) {
            float4 va = pa[i], vb = pb[i];
            fa[2 * i]      = pk2(va.x, va.y);
            fa[2 * i + 1]  = pk2(va.z, va.w);
            fbp[2 * i]     = pk2(vb.x, vb.y);
            fbp[2 * i + 1] = pk2(vb.z, vb.w);
        }
        fa[28]  = pk2(g_f[rA * 60 + 56], 0.f);
        fbp[28] = pk2(g_f[rB * 60 + 56], 0.f);
    }

    for (int nb = 0; nb < 9; ++nb) {
        const int n = n0 + nb;
        __syncthreads();   // previous iteration done with w1t/w2s/b1s
        // stage branch weights: O_w1[n] (57,128) -> w1t[j][k], coalesced reads
        for (int i = tid; i < 57 * 128; i += 128) {
            int k = i >> 7, j = i & 127;
            w1t[j * 60 + k] = Ow1[n * 7296 + i];
        }
        w1t[tid * 60 + 57] = 0.f;
        w1t[tid * 60 + 58] = 0.f;
        w1t[tid * 60 + 59] = 0.f;
        for (int i = tid; i < 128 * 3; i += 128) {
            int j = i / 3, m = i - j * 3;
            w2s[j * 4 + m] = Ow2[n * 384 + i];
        }
        w2s[tid * 4 + 3] = 0.f;
        b1s[tid] = Ob1[n * 128 + tid];
        __syncthreads();

        float lA0 = Ob2[n * 3 + 0], lA1 = Ob2[n * 3 + 1], lA2 = Ob2[n * 3 + 2];
        float lB0 = lA0, lB1 = lA1, lB2 = lA2;

        for (int j = 0; j < 128; ++j) {
            const ulonglong2* wp = (const ulonglong2*)(w1t + j * 60);
            u64 a0 = 0, a1 = 0, b0 = 0, b1 = 0;
#pragma unroll
            for (int i = 0; i < 14; ++i) {
                ulonglong2 w = wp[i];
                ffma2(a0, fa[2 * i],      w.x);
                ffma2(a1, fa[2 * i + 1],  w.y);
                ffma2(b0, fbp[2 * i],     w.x);
                ffma2(b1, fbp[2 * i + 1], w.y);
            }
            {
                u64 wl = *(const u64*)(w1t + j * 60 + 56);  // (w56, 0)
                ffma2(a0, fa[28],  wl);
                ffma2(b0, fbp[28], wl);
            }
            float bj = b1s[j];
            float p, q, r, s;
            up2(a0, p, q); up2(a1, r, s);
            float hA = fmaxf(((p + r) + (q + s)) + bj, 0.f);
            up2(b0, p, q); up2(b1, r, s);
            float hB = fmaxf(((p + r) + (q + s)) + bj, 0.f);
            float4 w2 = *(const float4*)(w2s + j * 4);
            lA0 += hA * w2.x; lA1 += hA * w2.y; lA2 += hA * w2.z;
            lB0 += hB * w2.x; lB1 += hB * w2.y; lB2 += hB * w2.z;
        }

        // softmax (3-way) for both rows, stage into ob
        {
            float mx = fmaxf(lA0, fmaxf(lA1, lA2));
            float e0 = __expf(lA0 - mx), e1 = __expf(lA1 - mx), e2 = __expf(lA2 - mx);
            float inv = 1.f / (e0 + e1 + e2);
            ob[tid * 27 + nb * 3 + 0] = e0 * inv;
            ob[tid * 27 + nb * 3 + 1] = e1 * inv;
            ob[tid * 27 + nb * 3 + 2] = e2 * inv;
        }
        {
            float mx = fmaxf(lB0, fmaxf(lB1, lB2));
            float e0 = __expf(lB0 - mx), e1 = __expf(lB1 - mx), e2 = __expf(lB2 - mx);
            float inv = 1.f / (e0 + e1 + e2);
            ob[(tid + 128) * 27 + nb * 3 + 0] = e0 * inv;
            ob[(tid + 128) * 27 + nb * 3 + 1] = e1 * inv;
            ob[(tid + 128) * 27 + nb * 3 + 2] = e2 * inv;
        }
    }
    __syncthreads();

    // coalesced output: 256 rows x 27 contiguous floats for this group
    for (int i = tid; i < 256 * 27; i += 128) {
        int r = i / 27, c = i - r * 27;
        out[(row0 + r) * 162 + g * 27 + c] = ob[i];
    }
}

// ---------------------------------------------------------------------------
extern "C" void kernel_launch(void* const* d_in, const int* in_sizes, int n_in,
                              void* d_out, int out_size)
{
    const float* x   = (const float*)d_in[0];
    const float* Cw1 = (const float*)d_in[1];
    const float* Cb1 = (const float*)d_in[2];
    const float* Cw2 = (const float*)d_in[3];
    const float* Cb2 = (const float*)d_in[4];
    const float* Nw1 = (const float*)d_in[5];
    const float* Nb1 = (const float*)d_in[6];
    const float* Nw2 = (const float*)d_in[7];
    const float* Nb2 = (const float*)d_in[8];
    const float* Fw1 = (const float*)d_in[9];
    const float* Fb1 = (const float*)d_in[10];
    const float* Fw2 = (const float*)d_in[11];
    const float* Fb2 = (const float*)d_in[12];
    const float* Ow1 = (const float*)d_in[13];
    const float* Ob1 = (const float*)d_in[14];
    const float* Ow2 = (const float*)d_in[15];
    const float* Ob2 = (const float*)d_in[16];
    float* out = (float*)d_out;

    const size_t smem1 = 32064 * sizeof(float);   // 128256 B
    const size_t smem2 = 15232 * sizeof(float);   //  60928 B
    cudaFuncSetAttribute(k_features, cudaFuncAttributeMaxDynamicSharedMemorySize, (int)smem1);
    cudaFuncSetAttribute(k_branches, cudaFuncAttributeMaxDynamicSharedMemorySize, (int)smem2);

    k_features<<<B_ROWS / TILE, 128, smem1>>>(
        x, Cw1, Cb1, Cw2, Cb2, Nw1, Nb1, Nw2, Nb2, Fw1, Fb1, Fw2, Fb2);

    dim3 grid2(B_ROWS / 256, 6);
    k_branches<<<grid2, 128, smem2>>>(Ow1, Ob1, Ow2, Ob2, out);
}

// round 4
// speedup vs baseline: 4.1465x; 2.5683x over previous
#include <cuda_runtime.h>
#include <cuda_fp16.h>
#include <cstdint>

#define B_ROWS 65536
#define NTILES 512          // 65536 / 128
#define NB     54

// ========================= device scratch ===================================
// f features, fp16, pre-swizzled SW128 A-tile images: 512 tiles x (128 rows x 64 k)
__device__ __align__(16) __half2 g_fh2[NTILES * 4096];
// O_w1 fp16, pre-swizzled SW128 B-tile images: 54 x (128 j x 64 k)
__device__ __align__(16) __half g_w1h[NB * 8192];

// ============================= PTX helpers =================================
__device__ __forceinline__ uint32_t smem_u32(const void* p) {
    uint32_t a;
    asm("{ .reg .u64 t; cvta.to.shared.u64 t, %1; cvt.u32.u64 %0, t; }"
        : "=r"(a) : "l"(p));
    return a;
}
__device__ __forceinline__ void ldsm_x4(uint32_t addr, uint32_t& r0, uint32_t& r1,
                                        uint32_t& r2, uint32_t& r3) {
    asm volatile("ldmatrix.sync.aligned.m8n8.x4.shared.b16 {%0,%1,%2,%3}, [%4];"
                 : "=r"(r0), "=r"(r1), "=r"(r2), "=r"(r3) : "r"(addr));
}
__device__ __forceinline__ void mma16816(float& d0, float& d1, float& d2, float& d3,
                                         uint32_t a0, uint32_t a1, uint32_t a2, uint32_t a3,
                                         uint32_t b0, uint32_t b1) {
    asm volatile("mma.sync.aligned.m16n8k16.row.col.f32.f16.f16.f32 "
                 "{%0,%1,%2,%3}, {%4,%5,%6,%7}, {%8,%9}, {%0,%1,%2,%3};"
                 : "+f"(d0), "+f"(d1), "+f"(d2), "+f"(d3)
                 : "r"(a0), "r"(a1), "r"(a2), "r"(a3), "r"(b0), "r"(b1));
}
__device__ __forceinline__ uint32_t sw128(uint32_t off) {
    return off ^ ((off >> 3) & 0x70);
}

// ============================================================================
// Weight convert: O_w1 (54,57,128) f32 -> per-branch swizzled fp16 tile image.
// B[j][k] = O_w1[n][k][j], k 57..63 zero-padded.
// ============================================================================
__global__ __launch_bounds__(256) void k_convert_w(const float* __restrict__ Ow1)
{
    int idx = blockIdx.x * 256 + threadIdx.x;   // < 54*8192
    int j = idx & 127;
    int k = (idx >> 7) & 63;
    int n = idx >> 13;
    float v = (k < 57) ? Ow1[n * 7296 + k * 128 + j] : 0.f;
    unsigned sw = sw128((unsigned)(j * 128 + k * 2));
    g_w1h[n * 8192 + (sw >> 1)] = __float2half(v);
}

// ============================================================================
// Kernel 1: fused C / N / F MLPs (fp32); writes f as fp16 swizzled A image.
// (unchanged from R2/R3 working version)
// ============================================================================
__global__ __launch_bounds__(128) void k_features(
    const float* __restrict__ x,
    const float* __restrict__ Cw1, const float* __restrict__ Cb1,
    const float* __restrict__ Cw2, const float* __restrict__ Cb2,
    const float* __restrict__ Nw1, const float* __restrict__ Nb1,
    const float* __restrict__ Nw2, const float* __restrict__ Nb2,
    const float* __restrict__ Fw1, const float* __restrict__ Fb1,
    const float* __restrict__ Fw2, const float* __restrict__ Fb2)
{
    extern __shared__ float sm[];
    float* xs   = sm;            // 128*60
    float* fb   = xs + 7680;     // 128*60
    float* w1t  = fb + 7680;     // 128*60
    float* w2s  = w1t + 7680;    // 128*60
    float* cw1t = w2s + 7680;    // 128*4
    float* cw2  = cw1t + 512;    // 128*4
    float* cb1  = cw2 + 512;     // 128
    float* cb2  = cb1 + 128;     // 4
    float* b1s  = cb2 + 4;       // 128
    float* b2s  = b1s + 128;     // 60

    const int tid  = threadIdx.x;
    const int row0 = blockIdx.x * 128;

    for (int i = tid; i < 128 * 58; i += 128) {
        int r = i / 58, k = i - r * 58;
        xs[r * 60 + k] = x[(row0 + r) * 58 + k];
    }
    for (int i = tid; i < 4 * 128; i += 128) {
        int k = i >> 7, j = i & 127;
        cw1t[j * 4 + k] = Cw1[i];
    }
    for (int i = tid; i < 128 * 3; i += 128) {
        int j = i / 3, m = i - j * 3;
        cw2[j * 4 + m] = Cw2[i];
    }
    cb1[tid] = Cb1[tid];
    if (tid < 4) cb2[tid] = (tid < 3) ? Cb2[tid] : 0.f;
    for (int i = tid; i < 54 * 128; i += 128) {
        int k = i >> 7, j = i & 127;
        w1t[j * 60 + k] = Nw1[i];
    }
    for (int i = tid; i < 128 * 54; i += 128) {
        int j = i / 54, m = i - j * 54;
        w2s[j * 60 + m] = Nw2[i];
    }
    b1s[tid] = Nb1[tid];
    if (tid < 54) b2s[tid] = Nb2[tid];
    __syncthreads();

    // ---- Stage C ----
    {
        float cx0 = xs[tid * 60 + 0], cx1 = xs[tid * 60 + 1];
        float cx2 = xs[tid * 60 + 2], cx3 = xs[tid * 60 + 3];
        float c0 = cb2[0], c1 = cb2[1], c2 = cb2[2];
        for (int j = 0; j < 128; ++j) {
            const float* w = &cw1t[j * 4];
            float h = cb1[j] + cx0 * w[0] + cx1 * w[1] + cx2 * w[2] + cx3 * w[3];
            h = fmaxf(h, 0.f);
            const float* w2 = &cw2[j * 4];
            c0 += h * w2[0]; c1 += h * w2[1]; c2 += h * w2[2];
        }
        fb[tid * 60 + 0] = c0; fb[tid * 60 + 1] = c1; fb[tid * 60 + 2] = c2;
    }

    // ---- Stage N ----
    {
        float nin[54];
#pragma unroll
        for (int k = 0; k < 54; ++k) nin[k] = xs[tid * 60 + 4 + k];
        float acc[54];
#pragma unroll
        for (int m = 0; m < 54; ++m) acc[m] = b2s[m];
        for (int j = 0; j < 128; ++j) {
            const float* w = &w1t[j * 60];
            float h0 = 0.f, h1 = 0.f, h2 = 0.f, h3 = 0.f;
#pragma unroll
            for (int k = 0; k < 52; k += 4) {
                h0 += nin[k] * w[k];         h1 += nin[k + 1] * w[k + 1];
                h2 += nin[k + 2] * w[k + 2]; h3 += nin[k + 3] * w[k + 3];
            }
            h0 += nin[52] * w[52];
            h1 += nin[53] * w[53];
            float h = fmaxf((h0 + h1) + (h2 + h3) + b1s[j], 0.f);
            const float* w2 = &w2s[j * 60];
#pragma unroll
            for (int m = 0; m < 54; ++m) acc[m] += h * w2[m];
        }
#pragma unroll
        for (int m = 0; m < 54; ++m) fb[tid * 60 + 3 + m] = acc[m];
    }
    __syncthreads();

    for (int i = tid; i < 57 * 128; i += 128) {
        int k = i >> 7, j = i & 127;
        w1t[j * 60 + k] = Fw1[i];
    }
    for (int i = tid; i < 128 * 57; i += 128) {
        int j = i / 57, m = i - j * 57;
        w2s[j * 60 + m] = Fw2[i];
    }
    b1s[tid] = Fb1[tid];
    if (tid < 57) b2s[tid] = Fb2[tid];
    __syncthreads();

    // ---- Stage F ----
    {
        float fin[57];
#pragma unroll
        for (int k = 0; k < 57; ++k) fin[k] = fb[tid * 60 + k];
        float acc[57];
#pragma unroll
        for (int m = 0; m < 57; ++m) acc[m] = b2s[m];
        for (int j = 0; j < 128; ++j) {
            const float* w = &w1t[j * 60];
            float h0 = 0.f, h1 = 0.f, h2 = 0.f, h3 = 0.f;
#pragma unroll
            for (int k = 0; k < 56; k += 4) {
                h0 += fin[k] * w[k];         h1 += fin[k + 1] * w[k + 1];
                h2 += fin[k + 2] * w[k + 2]; h3 += fin[k + 3] * w[k + 3];
            }
            h0 += fin[56] * w[56];
            float h = fmaxf((h0 + h1) + (h2 + h3) + b1s[j], 0.f);
            const float* w2 = &w2s[j * 60];
#pragma unroll
            for (int m = 0; m < 57; ++m) acc[m] += h * w2[m];
        }
        // write fp16 swizzled A-tile image (row = tid, k zero-padded to 64)
        char* base = (char*)g_fh2 + (size_t)blockIdx.x * 16384;
#pragma unroll
        for (int p = 0; p < 32; ++p) {
            float lo = (2 * p     < 57) ? acc[2 * p]     : 0.f;
            float hi = (2 * p + 1 < 57) ? acc[2 * p + 1] : 0.f;
            unsigned sw = sw128((unsigned)(tid * 128 + 4 * p));
            *(__half2*)(base + sw) = __floats2half2_rn(lo, hi);
        }
    }
}

// ============================================================================
// Kernel 2: O stage via warp-level HMMA (mma.sync m16n8k16 fp16->fp32).
// CTA = 256 threads (8 warps) handles 128 rows. Warp w owns rows 16w..16w+15.
// A fragments loaded ONCE into registers, reused for all 54 branches.
// B (128x64 fp16, swizzled image) double-buffered in SMEM; per-nt fused
// epilogue on register accumulators; quad shfl reduce; softmax; direct store.
// ============================================================================
#define SM_A   0            // 16384 B
#define SM_B   16384        // 2 x 16384 B
#define SM_B1  49152        // 2 x 128 f32
#define SM_W2  50176        // 2 x 128 float4
#define SM_TOT 54272

__global__ void __launch_bounds__(256, 2) k_omma(
    const float* __restrict__ Ob1, const float* __restrict__ Ow2,
    const float* __restrict__ Ob2, float* __restrict__ out)
{
    extern __shared__ char smem[];
    const uint32_t sa  = smem_u32(smem + SM_A);
    const uint32_t sb  = smem_u32(smem + SM_B);
    float* b1s = (float*)(smem + SM_B1);
    float* w2s = (float*)(smem + SM_W2);

    const int tid  = threadIdx.x;
    const int wid  = tid >> 5;
    const int lane = tid & 31;
    const int row0 = blockIdx.x * 128;

    // ---- stage A image + branch-0 B image / b1 / w2 ----
    {
        const uint4* srcA = (const uint4*)((const char*)g_fh2 + (size_t)blockIdx.x * 16384);
        uint4* dstA = (uint4*)(smem + SM_A);
        const uint4* srcB = (const uint4*)g_w1h;
        uint4* dstB = (uint4*)(smem + SM_B);
#pragma unroll
        for (int i = 0; i < 4; ++i) {
            dstA[tid + 256 * i] = srcA[tid + 256 * i];
            dstB[tid + 256 * i] = srcB[tid + 256 * i];
        }
        if (tid < 128) {
            b1s[tid] = Ob1[tid];
        } else {
            int j = tid - 128;
            float* d = w2s + j * 4;
            d[0] = Ow2[j * 3 + 0]; d[1] = Ow2[j * 3 + 1]; d[2] = Ow2[j * 3 + 2]; d[3] = 0.f;
        }
    }
    __syncthreads();

    // ---- load A fragments for this warp's 16 rows (held across all branches) ----
    // kt = 0..3 (K16 steps); fragment regs a[kt][0..3]
    uint32_t a[4][4];
    {
        int m01 = (lane >> 3) & 1;      // 0: rows 0-7 of tile, 1: rows 8-15
        int kh  = lane >> 4;            // k-half (0: k0-7, 1: k8-15)
        int rg  = (wid << 4) + (lane & 7) + (m01 << 3);   // global row
#pragma unroll
        for (int kt = 0; kt < 4; ++kt) {
            uint32_t off = sw128((uint32_t)(rg * 128 + kt * 32 + kh * 16));
            ldsm_x4(sa + off, a[kt][0], a[kt][1], a[kt][2], a[kt][3]);
        }
    }

    const int quad = lane & 3;
    const int qrow = lane >> 2;             // 0..7
    const int rA   = (wid << 4) + qrow;     // rows this thread reduces
    const int rB   = rA + 8;

    // ldmatrix B address pieces: matrices (kt,h0),(kt,h1),(kt+1,h0),(kt+1,h1)
    const int bjrow = lane & 7;             // j within nt
    const int bkt   = lane >> 4;            // 0/1 -> kt offset within pair
    const int bkh   = (lane >> 3) & 1;      // k-half

    for (int n = 0; n < NB; ++n) {
        const int buf = n & 1, nxt = buf ^ 1;

        // prefetch branch n+1 into the other buffer (overlaps with compute)
        if (n < NB - 1) {
            const uint4* srcB = (const uint4*)(g_w1h + (n + 1) * 8192);
            uint4* dstB = (uint4*)(smem + SM_B + nxt * 16384);
#pragma unroll
            for (int i = 0; i < 4; ++i) dstB[tid + 256 * i] = srcB[tid + 256 * i];
            if (tid < 128) {
                b1s[nxt * 128 + tid] = Ob1[(n + 1) * 128 + tid];
            } else {
                int j = tid - 128;
                float* d = w2s + nxt * 512 + j * 4;
                d[0] = Ow2[(n + 1) * 384 + j * 3 + 0];
                d[1] = Ow2[(n + 1) * 384 + j * 3 + 1];
                d[2] = Ow2[(n + 1) * 384 + j * 3 + 2];
                d[3] = 0.f;
            }
        }

        const uint32_t sbb = sb + (uint32_t)buf * 16384;
        const float*  b1p = b1s + buf * 128;
        const float4* w2p = (const float4*)(w2s + buf * 512);

        float lA0 = 0.f, lA1 = 0.f, lA2 = 0.f;
        float lB0 = 0.f, lB1 = 0.f, lB2 = 0.f;

#pragma unroll
        for (int nt = 0; nt < 16; ++nt) {
            // B fragments for all 4 k-steps of this 8-col tile
            uint32_t b[4][2];
            {
                uint32_t off0 = sw128((uint32_t)((nt * 8 + bjrow) * 128 + (bkt)     * 32 + bkh * 16));
                uint32_t off1 = sw128((uint32_t)((nt * 8 + bjrow) * 128 + (bkt + 2) * 32 + bkh * 16));
                ldsm_x4(sbb + off0, b[0][0], b[0][1], b[1][0], b[1][1]);
                ldsm_x4(sbb + off1, b[2][0], b[2][1], b[3][0], b[3][1]);
            }
            float d0 = 0.f, d1 = 0.f, d2 = 0.f, d3 = 0.f;
#pragma unroll
            for (int kt = 0; kt < 4; ++kt)
                mma16816(d0, d1, d2, d3,
                         a[kt][0], a[kt][1], a[kt][2], a[kt][3],
                         b[kt][0], b[kt][1]);

            // fused epilogue for this tile: j0 = nt*8 + quad*2, j1 = j0+1
            int j0 = nt * 8 + quad * 2;
            float2 bb = *(const float2*)(b1p + j0);
            float4 wza = w2p[j0];
            float4 wzb = w2p[j0 + 1];
            float h;
            h = fmaxf(d0 + bb.x, 0.f);
            lA0 = fmaf(h, wza.x, lA0); lA1 = fmaf(h, wza.y, lA1); lA2 = fmaf(h, wza.z, lA2);
            h = fmaxf(d1 + bb.y, 0.f);
            lA0 = fmaf(h, wzb.x, lA0); lA1 = fmaf(h, wzb.y, lA1); lA2 = fmaf(h, wzb.z, lA2);
            h = fmaxf(d2 + bb.x, 0.f);
            lB0 = fmaf(h, wza.x, lB0); lB1 = fmaf(h, wza.y, lB1); lB2 = fmaf(h, wza.z, lB2);
            h = fmaxf(d3 + bb.y, 0.f);
            lB0 = fmaf(h, wzb.x, lB0); lB1 = fmaf(h, wzb.y, lB1); lB2 = fmaf(h, wzb.z, lB2);
        }

        // reduce across the quad (lanes differing in bits 0-1 share rows)
#pragma unroll
        for (int m = 1; m <= 2; m <<= 1) {
            lA0 += __shfl_xor_sync(0xffffffffu, lA0, m);
            lA1 += __shfl_xor_sync(0xffffffffu, lA1, m);
            lA2 += __shfl_xor_sync(0xffffffffu, lA2, m);
            lB0 += __shfl_xor_sync(0xffffffffu, lB0, m);
            lB1 += __shfl_xor_sync(0xffffffffu, lB1, m);
            lB2 += __shfl_xor_sync(0xffffffffu, lB2, m);
        }

        if (quad == 0) {
            float c0 = Ob2[n * 3 + 0], c1 = Ob2[n * 3 + 1], c2 = Ob2[n * 3 + 2];
            {
                float l0 = lA0 + c0, l1 = lA1 + c1, l2 = lA2 + c2;
                float mx = fmaxf(l0, fmaxf(l1, l2));
                float e0 = __expf(l0 - mx), e1 = __expf(l1 - mx), e2 = __expf(l2 - mx);
                float inv = 1.f / (e0 + e1 + e2);
                float* o = out + (size_t)(row0 + rA) * 162 + n * 3;
                o[0] = e0 * inv; o[1] = e1 * inv; o[2] = e2 * inv;
            }
            {
                float l0 = lB0 + c0, l1 = lB1 + c1, l2 = lB2 + c2;
                float mx = fmaxf(l0, fmaxf(l1, l2));
                float e0 = __expf(l0 - mx), e1 = __expf(l1 - mx), e2 = __expf(l2 - mx);
                float inv = 1.f / (e0 + e1 + e2);
                float* o = out + (size_t)(row0 + rB) * 162 + n * 3;
                o[0] = e0 * inv; o[1] = e1 * inv; o[2] = e2 * inv;
            }
        }
        __syncthreads();   // buffer swap: prefetch done, everyone done reading buf
    }
}

// ============================================================================
extern "C" void kernel_launch(void* const* d_in, const int* in_sizes, int n_in,
                              void* d_out, int out_size)
{
    const float* x   = (const float*)d_in[0];
    const float* Cw1 = (const float*)d_in[1];
    const float* Cb1 = (const float*)d_in[2];
    const float* Cw2 = (const float*)d_in[3];
    const float* Cb2 = (const float*)d_in[4];
    const float* Nw1 = (const float*)d_in[5];
    const float* Nb1 = (const float*)d_in[6];
    const float* Nw2 = (const float*)d_in[7];
    const float* Nb2 = (const float*)d_in[8];
    const float* Fw1 = (const float*)d_in[9];
    const float* Fb1 = (const float*)d_in[10];
    const float* Fw2 = (const float*)d_in[11];
    const float* Fb2 = (const float*)d_in[12];
    const float* Ow1 = (const float*)d_in[13];
    const float* Ob1 = (const float*)d_in[14];
    const float* Ow2 = (const float*)d_in[15];
    const float* Ob2 = (const float*)d_in[16];
    float* out = (float*)d_out;

    const size_t smem1 = 32064 * sizeof(float);   // 128256 B
    cudaFuncSetAttribute(k_features, cudaFuncAttributeMaxDynamicSharedMemorySize, (int)smem1);
    cudaFuncSetAttribute(k_omma,     cudaFuncAttributeMaxDynamicSharedMemorySize, SM_TOT);

    k_convert_w<<<NB * 8192 / 256, 256>>>(Ow1);

    k_features<<<NTILES, 128, smem1>>>(
        x, Cw1, Cb1, Cw2, Cb2, Nw1, Nb1, Nw2, Nb2, Fw1, Fb1, Fw2, Fb2);

    k_omma<<<NTILES, 256, SM_TOT>>>(Ob1, Ow2, Ob2, out);
}

// round 5
// speedup vs baseline: 4.5080x; 1.0872x over previous
#include <cuda_runtime.h>
#include <cuda_fp16.h>
#include <cstdint>

#define B_ROWS 65536
#define NTILES 512          // 65536 / 128
#define NB     54

typedef unsigned long long u64;

// ========================= device scratch ===================================
__device__ __align__(16) __half2 g_fh2[NTILES * 4096];   // A images (swizzled)
__device__ __align__(16) __half  g_w1h[NB * 8192];       // B images (swizzled)

// ============================= PTX helpers =================================
__device__ __forceinline__ uint32_t smem_u32(const void* p) {
    uint32_t a;
    asm("{ .reg .u64 t; cvta.to.shared.u64 t, %1; cvt.u32.u64 %0, t; }"
        : "=r"(a) : "l"(p));
    return a;
}
__device__ __forceinline__ void ldsm_x4(uint32_t addr, uint32_t& r0, uint32_t& r1,
                                        uint32_t& r2, uint32_t& r3) {
    asm volatile("ldmatrix.sync.aligned.m8n8.x4.shared.b16 {%0,%1,%2,%3}, [%4];"
                 : "=r"(r0), "=r"(r1), "=r"(r2), "=r"(r3) : "r"(addr));
}
__device__ __forceinline__ void mma16816(float& d0, float& d1, float& d2, float& d3,
                                         uint32_t a0, uint32_t a1, uint32_t a2, uint32_t a3,
                                         uint32_t b0, uint32_t b1) {
    asm volatile("mma.sync.aligned.m16n8k16.row.col.f32.f16.f16.f32 "
                 "{%0,%1,%2,%3}, {%4,%5,%6,%7}, {%8,%9}, {%0,%1,%2,%3};"
                 : "+f"(d0), "+f"(d1), "+f"(d2), "+f"(d3)
                 : "r"(a0), "r"(a1), "r"(a2), "r"(a3), "r"(b0), "r"(b1));
}
__device__ __forceinline__ uint32_t sw128(uint32_t off) {
    return off ^ ((off >> 3) & 0x70);
}
__device__ __forceinline__ u64 pk2(float lo, float hi) {
    u64 r; asm("mov.b64 %0, {%1, %2};" : "=l"(r) : "f"(lo), "f"(hi)); return r;
}
__device__ __forceinline__ void up2(u64 v, float& lo, float& hi) {
    asm("mov.b64 {%0, %1}, %2;" : "=f"(lo), "=f"(hi) : "l"(v));
}
__device__ __forceinline__ void ffma2(u64& d, u64 a, u64 b) {
    asm("fma.rn.f32x2 %0, %1, %2, %0;" : "+l"(d) : "l"(a), "l"(b));
}

// ============================================================================
// Weight convert: O_w1 (54,57,128) f32 -> per-branch swizzled fp16 tile image.
// ============================================================================
__global__ __launch_bounds__(256) void k_convert_w(const float* __restrict__ Ow1)
{
    int idx = blockIdx.x * 256 + threadIdx.x;   // < 54*8192
    int j = idx & 127;
    int k = (idx >> 7) & 63;
    int n = idx >> 13;
    float v = (k < 57) ? Ow1[n * 7296 + k * 128 + j] : 0.f;
    unsigned sw = sw128((unsigned)(j * 128 + k * 2));
    g_w1h[n * 8192 + (sw >> 1)] = __float2half(v);
}

// ============================================================================
// Kernel 1: fused C / N / F MLPs, fp32 with packed f32x2 inner loops.
// SMEM ~97.5 KB -> 2 CTAs/SM. Per-thread intermediates live in registers.
// ============================================================================
__global__ __launch_bounds__(128) void k_features(
    const float* __restrict__ x,
    const float* __restrict__ Cw1, const float* __restrict__ Cb1,
    const float* __restrict__ Cw2, const float* __restrict__ Cb2,
    const float* __restrict__ Nw1, const float* __restrict__ Nb1,
    const float* __restrict__ Nw2, const float* __restrict__ Nb2,
    const float* __restrict__ Fw1, const float* __restrict__ Fb1,
    const float* __restrict__ Fw2, const float* __restrict__ Fb2)
{
    extern __shared__ float sm[];
    float* xs   = sm;            // 128*60
    float* w1t  = xs + 7680;     // 128*60  [j][k]
    float* w2s  = w1t + 7680;    // 128*60  [j][m]
    float* cw1t = w2s + 7680;    // 128*4
    float* cw2  = cw1t + 512;    // 128*4
    float* cb1  = cw2 + 512;     // 128
    float* cb2  = cb1 + 128;     // 4
    float* b1s  = cb2 + 4;       // 128
    float* b2s  = b1s + 128;     // 60
    // total 24384 floats = 97536 B

    const int tid  = threadIdx.x;
    const int row0 = blockIdx.x * 128;

    for (int i = tid; i < 128 * 58; i += 128) {
        int r = i / 58, k = i - r * 58;
        xs[r * 60 + k] = x[(row0 + r) * 58 + k];
    }
    for (int i = tid; i < 4 * 128; i += 128) {
        int k = i >> 7, j = i & 127;
        cw1t[j * 4 + k] = Cw1[i];
    }
    for (int i = tid; i < 128 * 3; i += 128) {
        int j = i / 3, m = i - j * 3;
        cw2[j * 4 + m] = Cw2[i];
    }
    cb1[tid] = Cb1[tid];
    if (tid < 4) cb2[tid] = (tid < 3) ? Cb2[tid] : 0.f;
    for (int i = tid; i < 54 * 128; i += 128) {       // N_w1 -> [j][k]
        int k = i >> 7, j = i & 127;
        w1t[j * 60 + k] = Nw1[i];
    }
    for (int i = tid; i < 128 * 54; i += 128) {       // N_w2 -> [j][m]
        int j = i / 54, m = i - j * 54;
        w2s[j * 60 + m] = Nw2[i];
    }
    b1s[tid] = Nb1[tid];
    if (tid < 54) b2s[tid] = Nb2[tid];
    __syncthreads();

    // ---- Stage C (scalar, tiny) ----
    float c0, c1, c2;
    {
        float cx0 = xs[tid * 60 + 0], cx1 = xs[tid * 60 + 1];
        float cx2 = xs[tid * 60 + 2], cx3 = xs[tid * 60 + 3];
        c0 = cb2[0]; c1 = cb2[1]; c2 = cb2[2];
        for (int j = 0; j < 128; ++j) {
            const float* w = &cw1t[j * 4];
            float h = cb1[j] + cx0 * w[0] + cx1 * w[1] + cx2 * w[2] + cx3 * w[3];
            h = fmaxf(h, 0.f);
            const float* w2 = &cw2[j * 4];
            c0 += h * w2[0]; c1 += h * w2[1]; c2 += h * w2[2];
        }
    }

    // ---- Stage N (packed f32x2) ----
    u64 acc2[27];
    {
        u64 nin2[27];
        const ulonglong2* xp = (const ulonglong2*)(xs + tid * 60 + 4);
#pragma unroll
        for (int i = 0; i < 13; ++i) {
            ulonglong2 v = xp[i];
            nin2[2 * i] = v.x; nin2[2 * i + 1] = v.y;
        }
        nin2[26] = *(const u64*)(xs + tid * 60 + 56);
        const ulonglong2* bp = (const ulonglong2*)(b2s);
#pragma unroll
        for (int i = 0; i < 13; ++i) {
            ulonglong2 v = bp[i];
            acc2[2 * i] = v.x; acc2[2 * i + 1] = v.y;
        }
        acc2[26] = *(const u64*)(b2s + 52);

        for (int j = 0; j < 128; ++j) {
            const ulonglong2* wp = (const ulonglong2*)(w1t + j * 60);
            u64 h0 = 0, h1 = 0;
#pragma unroll
            for (int i = 0; i < 13; ++i) {
                ulonglong2 w = wp[i];
                ffma2(h0, nin2[2 * i],     w.x);
                ffma2(h1, nin2[2 * i + 1], w.y);
            }
            ffma2(h0, nin2[26], *(const u64*)(w1t + j * 60 + 52));
            float p, q, r, s;
            up2(h0, p, q); up2(h1, r, s);
            float h = fmaxf((p + r) + (q + s) + b1s[j], 0.f);
            u64 hh = pk2(h, h);
            const ulonglong2* w2p = (const ulonglong2*)(w2s + j * 60);
#pragma unroll
            for (int i = 0; i < 13; ++i) {
                ulonglong2 w = w2p[i];
                ffma2(acc2[2 * i],     hh, w.x);
                ffma2(acc2[2 * i + 1], hh, w.y);
            }
            ffma2(acc2[26], hh, *(const u64*)(w2s + j * 60 + 52));
        }
    }
    __syncthreads();

    // ---- Load F weights ----
    for (int i = tid; i < 57 * 128; i += 128) {       // F_w1 -> [j][k]
        int k = i >> 7, j = i & 127;
        w1t[j * 60 + k] = Fw1[i];
    }
    for (int i = tid; i < 128 * 57; i += 128) {       // F_w2 -> [j][m]
        int j = i / 57, m = i - j * 57;
        w2s[j * 60 + m] = Fw2[i];
    }
    b1s[tid] = Fb1[tid];
    if (tid < 57) b2s[tid] = Fb2[tid];
    __syncthreads();

    // ---- Stage F (packed f32x2) ----
    {
        float nv[54];
#pragma unroll
        for (int p = 0; p < 27; ++p) up2(acc2[p], nv[2 * p], nv[2 * p + 1]);
        u64 fin2[28];
        fin2[0] = pk2(c0, c1);
        fin2[1] = pk2(c2, nv[0]);
#pragma unroll
        for (int p = 2; p < 28; ++p) fin2[p] = pk2(nv[2 * p - 3], nv[2 * p - 2]);
        const float fin56 = nv[53];

        u64 acf[28];
        const ulonglong2* bp = (const ulonglong2*)(b2s);
#pragma unroll
        for (int i = 0; i < 14; ++i) {
            ulonglong2 v = bp[i];
            acf[2 * i] = v.x; acf[2 * i + 1] = v.y;
        }
        float ac56 = b2s[56];

        for (int j = 0; j < 128; ++j) {
            const ulonglong2* wp = (const ulonglong2*)(w1t + j * 60);
            u64 h0 = 0, h1 = 0;
#pragma unroll
            for (int i = 0; i < 14; ++i) {
                ulonglong2 w = wp[i];
                ffma2(h0, fin2[2 * i],     w.x);
                ffma2(h1, fin2[2 * i + 1], w.y);
            }
            float p, q, r, s;
            up2(h0, p, q); up2(h1, r, s);
            float h = (p + r) + (q + s) + fin56 * w1t[j * 60 + 56] + b1s[j];
            h = fmaxf(h, 0.f);
            u64 hh = pk2(h, h);
            const ulonglong2* w2p = (const ulonglong2*)(w2s + j * 60);
#pragma unroll
            for (int i = 0; i < 14; ++i) {
                ulonglong2 w = w2p[i];
                ffma2(acf[2 * i],     hh, w.x);
                ffma2(acf[2 * i + 1], hh, w.y);
            }
            ac56 = fmaf(h, w2s[j * 60 + 56], ac56);
        }

        // write fp16 swizzled A-tile image (row = tid, k zero-padded to 64)
        float fv[58];
#pragma unroll
        for (int p = 0; p < 28; ++p) up2(acf[p], fv[2 * p], fv[2 * p + 1]);
        fv[56] = ac56; fv[57] = 0.f;
        char* base = (char*)g_fh2 + (size_t)blockIdx.x * 16384;
#pragma unroll
        for (int p = 0; p < 32; ++p) {
            float lo = (p < 29) ? fv[2 * p]     : 0.f;
            float hi = (p < 29) ? fv[2 * p + 1] : 0.f;
            unsigned sw = sw128((unsigned)(tid * 128 + 4 * p));
            *(__half2*)(base + sw) = __floats2half2_rn(lo, hi);
        }
    }
}

// ============================================================================
// Kernel 2: O stage via HMMA, 2 branches per iteration (dual independent
// MMA chains for ILP, half the barriers). A fragments register-resident.
// ============================================================================
#define SM_A   0            // 16384 B
#define SM_B   16384        // 4 x 16384 B (2 pairs of branch tiles)
#define SM_B1  81920        // 4 x 128 f32
#define SM_W2  83968        // 4 x 512 f32
#define SM_TOT 92160

__global__ void __launch_bounds__(256, 2) k_omma(
    const float* __restrict__ Ob1, const float* __restrict__ Ow2,
    const float* __restrict__ Ob2, float* __restrict__ out)
{
    extern __shared__ char smem[];
    const uint32_t sa = smem_u32(smem + SM_A);
    const uint32_t sb = smem_u32(smem + SM_B);
    float* b1s = (float*)(smem + SM_B1);
    float* w2s = (float*)(smem + SM_W2);

    const int tid  = threadIdx.x;
    const int wid  = tid >> 5;
    const int lane = tid & 31;
    const int row0 = blockIdx.x * 128;

    // ---- stage A image + branch 0,1 tiles / b1 / w2 ----
    {
        const uint4* srcA = (const uint4*)((const char*)g_fh2 + (size_t)blockIdx.x * 16384);
        uint4* dstA = (uint4*)(smem + SM_A);
#pragma unroll
        for (int i = 0; i < 4; ++i) dstA[tid + 256 * i] = srcA[tid + 256 * i];
        const uint4* srcB = (const uint4*)g_w1h;   // branches 0,1 contiguous (32 KB)
        uint4* dstB = (uint4*)(smem + SM_B);
#pragma unroll
        for (int i = 0; i < 8; ++i) dstB[tid + 256 * i] = srcB[tid + 256 * i];
        if (tid < 128) {
            b1s[tid]       = Ob1[tid];
            b1s[128 + tid] = Ob1[128 + tid];
        } else {
            int j = tid - 128;
            float* d0 = w2s + j * 4;
            d0[0] = Ow2[j * 3 + 0]; d0[1] = Ow2[j * 3 + 1]; d0[2] = Ow2[j * 3 + 2]; d0[3] = 0.f;
            float* d1 = w2s + 512 + j * 4;
            d1[0] = Ow2[384 + j * 3 + 0]; d1[1] = Ow2[384 + j * 3 + 1];
            d1[2] = Ow2[384 + j * 3 + 2]; d1[3] = 0.f;
        }
    }
    __syncthreads();

    // ---- A fragments for this warp's 16 rows (held across all branches) ----
    uint32_t a[4][4];
    {
        int m01 = (lane >> 3) & 1;
        int kh  = lane >> 4;
        int rg  = (wid << 4) + (lane & 7) + (m01 << 3);
#pragma unroll
        for (int kt = 0; kt < 4; ++kt) {
            uint32_t off = sw128((uint32_t)(rg * 128 + kt * 32 + kh * 16));
            ldsm_x4(sa + off, a[kt][0], a[kt][1], a[kt][2], a[kt][3]);
        }
    }

    const int quad = lane & 3;
    const int qrow = lane >> 2;
    const int rA   = (wid << 4) + qrow;
    const int rB   = rA + 8;
    const int bjrow = lane & 7;
    const int bkt   = lane >> 4;
    const int bkh   = (lane >> 3) & 1;

    for (int p = 0; p < 27; ++p) {
        const int buf = p & 1, nxt = buf ^ 1;
        const int nP = 2 * p, nQ = nP + 1;

        // prefetch next branch pair (overlaps compute)
        if (p < 26) {
            const uint4* s = (const uint4*)(g_w1h + (nP + 2) * 8192);
            uint4* d = (uint4*)(smem + SM_B + nxt * 32768);
#pragma unroll
            for (int i = 0; i < 8; ++i) d[tid + 256 * i] = s[tid + 256 * i];
            if (tid < 128) {
                b1s[nxt * 256 + tid]       = Ob1[(nP + 2) * 128 + tid];
                b1s[nxt * 256 + 128 + tid] = Ob1[(nP + 3) * 128 + tid];
            } else {
                int j = tid - 128;
                float* d0 = w2s + nxt * 1024 + j * 4;
                d0[0] = Ow2[(nP + 2) * 384 + j * 3 + 0];
                d0[1] = Ow2[(nP + 2) * 384 + j * 3 + 1];
                d0[2] = Ow2[(nP + 2) * 384 + j * 3 + 2];
                d0[3] = 0.f;
                float* d1 = w2s + nxt * 1024 + 512 + j * 4;
                d1[0] = Ow2[(nP + 3) * 384 + j * 3 + 0];
                d1[1] = Ow2[(nP + 3) * 384 + j * 3 + 1];
                d1[2] = Ow2[(nP + 3) * 384 + j * 3 + 2];
                d1[3] = 0.f;
            }
        }

        const uint32_t sb0 = sb + (uint32_t)buf * 32768;
        const uint32_t sb1 = sb0 + 16384;
        const float*  b1P = b1s + buf * 256;
        const float*  b1Q = b1P + 128;
        const float4* w2P = (const float4*)(w2s + buf * 1024);
        const float4* w2Q = (const float4*)(w2s + buf * 1024 + 512);

        float lPA0 = 0.f, lPA1 = 0.f, lPA2 = 0.f, lPB0 = 0.f, lPB1 = 0.f, lPB2 = 0.f;
        float lQA0 = 0.f, lQA1 = 0.f, lQA2 = 0.f, lQB0 = 0.f, lQB1 = 0.f, lQB2 = 0.f;

#pragma unroll 4
        for (int nt = 0; nt < 16; ++nt) {
            uint32_t off0 = sw128((uint32_t)((nt * 8 + bjrow) * 128 + bkt * 32 + bkh * 16));
            uint32_t off1 = sw128((uint32_t)((nt * 8 + bjrow) * 128 + (bkt + 2) * 32 + bkh * 16));
            uint32_t bP[4][2], bQ[4][2];
            ldsm_x4(sb0 + off0, bP[0][0], bP[0][1], bP[1][0], bP[1][1]);
            ldsm_x4(sb0 + off1, bP[2][0], bP[2][1], bP[3][0], bP[3][1]);
            ldsm_x4(sb1 + off0, bQ[0][0], bQ[0][1], bQ[1][0], bQ[1][1]);
            ldsm_x4(sb1 + off1, bQ[2][0], bQ[2][1], bQ[3][0], bQ[3][1]);

            float dP0 = 0.f, dP1 = 0.f, dP2 = 0.f, dP3 = 0.f;
            float dQ0 = 0.f, dQ1 = 0.f, dQ2 = 0.f, dQ3 = 0.f;
#pragma unroll
            for (int kt = 0; kt < 4; ++kt) {
                mma16816(dP0, dP1, dP2, dP3,
                         a[kt][0], a[kt][1], a[kt][2], a[kt][3], bP[kt][0], bP[kt][1]);
                mma16816(dQ0, dQ1, dQ2, dQ3,
                         a[kt][0], a[kt][1], a[kt][2], a[kt][3], bQ[kt][0], bQ[kt][1]);
            }

            const int j0 = nt * 8 + quad * 2;
            {
                float2 bb = *(const float2*)(b1P + j0);
                float4 wza = w2P[j0], wzb = w2P[j0 + 1];
                float h;
                h = fmaxf(dP0 + bb.x, 0.f);
                lPA0 = fmaf(h, wza.x, lPA0); lPA1 = fmaf(h, wza.y, lPA1); lPA2 = fmaf(h, wza.z, lPA2);
                h = fmaxf(dP1 + bb.y, 0.f);
                lPA0 = fmaf(h, wzb.x, lPA0); lPA1 = fmaf(h, wzb.y, lPA1); lPA2 = fmaf(h, wzb.z, lPA2);
                h = fmaxf(dP2 + bb.x, 0.f);
                lPB0 = fmaf(h, wza.x, lPB0); lPB1 = fmaf(h, wza.y, lPB1); lPB2 = fmaf(h, wza.z, lPB2);
                h = fmaxf(dP3 + bb.y, 0.f);
                lPB0 = fmaf(h, wzb.x, lPB0); lPB1 = fmaf(h, wzb.y, lPB1); lPB2 = fmaf(h, wzb.z, lPB2);
            }
            {
                float2 bb = *(const float2*)(b1Q + j0);
                float4 wza = w2Q[j0], wzb = w2Q[j0 + 1];
                float h;
                h = fmaxf(dQ0 + bb.x, 0.f);
                lQA0 = fmaf(h, wza.x, lQA0); lQA1 = fmaf(h, wza.y, lQA1); lQA2 = fmaf(h, wza.z, lQA2);
                h = fmaxf(dQ1 + bb.y, 0.f);
                lQA0 = fmaf(h, wzb.x, lQA0); lQA1 = fmaf(h, wzb.y, lQA1); lQA2 = fmaf(h, wzb.z, lQA2);
                h = fmaxf(dQ2 + bb.x, 0.f);
                lQB0 = fmaf(h, wza.x, lQB0); lQB1 = fmaf(h, wza.y, lQB1); lQB2 = fmaf(h, wza.z, lQB2);
                h = fmaxf(dQ3 + bb.y, 0.f);
                lQB0 = fmaf(h, wzb.x, lQB0); lQB1 = fmaf(h, wzb.y, lQB1); lQB2 = fmaf(h, wzb.z, lQB2);
            }
        }

        // quad reduction (lanes differing in bits 0-1 share rows)
#pragma unroll
        for (int m = 1; m <= 2; m <<= 1) {
            lPA0 += __shfl_xor_sync(0xffffffffu, lPA0, m);
            lPA1 += __shfl_xor_sync(0xffffffffu, lPA1, m);
            lPA2 += __shfl_xor_sync(0xffffffffu, lPA2, m);
            lPB0 += __shfl_xor_sync(0xffffffffu, lPB0, m);
            lPB1 += __shfl_xor_sync(0xffffffffu, lPB1, m);
            lPB2 += __shfl_xor_sync(0xffffffffu, lPB2, m);
            lQA0 += __shfl_xor_sync(0xffffffffu, lQA0, m);
            lQA1 += __shfl_xor_sync(0xffffffffu, lQA1, m);
            lQA2 += __shfl_xor_sync(0xffffffffu, lQA2, m);
            lQB0 += __shfl_xor_sync(0xffffffffu, lQB0, m);
            lQB1 += __shfl_xor_sync(0xffffffffu, lQB1, m);
            lQB2 += __shfl_xor_sync(0xffffffffu, lQB2, m);
        }

        if (quad == 0) {
            float cP0 = Ob2[nP * 3 + 0], cP1 = Ob2[nP * 3 + 1], cP2 = Ob2[nP * 3 + 2];
            float cQ0 = Ob2[nQ * 3 + 0], cQ1 = Ob2[nQ * 3 + 1], cQ2 = Ob2[nQ * 3 + 2];
            {
                float l0 = lPA0 + cP0, l1 = lPA1 + cP1, l2 = lPA2 + cP2;
                float mx = fmaxf(l0, fmaxf(l1, l2));
                float e0 = __expf(l0 - mx), e1 = __expf(l1 - mx), e2 = __expf(l2 - mx);
                float inv = 1.f / (e0 + e1 + e2);
                float* o = out + (size_t)(row0 + rA) * 162 + nP * 3;
                o[0] = e0 * inv; o[1] = e1 * inv; o[2] = e2 * inv;
            }
            {
                float l0 = lPB0 + cP0, l1 = lPB1 + cP1, l2 = lPB2 + cP2;
                float mx = fmaxf(l0, fmaxf(l1, l2));
                float e0 = __expf(l0 - mx), e1 = __expf(l1 - mx), e2 = __expf(l2 - mx);
                float inv = 1.f / (e0 + e1 + e2);
                float* o = out + (size_t)(row0 + rB) * 162 + nP * 3;
                o[0] = e0 * inv; o[1] = e1 * inv; o[2] = e2 * inv;
            }
            {
                float l0 = lQA0 + cQ0, l1 = lQA1 + cQ1, l2 = lQA2 + cQ2;
                float mx = fmaxf(l0, fmaxf(l1, l2));
                float e0 = __expf(l0 - mx), e1 = __expf(l1 - mx), e2 = __expf(l2 - mx);
                float inv = 1.f / (e0 + e1 + e2);
                float* o = out + (size_t)(row0 + rA) * 162 + nQ * 3;
                o[0] = e0 * inv; o[1] = e1 * inv; o[2] = e2 * inv;
            }
            {
                float l0 = lQB0 + cQ0, l1 = lQB1 + cQ1, l2 = lQB2 + cQ2;
                float mx = fmaxf(l0, fmaxf(l1, l2));
                float e0 = __expf(l0 - mx), e1 = __expf(l1 - mx), e2 = __expf(l2 - mx);
                float inv = 1.f / (e0 + e1 + e2);
                float* o = out + (size_t)(row0 + rB) * 162 + nQ * 3;
                o[0] = e0 * inv; o[1] = e1 * inv; o[2] = e2 * inv;
            }
        }
        __syncthreads();
    }
}

// ============================================================================
extern "C" void kernel_launch(void* const* d_in, const int* in_sizes, int n_in,
                              void* d_out, int out_size)
{
    const float* x   = (const float*)d_in[0];
    const float* Cw1 = (const float*)d_in[1];
    const float* Cb1 = (const float*)d_in[2];
    const float* Cw2 = (const float*)d_in[3];
    const float* Cb2 = (const float*)d_in[4];
    const float* Nw1 = (const float*)d_in[5];
    const float* Nb1 = (const float*)d_in[6];
    const float* Nw2 = (const float*)d_in[7];
    const float* Nb2 = (const float*)d_in[8];
    const float* Fw1 = (const float*)d_in[9];
    const float* Fb1 = (const float*)d_in[10];
    const float* Fw2 = (const float*)d_in[11];
    const float* Fb2 = (const float*)d_in[12];
    const float* Ow1 = (const float*)d_in[13];
    const float* Ob1 = (const float*)d_in[14];
    const float* Ow2 = (const float*)d_in[15];
    const float* Ob2 = (const float*)d_in[16];
    float* out = (float*)d_out;

    const size_t smem1 = 24384 * sizeof(float);   // 97536 B
    cudaFuncSetAttribute(k_features, cudaFuncAttributeMaxDynamicSharedMemorySize, (int)smem1);
    cudaFuncSetAttribute(k_omma,     cudaFuncAttributeMaxDynamicSharedMemorySize, SM_TOT);

    k_convert_w<<<NB * 8192 / 256, 256>>>(Ow1);

    k_features<<<NTILES, 128, smem1>>>(
        x, Cw1, Cb1, Cw2, Cb2, Nw1, Nb1, Nw2, Nb2, Fw1, Fb1, Fw2, Fb2);

    k_omma<<<NTILES, 256, SM_TOT>>>(Ob1, Ow2, Ob2, out);
}

// round 6
// speedup vs baseline: 5.9553x; 1.3211x over previous
#include <cuda_runtime.h>
#include <cuda_fp16.h>
#include <cstdint>

#define B_ROWS 65536
#define NTILES 512
#define NB     54

// ========================= device scratch (fp16 B images) ===================
__device__ __align__(16) __half g_w1h[NB * 8192];  // O_w1: 54 x [j=128][k=64]
__device__ __align__(16) __half g_bn1[8192];       // N_w1: [j=128][k=64]
__device__ __align__(16) __half g_bn2[8192];       // N_w2: [m=64][k=128]
__device__ __align__(16) __half g_bf1[8192];       // F_w1: [j=128][k=64]
__device__ __align__(16) __half g_bf2[8192];       // F_w2: [m=64][k=128]

// ============================= PTX helpers =================================
__device__ __forceinline__ uint32_t smem_u32(const void* p) {
    uint32_t a;
    asm("{ .reg .u64 t; cvta.to.shared.u64 t, %1; cvt.u32.u64 %0, t; }"
        : "=r"(a) : "l"(p));
    return a;
}
__device__ __forceinline__ void ldsm_x4(uint32_t addr, uint32_t& r0, uint32_t& r1,
                                        uint32_t& r2, uint32_t& r3) {
    asm volatile("ldmatrix.sync.aligned.m8n8.x4.shared.b16 {%0,%1,%2,%3}, [%4];"
                 : "=r"(r0), "=r"(r1), "=r"(r2), "=r"(r3) : "r"(addr));
}
__device__ __forceinline__ void mma16816(float& d0, float& d1, float& d2, float& d3,
                                         uint32_t a0, uint32_t a1, uint32_t a2, uint32_t a3,
                                         uint32_t b0, uint32_t b1) {
    asm volatile("mma.sync.aligned.m16n8k16.row.col.f32.f16.f16.f32 "
                 "{%0,%1,%2,%3}, {%4,%5,%6,%7}, {%8,%9}, {%0,%1,%2,%3};"
                 : "+f"(d0), "+f"(d1), "+f"(d2), "+f"(d3)
                 : "r"(a0), "r"(a1), "r"(a2), "r"(a3), "r"(b0), "r"(b1));
}
__device__ __forceinline__ uint32_t sw128(uint32_t off) {
    return off ^ ((off >> 3) & 0x70);
}

// ============================================================================
// Convert: all layer-1/2 weights -> swizzled fp16 tile images.
// ============================================================================
__global__ __launch_bounds__(256) void k_convert(
    const float* __restrict__ Ow1,
    const float* __restrict__ Nw1, const float* __restrict__ Nw2,
    const float* __restrict__ Fw1, const float* __restrict__ Fw2)
{
    int idx = blockIdx.x * 256 + threadIdx.x;
    if (idx < NB * 8192) {                       // O_w1 images
        int j = idx & 127, k = (idx >> 7) & 63, n = idx >> 13;
        float v = (k < 57) ? Ow1[n * 7296 + k * 128 + j] : 0.f;
        g_w1h[n * 8192 + (sw128((unsigned)(j * 128 + k * 2)) >> 1)] = __float2half(v);
        return;
    }
    int t = idx - NB * 8192;
    if (t >= 4 * 8192) return;
    int img = t >> 13, e = t & 8191;
    if (img == 0) {                              // N_w1 [j=128][k=64]
        int j = e >> 6, k = e & 63;
        float v = (k < 54) ? Nw1[k * 128 + j] : 0.f;
        g_bn1[sw128((unsigned)(j * 128 + k * 2)) >> 1] = __float2half(v);
    } else if (img == 1) {                       // F_w1 [j=128][k=64]
        int j = e >> 6, k = e & 63;
        float v = (k < 57) ? Fw1[k * 128 + j] : 0.f;
        g_bf1[sw128((unsigned)(j * 128 + k * 2)) >> 1] = __float2half(v);
    } else if (img == 2) {                       // N_w2 [m=64][k=128]
        int m = e >> 7, k = e & 127;
        float v = (m < 54) ? Nw2[k * 54 + m] : 0.f;
        g_bn2[sw128((unsigned)(m * 256 + k * 2)) >> 1] = __float2half(v);
    } else {                                     // F_w2 [m=64][k=128]
        int m = e >> 7, k = e & 127;
        float v = (m < 57) ? Fw2[k * 57 + m] : 0.f;
        g_bf2[sw128((unsigned)(m * 256 + k * 2)) >> 1] = __float2half(v);
    }
}

// ============================ SMEM layout ===================================
#define SM_AIMG 0          // 16 KB: A image (N-input -> F-input -> f)
#define SM_R1A  16384      // 16 KB: B_N1 -> B_F1 -> O buf0
#define SM_R1B  32768      // 16 KB: B_N2 -> B_F2 -> O buf1
#define SM_HIMG 49152      // 32 KB: hidden image (RS=256) -> O buf2/buf3
#define SM_OB2  49152
#define SM_OB3  65536
#define SM_XC   81920      // 128*4 f32
#define SM_CW1  83968      // 512 f32
#define SM_CW2  86016      // 512 f32
#define SM_CB1  88064      // 128 f32
#define SM_CB2  88576      // 8 f32
#define SM_BN1  88608      // 128 f32
#define SM_BN2  89120      // 64 f32
#define SM_BF1  89376      // 128 f32
#define SM_BF2  89888      // 64 f32
#define SM_B1S  90144      // 4*128 f32 (O-stage, 2 pair-buffers)
#define SM_W2S  92192      // 4*512 f32
#define SM_TOT  100384

// ---- layer: 64-K HMMA, 128 outputs, bias+relu, fp16 -> himg (RS=256) ----
__device__ __forceinline__ void layer_wide(
    uint32_t sA, uint32_t sB, const float* __restrict__ bias, char* himg,
    int wid, int lane)
{
    const int m01 = (lane >> 3) & 1, kh = lane >> 4;
    const int rg  = (wid << 4) + (lane & 7) + (m01 << 3);
    const int quad = lane & 3, qrow = lane >> 2;
    const int rA = (wid << 4) + qrow, rB = rA + 8;
    const int bjrow = lane & 7, bkt = lane >> 4, bkh = (lane >> 3) & 1;

    uint32_t a[4][4];
#pragma unroll
    for (int kt = 0; kt < 4; ++kt) {
        uint32_t off = sw128((uint32_t)(rg * 128 + kt * 32 + kh * 16));
        ldsm_x4(sA + off, a[kt][0], a[kt][1], a[kt][2], a[kt][3]);
    }
#pragma unroll 4
    for (int nt = 0; nt < 16; ++nt) {
        uint32_t off0 = sw128((uint32_t)((nt * 8 + bjrow) * 128 + bkt * 32 + bkh * 16));
        uint32_t off1 = sw128((uint32_t)((nt * 8 + bjrow) * 128 + (bkt + 2) * 32 + bkh * 16));
        uint32_t b[4][2];
        ldsm_x4(sB + off0, b[0][0], b[0][1], b[1][0], b[1][1]);
        ldsm_x4(sB + off1, b[2][0], b[2][1], b[3][0], b[3][1]);
        float d0 = 0.f, d1 = 0.f, d2 = 0.f, d3 = 0.f;
#pragma unroll
        for (int kt = 0; kt < 4; ++kt)
            mma16816(d0, d1, d2, d3, a[kt][0], a[kt][1], a[kt][2], a[kt][3],
                     b[kt][0], b[kt][1]);
        int j0 = nt * 8 + quad * 2;
        float2 bb = *(const float2*)(bias + j0);
        __half2 hA = __floats2half2_rn(fmaxf(d0 + bb.x, 0.f), fmaxf(d1 + bb.y, 0.f));
        __half2 hB = __floats2half2_rn(fmaxf(d2 + bb.x, 0.f), fmaxf(d3 + bb.y, 0.f));
        *(__half2*)(himg + sw128((uint32_t)(rA * 256 + j0 * 2))) = hA;
        *(__half2*)(himg + sw128((uint32_t)(rB * 256 + j0 * 2))) = hB;
    }
}

// ---- layer: 128-K HMMA, ntn*8 outputs, bias (no relu), fp16 -> aimg cols m+coff ----
__device__ __forceinline__ void layer_narrow(
    uint32_t sH, uint32_t sB, const float* __restrict__ bias, char* outimg,
    int coff, int mlim, int ntn, int wid, int lane)
{
    const int m01 = (lane >> 3) & 1, kh = lane >> 4;
    const int rg  = (wid << 4) + (lane & 7) + (m01 << 3);
    const int quad = lane & 3, qrow = lane >> 2;
    const int rA = (wid << 4) + qrow, rB = rA + 8;
    const int bjrow = lane & 7, bkt = lane >> 4, bkh = (lane >> 3) & 1;

    uint32_t a[8][4];
#pragma unroll
    for (int kt = 0; kt < 8; ++kt) {
        uint32_t off = sw128((uint32_t)(rg * 256 + kt * 32 + kh * 16));
        ldsm_x4(sH + off, a[kt][0], a[kt][1], a[kt][2], a[kt][3]);
    }
    for (int nt = 0; nt < ntn; ++nt) {
        uint32_t b[8][2];
#pragma unroll
        for (int q = 0; q < 4; ++q) {
            uint32_t off = sw128((uint32_t)((nt * 8 + bjrow) * 256 + q * 64 + bkt * 32 + bkh * 16));
            ldsm_x4(sB + off, b[2 * q][0], b[2 * q][1], b[2 * q + 1][0], b[2 * q + 1][1]);
        }
        float d0 = 0.f, d1 = 0.f, d2 = 0.f, d3 = 0.f;
#pragma unroll
        for (int kt = 0; kt < 8; ++kt)
            mma16816(d0, d1, d2, d3, a[kt][0], a[kt][1], a[kt][2], a[kt][3],
                     b[kt][0], b[kt][1]);
        int m0 = nt * 8 + quad * 2, m1 = m0 + 1;
        if (m0 < mlim) {
            *(__half*)(outimg + sw128((uint32_t)(rA * 128 + (m0 + coff) * 2))) =
                __float2half(d0 + bias[m0]);
            *(__half*)(outimg + sw128((uint32_t)(rB * 128 + (m0 + coff) * 2))) =
                __float2half(d2 + bias[m0]);
        }
        if (m1 < mlim) {
            *(__half*)(outimg + sw128((uint32_t)(rA * 128 + (m1 + coff) * 2))) =
                __float2half(d1 + bias[m1]);
            *(__half*)(outimg + sw128((uint32_t)(rB * 128 + (m1 + coff) * 2))) =
                __float2half(d3 + bias[m1]);
        }
    }
}

// ============================================================================
// Fused kernel: C (fp32 scalar) + N/F (HMMA) + O stage (HMMA dual-branch).
// ============================================================================
__global__ void __launch_bounds__(256, 2) k_fused(
    const float* __restrict__ x,
    const float* __restrict__ Cw1, const float* __restrict__ Cb1v,
    const float* __restrict__ Cw2, const float* __restrict__ Cb2v,
    const float* __restrict__ Nb1v, const float* __restrict__ Nb2v,
    const float* __restrict__ Fb1v, const float* __restrict__ Fb2v,
    const float* __restrict__ Ob1, const float* __restrict__ Ow2,
    const float* __restrict__ Ob2, float* __restrict__ out)
{
    extern __shared__ char smem[];
    const uint32_t sbase = smem_u32(smem);
    float* xc   = (float*)(smem + SM_XC);
    float* cw1t = (float*)(smem + SM_CW1);
    float* cw2  = (float*)(smem + SM_CW2);
    float* cb1  = (float*)(smem + SM_CB1);
    float* cb2  = (float*)(smem + SM_CB2);
    float* bn1  = (float*)(smem + SM_BN1);
    float* bn2  = (float*)(smem + SM_BN2);
    float* bf1  = (float*)(smem + SM_BF1);
    float* bf2  = (float*)(smem + SM_BF2);
    float* b1s  = (float*)(smem + SM_B1S);
    float* w2s  = (float*)(smem + SM_W2S);

    const int tid  = threadIdx.x;
    const int wid  = tid >> 5;
    const int lane = tid & 31;
    const int row0 = blockIdx.x * 128;

    // ---------------- phase 0: stage x image + N weights + biases ----------
    for (int i = tid; i < 128 * 58; i += 256) {
        int r = i / 58, c = i - r * 58;
        float v = x[(size_t)(row0 + r) * 58 + c];
        if (c < 4) xc[r * 4 + c] = v;
        else *(__half*)(smem + SM_AIMG + sw128((uint32_t)(r * 128 + (c - 4) * 2))) =
                 __float2half(v);
    }
    for (int i = tid; i < 128 * 10; i += 256) {   // zero pad cols 54..63
        int r = i / 10, k = 54 + (i - (i / 10) * 10);
        *(unsigned short*)(smem + SM_AIMG + sw128((uint32_t)(r * 128 + k * 2))) = 0;
    }
    {
        const uint4* s0 = (const uint4*)g_bn1; uint4* d0 = (uint4*)(smem + SM_R1A);
        const uint4* s1 = (const uint4*)g_bn2; uint4* d1 = (uint4*)(smem + SM_R1B);
#pragma unroll
        for (int i = 0; i < 4; ++i) {
            d0[tid + 256 * i] = s0[tid + 256 * i];
            d1[tid + 256 * i] = s1[tid + 256 * i];
        }
    }
    if (tid < 128) {
        cb1[tid] = Cb1v[tid]; bn1[tid] = Nb1v[tid]; bf1[tid] = Fb1v[tid];
    } else {
        int t = tid - 128;
        if (t < 64) { bn2[t] = (t < 54) ? Nb2v[t] : 0.f;
                      bf2[t] = (t < 57) ? Fb2v[t] : 0.f; }
        if (t < 4)  cb2[t] = (t < 3) ? Cb2v[t] : 0.f;
    }
    for (int i = tid; i < 512; i += 256) { int k = i >> 7, j = i & 127; cw1t[j * 4 + k] = Cw1[i]; }
    for (int i = tid; i < 384; i += 256) { int j = i / 3, m = i - j * 3; cw2[j * 4 + m] = Cw2[i]; }
    __syncthreads();

    // ---------------- stage C (threads 0..127, fp32 scalar) ----------------
    float c0 = 0.f, c1 = 0.f, c2 = 0.f;
    if (tid < 128) {
        float cx0 = xc[tid * 4 + 0], cx1 = xc[tid * 4 + 1];
        float cx2 = xc[tid * 4 + 2], cx3 = xc[tid * 4 + 3];
        c0 = cb2[0]; c1 = cb2[1]; c2 = cb2[2];
        for (int j = 0; j < 128; ++j) {
            const float* w = &cw1t[j * 4];
            float h = cb1[j] + cx0 * w[0] + cx1 * w[1] + cx2 * w[2] + cx3 * w[3];
            h = fmaxf(h, 0.f);
            const float* w2 = &cw2[j * 4];
            c0 += h * w2[0]; c1 += h * w2[1]; c2 += h * w2[2];
        }
    }

    // ---------------- N1: h = relu(xN @ Nw1 + b1) -> himg -------------------
    layer_wide(sbase + SM_AIMG, sbase + SM_R1A, bn1, smem + SM_HIMG, wid, lane);
    __syncthreads();

    // ---------------- N2: n = h @ Nw2 + b2 -> aimg cols 3..56 ---------------
    layer_narrow(sbase + SM_HIMG, sbase + SM_R1B, bn2, smem + SM_AIMG,
                 3, 54, 7, wid, lane);
    if (tid < 128) {   // c -> aimg cols 0..2
        *(__half*)(smem + SM_AIMG + sw128((uint32_t)(tid * 128 + 0))) = __float2half(c0);
        *(__half*)(smem + SM_AIMG + sw128((uint32_t)(tid * 128 + 2))) = __float2half(c1);
        *(__half*)(smem + SM_AIMG + sw128((uint32_t)(tid * 128 + 4))) = __float2half(c2);
    }
    __syncthreads();

    // ---------------- load F weights into R1 --------------------------------
    {
        const uint4* s0 = (const uint4*)g_bf1; uint4* d0 = (uint4*)(smem + SM_R1A);
        const uint4* s1 = (const uint4*)g_bf2; uint4* d1 = (uint4*)(smem + SM_R1B);
#pragma unroll
        for (int i = 0; i < 4; ++i) {
            d0[tid + 256 * i] = s0[tid + 256 * i];
            d1[tid + 256 * i] = s1[tid + 256 * i];
        }
    }
    __syncthreads();

    // ---------------- F1: h = relu(fin @ Fw1 + b1) -> himg ------------------
    layer_wide(sbase + SM_AIMG, sbase + SM_R1A, bf1, smem + SM_HIMG, wid, lane);
    __syncthreads();

    // ---------------- F2 (+ preload O branch0 / b1 / w2 pair0) --------------
    {
        const uint4* s = (const uint4*)g_w1h; uint4* d = (uint4*)(smem + SM_R1A);
#pragma unroll
        for (int i = 0; i < 4; ++i) d[tid + 256 * i] = s[tid + 256 * i];
        if (tid < 128) {
            b1s[tid]       = Ob1[tid];
            b1s[128 + tid] = Ob1[128 + tid];
        } else {
            int j = tid - 128;
            float* p0 = w2s + j * 4;
            p0[0] = Ow2[j * 3 + 0]; p0[1] = Ow2[j * 3 + 1]; p0[2] = Ow2[j * 3 + 2]; p0[3] = 0.f;
            float* p1 = w2s + 512 + j * 4;
            p1[0] = Ow2[384 + j * 3 + 0]; p1[1] = Ow2[384 + j * 3 + 1];
            p1[2] = Ow2[384 + j * 3 + 2]; p1[3] = 0.f;
        }
    }
    layer_narrow(sbase + SM_HIMG, sbase + SM_R1B, bf2, smem + SM_AIMG,
                 0, 57, 8, wid, lane);
    __syncthreads();

    // ---------------- O branch1 -> R1B (F2's B now free) ---------------------
    {
        const uint4* s = (const uint4*)(g_w1h + 8192); uint4* d = (uint4*)(smem + SM_R1B);
#pragma unroll
        for (int i = 0; i < 4; ++i) d[tid + 256 * i] = s[tid + 256 * i];
    }
    __syncthreads();

    // ---------------- O stage: dual-branch HMMA loop -------------------------
    uint32_t a[4][4];
    {
        int m01 = (lane >> 3) & 1, kh = lane >> 4;
        int rg  = (wid << 4) + (lane & 7) + (m01 << 3);
#pragma unroll
        for (int kt = 0; kt < 4; ++kt) {
            uint32_t off = sw128((uint32_t)(rg * 128 + kt * 32 + kh * 16));
            ldsm_x4(sbase + SM_AIMG + off, a[kt][0], a[kt][1], a[kt][2], a[kt][3]);
        }
    }
    const int quad = lane & 3;
    const int qrow = lane >> 2;
    const int rA   = (wid << 4) + qrow;
    const int rB   = rA + 8;
    const int bjrow = lane & 7;
    const int bkt   = lane >> 4;
    const int bkh   = (lane >> 3) & 1;

    for (int p = 0; p < 27; ++p) {
        const int buf = p & 1, nxt = buf ^ 1;
        const int nP = 2 * p, nQ = nP + 1;

        if (p < 26) {
            uint32_t dA = nxt ? SM_OB2 : SM_R1A;
            uint32_t dB = nxt ? SM_OB3 : SM_R1B;
            const uint4* s0 = (const uint4*)(g_w1h + (nP + 2) * 8192);
            const uint4* s1 = (const uint4*)(g_w1h + (nP + 3) * 8192);
            uint4* p0 = (uint4*)(smem + dA);
            uint4* p1 = (uint4*)(smem + dB);
#pragma unroll
            for (int i = 0; i < 4; ++i) {
                p0[tid + 256 * i] = s0[tid + 256 * i];
                p1[tid + 256 * i] = s1[tid + 256 * i];
            }
            if (tid < 128) {
                b1s[nxt * 256 + tid]       = Ob1[(nP + 2) * 128 + tid];
                b1s[nxt * 256 + 128 + tid] = Ob1[(nP + 3) * 128 + tid];
            } else {
                int j = tid - 128;
                float* d0 = w2s + nxt * 1024 + j * 4;
                d0[0] = Ow2[(nP + 2) * 384 + j * 3 + 0];
                d0[1] = Ow2[(nP + 2) * 384 + j * 3 + 1];
                d0[2] = Ow2[(nP + 2) * 384 + j * 3 + 2];
                d0[3] = 0.f;
                float* d1 = w2s + nxt * 1024 + 512 + j * 4;
                d1[0] = Ow2[(nP + 3) * 384 + j * 3 + 0];
                d1[1] = Ow2[(nP + 3) * 384 + j * 3 + 1];
                d1[2] = Ow2[(nP + 3) * 384 + j * 3 + 2];
                d1[3] = 0.f;
            }
        }

        const uint32_t sb0 = sbase + (buf ? SM_OB2 : SM_R1A);
        const uint32_t sb1 = sbase + (buf ? SM_OB3 : SM_R1B);
        const float*  b1P = b1s + buf * 256;
        const float*  b1Q = b1P + 128;
        const float4* w2P = (const float4*)(w2s + buf * 1024);
        const float4* w2Q = (const float4*)(w2s + buf * 1024 + 512);

        float lPA0 = 0.f, lPA1 = 0.f, lPA2 = 0.f, lPB0 = 0.f, lPB1 = 0.f, lPB2 = 0.f;
        float lQA0 = 0.f, lQA1 = 0.f, lQA2 = 0.f, lQB0 = 0.f, lQB1 = 0.f, lQB2 = 0.f;

#pragma unroll 4
        for (int nt = 0; nt < 16; ++nt) {
            uint32_t off0 = sw128((uint32_t)((nt * 8 + bjrow) * 128 + bkt * 32 + bkh * 16));
            uint32_t off1 = sw128((uint32_t)((nt * 8 + bjrow) * 128 + (bkt + 2) * 32 + bkh * 16));
            uint32_t bP[4][2], bQ[4][2];
            ldsm_x4(sb0 + off0, bP[0][0], bP[0][1], bP[1][0], bP[1][1]);
            ldsm_x4(sb0 + off1, bP[2][0], bP[2][1], bP[3][0], bP[3][1]);
            ldsm_x4(sb1 + off0, bQ[0][0], bQ[0][1], bQ[1][0], bQ[1][1]);
            ldsm_x4(sb1 + off1, bQ[2][0], bQ[2][1], bQ[3][0], bQ[3][1]);

            float dP0 = 0.f, dP1 = 0.f, dP2 = 0.f, dP3 = 0.f;
            float dQ0 = 0.f, dQ1 = 0.f, dQ2 = 0.f, dQ3 = 0.f;
#pragma unroll
            for (int kt = 0; kt < 4; ++kt) {
                mma16816(dP0, dP1, dP2, dP3,
                         a[kt][0], a[kt][1], a[kt][2], a[kt][3], bP[kt][0], bP[kt][1]);
                mma16816(dQ0, dQ1, dQ2, dQ3,
                         a[kt][0], a[kt][1], a[kt][2], a[kt][3], bQ[kt][0], bQ[kt][1]);
            }

            const int j0 = nt * 8 + quad * 2;
            {
                float2 bb = *(const float2*)(b1P + j0);
                float4 wza = w2P[j0], wzb = w2P[j0 + 1];
                float h;
                h = fmaxf(dP0 + bb.x, 0.f);
                lPA0 = fmaf(h, wza.x, lPA0); lPA1 = fmaf(h, wza.y, lPA1); lPA2 = fmaf(h, wza.z, lPA2);
                h = fmaxf(dP1 + bb.y, 0.f);
                lPA0 = fmaf(h, wzb.x, lPA0); lPA1 = fmaf(h, wzb.y, lPA1); lPA2 = fmaf(h, wzb.z, lPA2);
                h = fmaxf(dP2 + bb.x, 0.f);
                lPB0 = fmaf(h, wza.x, lPB0); lPB1 = fmaf(h, wza.y, lPB1); lPB2 = fmaf(h, wza.z, lPB2);
                h = fmaxf(dP3 + bb.y, 0.f);
                lPB0 = fmaf(h, wzb.x, lPB0); lPB1 = fmaf(h, wzb.y, lPB1); lPB2 = fmaf(h, wzb.z, lPB2);
            }
            {
                float2 bb = *(const float2*)(b1Q + j0);
                float4 wza = w2Q[j0], wzb = w2Q[j0 + 1];
                float h;
                h = fmaxf(dQ0 + bb.x, 0.f);
                lQA0 = fmaf(h, wza.x, lQA0); lQA1 = fmaf(h, wza.y, lQA1); lQA2 = fmaf(h, wza.z, lQA2);
                h = fmaxf(dQ1 + bb.y, 0.f);
                lQA0 = fmaf(h, wzb.x, lQA0); lQA1 = fmaf(h, wzb.y, lQA1); lQA2 = fmaf(h, wzb.z, lQA2);
                h = fmaxf(dQ2 + bb.x, 0.f);
                lQB0 = fmaf(h, wza.x, lQB0); lQB1 = fmaf(h, wza.y, lQB1); lQB2 = fmaf(h, wza.z, lQB2);
                h = fmaxf(dQ3 + bb.y, 0.f);
                lQB0 = fmaf(h, wzb.x, lQB0); lQB1 = fmaf(h, wzb.y, lQB1); lQB2 = fmaf(h, wzb.z, lQB2);
            }
        }

#pragma unroll
        for (int m = 1; m <= 2; m <<= 1) {
            lPA0 += __shfl_xor_sync(0xffffffffu, lPA0, m);
            lPA1 += __shfl_xor_sync(0xffffffffu, lPA1, m);
            lPA2 += __shfl_xor_sync(0xffffffffu, lPA2, m);
            lPB0 += __shfl_xor_sync(0xffffffffu, lPB0, m);
            lPB1 += __shfl_xor_sync(0xffffffffu, lPB1, m);
            lPB2 += __shfl_xor_sync(0xffffffffu, lPB2, m);
            lQA0 += __shfl_xor_sync(0xffffffffu, lQA0, m);
            lQA1 += __shfl_xor_sync(0xffffffffu, lQA1, m);
            lQA2 += __shfl_xor_sync(0xffffffffu, lQA2, m);
            lQB0 += __shfl_xor_sync(0xffffffffu, lQB0, m);
            lQB1 += __shfl_xor_sync(0xffffffffu, lQB1, m);
            lQB2 += __shfl_xor_sync(0xffffffffu, lQB2, m);
        }

        if (quad == 0) {
            float cP0 = Ob2[nP * 3 + 0], cP1 = Ob2[nP * 3 + 1], cP2 = Ob2[nP * 3 + 2];
            float cQ0 = Ob2[nQ * 3 + 0], cQ1 = Ob2[nQ * 3 + 1], cQ2 = Ob2[nQ * 3 + 2];
            {
                float l0 = lPA0 + cP0, l1 = lPA1 + cP1, l2 = lPA2 + cP2;
                float mx = fmaxf(l0, fmaxf(l1, l2));
                float e0 = __expf(l0 - mx), e1 = __expf(l1 - mx), e2 = __expf(l2 - mx);
                float inv = 1.f / (e0 + e1 + e2);
                float* o = out + (size_t)(row0 + rA) * 162 + nP * 3;
                o[0] = e0 * inv; o[1] = e1 * inv; o[2] = e2 * inv;
            }
            {
                float l0 = lPB0 + cP0, l1 = lPB1 + cP1, l2 = lPB2 + cP2;
                float mx = fmaxf(l0, fmaxf(l1, l2));
                float e0 = __expf(l0 - mx), e1 = __expf(l1 - mx), e2 = __expf(l2 - mx);
                float inv = 1.f / (e0 + e1 + e2);
                float* o = out + (size_t)(row0 + rB) * 162 + nP * 3;
                o[0] = e0 * inv; o[1] = e1 * inv; o[2] = e2 * inv;
            }
            {
                float l0 = lQA0 + cQ0, l1 = lQA1 + cQ1, l2 = lQA2 + cQ2;
                float mx = fmaxf(l0, fmaxf(l1, l2));
                float e0 = __expf(l0 - mx), e1 = __expf(l1 - mx), e2 = __expf(l2 - mx);
                float inv = 1.f / (e0 + e1 + e2);
                float* o = out + (size_t)(row0 + rA) * 162 + nQ * 3;
                o[0] = e0 * inv; o[1] = e1 * inv; o[2] = e2 * inv;
            }
            {
                float l0 = lQB0 + cQ0, l1 = lQB1 + cQ1, l2 = lQB2 + cQ2;
                float mx = fmaxf(l0, fmaxf(l1, l2));
                float e0 = __expf(l0 - mx), e1 = __expf(l1 - mx), e2 = __expf(l2 - mx);
                float inv = 1.f / (e0 + e1 + e2);
                float* o = out + (size_t)(row0 + rB) * 162 + nQ * 3;
                o[0] = e0 * inv; o[1] = e1 * inv; o[2] = e2 * inv;
            }
        }
        __syncthreads();
    }
}

// ============================================================================
extern "C" void kernel_launch(void* const* d_in, const int* in_sizes, int n_in,
                              void* d_out, int out_size)
{
    const float* x   = (const float*)d_in[0];
    const float* Cw1 = (const float*)d_in[1];
    const float* Cb1 = (const float*)d_in[2];
    const float* Cw2 = (const float*)d_in[3];
    const float* Cb2 = (const float*)d_in[4];
    const float* Nw1 = (const float*)d_in[5];
    const float* Nb1 = (const float*)d_in[6];
    const float* Nw2 = (const float*)d_in[7];
    const float* Nb2 = (const float*)d_in[8];
    const float* Fw1 = (const float*)d_in[9];
    const float* Fb1 = (const float*)d_in[10];
    const float* Fw2 = (const float*)d_in[11];
    const float* Fb2 = (const float*)d_in[12];
    const float* Ow1 = (const float*)d_in[13];
    const float* Ob1 = (const float*)d_in[14];
    const float* Ow2 = (const float*)d_in[15];
    const float* Ob2 = (const float*)d_in[16];
    float* out = (float*)d_out;

    cudaFuncSetAttribute(k_fused, cudaFuncAttributeMaxDynamicSharedMemorySize, SM_TOT);

    const int conv_elems = NB * 8192 + 4 * 8192;
    k_convert<<<(conv_elems + 255) / 256, 256>>>(Ow1, Nw1, Nw2, Fw1, Fw2);

    k_fused<<<NTILES, 256, SM_TOT>>>(
        x, Cw1, Cb1, Cw2, Cb2, Nb1, Nb2, Fb1, Fb2, Ob1, Ow2, Ob2, out);
}

// round 7
// speedup vs baseline: 7.1973x; 1.2085x over previous
#include <cuda_runtime.h>
#include <cuda_fp16.h>
#include <cstdint>

#define B_ROWS 65536
#define NTILES 512
#define NB     54

// ========================= device scratch (fp16 B images) ===================
__device__ __align__(16) __half g_w1h[NB * 8192];  // O_w1: 54 x [j=128][k=64]
__device__ __align__(16) __half g_bn1[8192];       // N_w1: [j=128][k=64]
__device__ __align__(16) __half g_bn2[8192];       // N_w2: [m=64][k=128]
__device__ __align__(16) __half g_bf1[8192];       // F_w1: [j=128][k=64]
__device__ __align__(16) __half g_bf2[8192];       // F_w2: [m=64][k=128]

// ============================= PTX helpers =================================
__device__ __forceinline__ uint32_t smem_u32(const void* p) {
    uint32_t a;
    asm("{ .reg .u64 t; cvta.to.shared.u64 t, %1; cvt.u32.u64 %0, t; }"
        : "=r"(a) : "l"(p));
    return a;
}
__device__ __forceinline__ void ldsm_x4(uint32_t addr, uint32_t& r0, uint32_t& r1,
                                        uint32_t& r2, uint32_t& r3) {
    asm volatile("ldmatrix.sync.aligned.m8n8.x4.shared.b16 {%0,%1,%2,%3}, [%4];"
                 : "=r"(r0), "=r"(r1), "=r"(r2), "=r"(r3) : "r"(addr));
}
__device__ __forceinline__ void mma16816(float& d0, float& d1, float& d2, float& d3,
                                         uint32_t a0, uint32_t a1, uint32_t a2, uint32_t a3,
                                         uint32_t b0, uint32_t b1) {
    asm volatile("mma.sync.aligned.m16n8k16.row.col.f32.f16.f16.f32 "
                 "{%0,%1,%2,%3}, {%4,%5,%6,%7}, {%8,%9}, {%0,%1,%2,%3};"
                 : "+f"(d0), "+f"(d1), "+f"(d2), "+f"(d3)
                 : "r"(a0), "r"(a1), "r"(a2), "r"(a3), "r"(b0), "r"(b1));
}
__device__ __forceinline__ uint32_t sw128(uint32_t off) {
    return off ^ ((off >> 3) & 0x70);
}

// ============================================================================
// Convert: all layer-1/2 weights -> swizzled fp16 tile images.
// ============================================================================
__global__ __launch_bounds__(256) void k_convert(
    const float* __restrict__ Ow1,
    const float* __restrict__ Nw1, const float* __restrict__ Nw2,
    const float* __restrict__ Fw1, const float* __restrict__ Fw2)
{
    int idx = blockIdx.x * 256 + threadIdx.x;
    if (idx < NB * 8192) {
        int j = idx & 127, k = (idx >> 7) & 63, n = idx >> 13;
        float v = (k < 57) ? Ow1[n * 7296 + k * 128 + j] : 0.f;
        g_w1h[n * 8192 + (sw128((unsigned)(j * 128 + k * 2)) >> 1)] = __float2half(v);
        return;
    }
    int t = idx - NB * 8192;
    if (t >= 4 * 8192) return;
    int img = t >> 13, e = t & 8191;
    if (img == 0) {
        int j = e >> 6, k = e & 63;
        float v = (k < 54) ? Nw1[k * 128 + j] : 0.f;
        g_bn1[sw128((unsigned)(j * 128 + k * 2)) >> 1] = __float2half(v);
    } else if (img == 1) {
        int j = e >> 6, k = e & 63;
        float v = (k < 57) ? Fw1[k * 128 + j] : 0.f;
        g_bf1[sw128((unsigned)(j * 128 + k * 2)) >> 1] = __float2half(v);
    } else if (img == 2) {
        int m = e >> 7, k = e & 127;
        float v = (m < 54) ? Nw2[k * 54 + m] : 0.f;
        g_bn2[sw128((unsigned)(m * 256 + k * 2)) >> 1] = __float2half(v);
    } else {
        int m = e >> 7, k = e & 127;
        float v = (m < 57) ? Fw2[k * 57 + m] : 0.f;
        g_bf2[sw128((unsigned)(m * 256 + k * 2)) >> 1] = __float2half(v);
    }
}

// ============================ SMEM layout ===================================
#define SM_AIMG 0          // 16 KB
#define SM_R1A  16384      // 16 KB
#define SM_R1B  32768      // 16 KB
#define SM_HIMG 49152      // 32 KB (alias O buf2/3)
#define SM_OB2  49152
#define SM_OB3  65536
#define SM_XC   81920      // 128*4 f32
#define SM_CW1  83968
#define SM_CW2  86016
#define SM_CB1  88064
#define SM_CB2  88576
#define SM_BN1  88608
#define SM_BN2  89120
#define SM_BF1  89376
#define SM_BF2  89888
#define SM_W2S  90144      // 2 pairbuf x 2 branch x 128 j x float4 = 8192 B
#define SM_TOT  98336

// ---- layer: 64-K HMMA, 128 out cols, bias+relu, fp16 -> himg (RS=256) ------
// 4 warps; warp owns rows 32w..32w+31 (two m-tiles).
__device__ __forceinline__ void layer_wide(
    uint32_t sA, uint32_t sB, const float* __restrict__ bias, char* himg,
    int wid, int lane)
{
    const int m01 = (lane >> 3) & 1, kh = lane >> 4;
    const int quad = lane & 3, qrow = lane >> 2;
    const int bjrow = lane & 7, bkt = lane >> 4, bkh = (lane >> 3) & 1;

    uint32_t a[2][4][4];
#pragma unroll
    for (int mt = 0; mt < 2; ++mt) {
        int rg = wid * 32 + mt * 16 + (lane & 7) + (m01 << 3);
#pragma unroll
        for (int kt = 0; kt < 4; ++kt) {
            uint32_t off = sw128((uint32_t)(rg * 128 + kt * 32 + kh * 16));
            ldsm_x4(sA + off, a[mt][kt][0], a[mt][kt][1], a[mt][kt][2], a[mt][kt][3]);
        }
    }
#pragma unroll 4
    for (int nt = 0; nt < 16; ++nt) {
        uint32_t off0 = sw128((uint32_t)((nt * 8 + bjrow) * 128 + bkt * 32 + bkh * 16));
        uint32_t off1 = sw128((uint32_t)((nt * 8 + bjrow) * 128 + (bkt + 2) * 32 + bkh * 16));
        uint32_t b[4][2];
        ldsm_x4(sB + off0, b[0][0], b[0][1], b[1][0], b[1][1]);
        ldsm_x4(sB + off1, b[2][0], b[2][1], b[3][0], b[3][1]);
        int j0 = nt * 8 + quad * 2;
        float2 bb = *(const float2*)(bias + j0);
#pragma unroll
        for (int mt = 0; mt < 2; ++mt) {
            float d0 = 0.f, d1 = 0.f, d2 = 0.f, d3 = 0.f;
#pragma unroll
            for (int kt = 0; kt < 4; ++kt)
                mma16816(d0, d1, d2, d3,
                         a[mt][kt][0], a[mt][kt][1], a[mt][kt][2], a[mt][kt][3],
                         b[kt][0], b[kt][1]);
            int rA = wid * 32 + mt * 16 + qrow, rB = rA + 8;
            __half2 hA = __floats2half2_rn(fmaxf(d0 + bb.x, 0.f), fmaxf(d1 + bb.y, 0.f));
            __half2 hB = __floats2half2_rn(fmaxf(d2 + bb.x, 0.f), fmaxf(d3 + bb.y, 0.f));
            *(__half2*)(himg + sw128((uint32_t)(rA * 256 + j0 * 2))) = hA;
            *(__half2*)(himg + sw128((uint32_t)(rB * 256 + j0 * 2))) = hB;
        }
    }
}

// ---- layer: 128-K HMMA, ntn*8 out cols, bias, fp16 -> aimg col m+coff ------
__device__ __forceinline__ void layer_narrow(
    uint32_t sH, uint32_t sB, const float* __restrict__ bias, char* outimg,
    int coff, int mlim, int ntn, int wid, int lane)
{
    const int m01 = (lane >> 3) & 1, kh = lane >> 4;
    const int quad = lane & 3, qrow = lane >> 2;
    const int bjrow = lane & 7, bkt = lane >> 4, bkh = (lane >> 3) & 1;

    for (int mt = 0; mt < 2; ++mt) {
        int rg = wid * 32 + mt * 16 + (lane & 7) + (m01 << 3);
        uint32_t a[8][4];
#pragma unroll
        for (int kt = 0; kt < 8; ++kt) {
            uint32_t off = sw128((uint32_t)(rg * 256 + kt * 32 + kh * 16));
            ldsm_x4(sH + off, a[kt][0], a[kt][1], a[kt][2], a[kt][3]);
        }
        for (int nt = 0; nt < ntn; ++nt) {
            uint32_t b[8][2];
#pragma unroll
            for (int q = 0; q < 4; ++q) {
                uint32_t off = sw128((uint32_t)((nt * 8 + bjrow) * 256 + q * 64 + bkt * 32 + bkh * 16));
                ldsm_x4(sB + off, b[2 * q][0], b[2 * q][1], b[2 * q + 1][0], b[2 * q + 1][1]);
            }
            float d0 = 0.f, d1 = 0.f, d2 = 0.f, d3 = 0.f;
#pragma unroll
            for (int kt = 0; kt < 8; ++kt)
                mma16816(d0, d1, d2, d3, a[kt][0], a[kt][1], a[kt][2], a[kt][3],
                         b[kt][0], b[kt][1]);
            int m0 = nt * 8 + quad * 2, m1 = m0 + 1;
            int rA = wid * 32 + mt * 16 + qrow, rB = rA + 8;
            if (m0 < mlim) {
                *(__half*)(outimg + sw128((uint32_t)(rA * 128 + (m0 + coff) * 2))) =
                    __float2half(d0 + bias[m0]);
                *(__half*)(outimg + sw128((uint32_t)(rB * 128 + (m0 + coff) * 2))) =
                    __float2half(d2 + bias[m0]);
            }
            if (m1 < mlim) {
                *(__half*)(outimg + sw128((uint32_t)(rA * 128 + (m1 + coff) * 2))) =
                    __float2half(d1 + bias[m1]);
                *(__half*)(outimg + sw128((uint32_t)(rB * 128 + (m1 + coff) * 2))) =
                    __float2half(d3 + bias[m1]);
            }
        }
    }
}

// ============================================================================
// Fused kernel, 128 threads / 4 warps, 128 rows per CTA.
// ============================================================================
__global__ void __launch_bounds__(128, 2) k_fused(
    const float* __restrict__ x,
    const float* __restrict__ Cw1, const float* __restrict__ Cb1v,
    const float* __restrict__ Cw2, const float* __restrict__ Cb2v,
    const float* __restrict__ Nb1v, const float* __restrict__ Nb2v,
    const float* __restrict__ Fb1v, const float* __restrict__ Fb2v,
    const float* __restrict__ Ob1, const float* __restrict__ Ow2,
    const float* __restrict__ Ob2, float* __restrict__ out)
{
    extern __shared__ char smem[];
    const uint32_t sbase = smem_u32(smem);
    float* xc   = (float*)(smem + SM_XC);
    float* cw1t = (float*)(smem + SM_CW1);
    float* cw2  = (float*)(smem + SM_CW2);
    float* cb1  = (float*)(smem + SM_CB1);
    float* cb2  = (float*)(smem + SM_CB2);
    float* bn1  = (float*)(smem + SM_BN1);
    float* bn2  = (float*)(smem + SM_BN2);
    float* bf1  = (float*)(smem + SM_BF1);
    float* bf2  = (float*)(smem + SM_BF2);
    float* w2s  = (float*)(smem + SM_W2S);   // [pairbuf][branch][j] float4 {w2x,w2y,w2z,b1}

    const int tid  = threadIdx.x;
    const int wid  = tid >> 5;
    const int lane = tid & 31;
    const int row0 = blockIdx.x * 128;

    // ---------------- phase 0: stage x image + N weights + biases ----------
    for (int i = tid; i < 128 * 58; i += 128) {
        int r = i / 58, c = i - r * 58;
        float v = x[(size_t)(row0 + r) * 58 + c];
        if (c < 4) xc[r * 4 + c] = v;
        else *(__half*)(smem + SM_AIMG + sw128((uint32_t)(r * 128 + (c - 4) * 2))) =
                 __float2half(v);
    }
    for (int i = tid; i < 128 * 10; i += 128) {
        int r = i / 10, k = 54 + (i - (i / 10) * 10);
        *(unsigned short*)(smem + SM_AIMG + sw128((uint32_t)(r * 128 + k * 2))) = 0;
    }
    {
        const uint4* s0 = (const uint4*)g_bn1; uint4* d0 = (uint4*)(smem + SM_R1A);
        const uint4* s1 = (const uint4*)g_bn2; uint4* d1 = (uint4*)(smem + SM_R1B);
#pragma unroll
        for (int i = 0; i < 8; ++i) {
            d0[tid + 128 * i] = s0[tid + 128 * i];
            d1[tid + 128 * i] = s1[tid + 128 * i];
        }
    }
    cb1[tid] = Cb1v[tid]; bn1[tid] = Nb1v[tid]; bf1[tid] = Fb1v[tid];
    if (tid < 64) {
        bn2[tid] = (tid < 54) ? Nb2v[tid] : 0.f;
        bf2[tid] = (tid < 57) ? Fb2v[tid] : 0.f;
    }
    if (tid < 4) cb2[tid] = (tid < 3) ? Cb2v[tid] : 0.f;
    for (int i = tid; i < 512; i += 128) { int k = i >> 7, j = i & 127; cw1t[j * 4 + k] = Cw1[i]; }
    for (int i = tid; i < 384; i += 128) { int j = i / 3, m = i - j * 3; cw2[j * 4 + m] = Cw2[i]; }
    __syncthreads();

    // ---------------- stage C (one row per thread, fp32 scalar) ------------
    float c0, c1, c2;
    {
        float cx0 = xc[tid * 4 + 0], cx1 = xc[tid * 4 + 1];
        float cx2 = xc[tid * 4 + 2], cx3 = xc[tid * 4 + 3];
        c0 = cb2[0]; c1 = cb2[1]; c2 = cb2[2];
        for (int j = 0; j < 128; ++j) {
            const float* w = &cw1t[j * 4];
            float h = cb1[j] + cx0 * w[0] + cx1 * w[1] + cx2 * w[2] + cx3 * w[3];
            h = fmaxf(h, 0.f);
            const float* w2 = &cw2[j * 4];
            c0 += h * w2[0]; c1 += h * w2[1]; c2 += h * w2[2];
        }
    }

    // ---------------- N1 -> himg --------------------------------------------
    layer_wide(sbase + SM_AIMG, sbase + SM_R1A, bn1, smem + SM_HIMG, wid, lane);
    __syncthreads();

    // ---------------- N2 -> aimg cols 3..56 ---------------------------------
    layer_narrow(sbase + SM_HIMG, sbase + SM_R1B, bn2, smem + SM_AIMG, 3, 54, 7, wid, lane);
    {   // c -> aimg cols 0..2
        *(__half*)(smem + SM_AIMG + sw128((uint32_t)(tid * 128 + 0))) = __float2half(c0);
        *(__half*)(smem + SM_AIMG + sw128((uint32_t)(tid * 128 + 2))) = __float2half(c1);
        *(__half*)(smem + SM_AIMG + sw128((uint32_t)(tid * 128 + 4))) = __float2half(c2);
    }
    __syncthreads();

    // ---------------- F weights into R1 -------------------------------------
    {
        const uint4* s0 = (const uint4*)g_bf1; uint4* d0 = (uint4*)(smem + SM_R1A);
        const uint4* s1 = (const uint4*)g_bf2; uint4* d1 = (uint4*)(smem + SM_R1B);
#pragma unroll
        for (int i = 0; i < 8; ++i) {
            d0[tid + 128 * i] = s0[tid + 128 * i];
            d1[tid + 128 * i] = s1[tid + 128 * i];
        }
    }
    __syncthreads();

    // ---------------- F1 -> himg ---------------------------------------------
    layer_wide(sbase + SM_AIMG, sbase + SM_R1A, bf1, smem + SM_HIMG, wid, lane);
    __syncthreads();

    // ---------------- F2 (+ preload O pair0) --------------------------------
    {
        const uint4* s = (const uint4*)g_w1h; uint4* d = (uint4*)(smem + SM_R1A);
#pragma unroll
        for (int i = 0; i < 8; ++i) d[tid + 128 * i] = s[tid + 128 * i];
        // pack {w2, b1} for branches 0,1
        float4 p0, p1;
        p0.x = Ow2[tid * 3 + 0]; p0.y = Ow2[tid * 3 + 1]; p0.z = Ow2[tid * 3 + 2];
        p0.w = Ob1[tid];
        p1.x = Ow2[384 + tid * 3 + 0]; p1.y = Ow2[384 + tid * 3 + 1];
        p1.z = Ow2[384 + tid * 3 + 2]; p1.w = Ob1[128 + tid];
        ((float4*)w2s)[tid] = p0;
        ((float4*)w2s)[128 + tid] = p1;
    }
    layer_narrow(sbase + SM_HIMG, sbase + SM_R1B, bf2, smem + SM_AIMG, 0, 57, 8, wid, lane);
    __syncthreads();

    // ---------------- O branch1 -> R1B ---------------------------------------
    {
        const uint4* s = (const uint4*)(g_w1h + 8192); uint4* d = (uint4*)(smem + SM_R1B);
#pragma unroll
        for (int i = 0; i < 8; ++i) d[tid + 128 * i] = s[tid + 128 * i];
    }
    __syncthreads();

    // ---------------- O stage: dual-branch, dual m-tile HMMA loop ------------
    uint32_t a[2][4][4];
    {
        int m01 = (lane >> 3) & 1, kh = lane >> 4;
#pragma unroll
        for (int mt = 0; mt < 2; ++mt) {
            int rg = wid * 32 + mt * 16 + (lane & 7) + (m01 << 3);
#pragma unroll
            for (int kt = 0; kt < 4; ++kt) {
                uint32_t off = sw128((uint32_t)(rg * 128 + kt * 32 + kh * 16));
                ldsm_x4(sbase + SM_AIMG + off,
                        a[mt][kt][0], a[mt][kt][1], a[mt][kt][2], a[mt][kt][3]);
            }
        }
    }
    const int quad = lane & 3;
    const int qrow = lane >> 2;
    const int bjrow = lane & 7;
    const int bkt   = lane >> 4;
    const int bkh   = (lane >> 3) & 1;

    for (int p = 0; p < 27; ++p) {
        const int buf = p & 1, nxt = buf ^ 1;
        const int nP = 2 * p, nQ = nP + 1;

        if (p < 26) {
            const uint4* s0 = (const uint4*)(g_w1h + (nP + 2) * 8192);
            const uint4* s1 = (const uint4*)(g_w1h + (nP + 3) * 8192);
            uint4* d0 = (uint4*)(smem + (nxt ? SM_OB2 : SM_R1A));
            uint4* d1 = (uint4*)(smem + (nxt ? SM_OB3 : SM_R1B));
#pragma unroll
            for (int i = 0; i < 8; ++i) {
                d0[tid + 128 * i] = s0[tid + 128 * i];
                d1[tid + 128 * i] = s1[tid + 128 * i];
            }
            float4 q0, q1;
            q0.x = Ow2[(nP + 2) * 384 + tid * 3 + 0];
            q0.y = Ow2[(nP + 2) * 384 + tid * 3 + 1];
            q0.z = Ow2[(nP + 2) * 384 + tid * 3 + 2];
            q0.w = Ob1[(nP + 2) * 128 + tid];
            q1.x = Ow2[(nP + 3) * 384 + tid * 3 + 0];
            q1.y = Ow2[(nP + 3) * 384 + tid * 3 + 1];
            q1.z = Ow2[(nP + 3) * 384 + tid * 3 + 2];
            q1.w = Ob1[(nP + 3) * 128 + tid];
            ((float4*)w2s)[nxt * 256 + tid] = q0;
            ((float4*)w2s)[nxt * 256 + 128 + tid] = q1;
        }

        const uint32_t sb0 = sbase + (buf ? SM_OB2 : SM_R1A);
        const uint32_t sb1 = sbase + (buf ? SM_OB3 : SM_R1B);
        const float4* w2P = (const float4*)w2s + buf * 256;
        const float4* w2Q = w2P + 128;

        float lP[2][6], lQ[2][6];
#pragma unroll
        for (int mt = 0; mt < 2; ++mt)
#pragma unroll
            for (int q = 0; q < 6; ++q) { lP[mt][q] = 0.f; lQ[mt][q] = 0.f; }

#pragma unroll 4
        for (int nt = 0; nt < 16; ++nt) {
            uint32_t off0 = sw128((uint32_t)((nt * 8 + bjrow) * 128 + bkt * 32 + bkh * 16));
            uint32_t off1 = sw128((uint32_t)((nt * 8 + bjrow) * 128 + (bkt + 2) * 32 + bkh * 16));
            uint32_t bP[4][2], bQ[4][2];
            ldsm_x4(sb0 + off0, bP[0][0], bP[0][1], bP[1][0], bP[1][1]);
            ldsm_x4(sb0 + off1, bP[2][0], bP[2][1], bP[3][0], bP[3][1]);
            ldsm_x4(sb1 + off0, bQ[0][0], bQ[0][1], bQ[1][0], bQ[1][1]);
            ldsm_x4(sb1 + off1, bQ[2][0], bQ[2][1], bQ[3][0], bQ[3][1]);

            const int j0 = nt * 8 + quad * 2;
            float4 waP = w2P[j0], wbP = w2P[j0 + 1];
            float4 waQ = w2Q[j0], wbQ = w2Q[j0 + 1];

#pragma unroll
            for (int mt = 0; mt < 2; ++mt) {
                float dP0 = 0.f, dP1 = 0.f, dP2 = 0.f, dP3 = 0.f;
                float dQ0 = 0.f, dQ1 = 0.f, dQ2 = 0.f, dQ3 = 0.f;
#pragma unroll
                for (int kt = 0; kt < 4; ++kt) {
                    mma16816(dP0, dP1, dP2, dP3,
                             a[mt][kt][0], a[mt][kt][1], a[mt][kt][2], a[mt][kt][3],
                             bP[kt][0], bP[kt][1]);
                    mma16816(dQ0, dQ1, dQ2, dQ3,
                             a[mt][kt][0], a[mt][kt][1], a[mt][kt][2], a[mt][kt][3],
                             bQ[kt][0], bQ[kt][1]);
                }
                float h;
                h = fmaxf(dP0 + waP.w, 0.f);
                lP[mt][0] = fmaf(h, waP.x, lP[mt][0]);
                lP[mt][1] = fmaf(h, waP.y, lP[mt][1]);
                lP[mt][2] = fmaf(h, waP.z, lP[mt][2]);
                h = fmaxf(dP1 + wbP.w, 0.f);
                lP[mt][0] = fmaf(h, wbP.x, lP[mt][0]);
                lP[mt][1] = fmaf(h, wbP.y, lP[mt][1]);
                lP[mt][2] = fmaf(h, wbP.z, lP[mt][2]);
                h = fmaxf(dP2 + waP.w, 0.f);
                lP[mt][3] = fmaf(h, waP.x, lP[mt][3]);
                lP[mt][4] = fmaf(h, waP.y, lP[mt][4]);
                lP[mt][5] = fmaf(h, waP.z, lP[mt][5]);
                h = fmaxf(dP3 + wbP.w, 0.f);
                lP[mt][3] = fmaf(h, wbP.x, lP[mt][3]);
                lP[mt][4] = fmaf(h, wbP.y, lP[mt][4]);
                lP[mt][5] = fmaf(h, wbP.z, lP[mt][5]);
                h = fmaxf(dQ0 + waQ.w, 0.f);
                lQ[mt][0] = fmaf(h, waQ.x, lQ[mt][0]);
                lQ[mt][1] = fmaf(h, waQ.y, lQ[mt][1]);
                lQ[mt][2] = fmaf(h, waQ.z, lQ[mt][2]);
                h = fmaxf(dQ1 + wbQ.w, 0.f);
                lQ[mt][0] = fmaf(h, wbQ.x, lQ[mt][0]);
                lQ[mt][1] = fmaf(h, wbQ.y, lQ[mt][1]);
                lQ[mt][2] = fmaf(h, wbQ.z, lQ[mt][2]);
                h = fmaxf(dQ2 + waQ.w, 0.f);
                lQ[mt][3] = fmaf(h, waQ.x, lQ[mt][3]);
                lQ[mt][4] = fmaf(h, waQ.y, lQ[mt][4]);
                lQ[mt][5] = fmaf(h, waQ.z, lQ[mt][5]);
                h = fmaxf(dQ3 + wbQ.w, 0.f);
                lQ[mt][3] = fmaf(h, wbQ.x, lQ[mt][3]);
                lQ[mt][4] = fmaf(h, wbQ.y, lQ[mt][4]);
                lQ[mt][5] = fmaf(h, wbQ.z, lQ[mt][5]);
            }
        }

#pragma unroll
        for (int m = 1; m <= 2; m <<= 1) {
#pragma unroll
            for (int mt = 0; mt < 2; ++mt)
#pragma unroll
                for (int q = 0; q < 6; ++q) {
                    lP[mt][q] += __shfl_xor_sync(0xffffffffu, lP[mt][q], m);
                    lQ[mt][q] += __shfl_xor_sync(0xffffffffu, lQ[mt][q], m);
                }
        }

        if (quad == 0) {
            float cP0 = Ob2[nP * 3 + 0], cP1 = Ob2[nP * 3 + 1], cP2 = Ob2[nP * 3 + 2];
            float cQ0 = Ob2[nQ * 3 + 0], cQ1 = Ob2[nQ * 3 + 1], cQ2 = Ob2[nQ * 3 + 2];
#pragma unroll
            for (int mt = 0; mt < 2; ++mt) {
                int rA = wid * 32 + mt * 16 + qrow, rB = rA + 8;
                {
                    float l0 = lP[mt][0] + cP0, l1 = lP[mt][1] + cP1, l2 = lP[mt][2] + cP2;
                    float mx = fmaxf(l0, fmaxf(l1, l2));
                    float e0 = __expf(l0 - mx), e1 = __expf(l1 - mx), e2 = __expf(l2 - mx);
                    float inv = 1.f / (e0 + e1 + e2);
                    float* o = out + (size_t)(row0 + rA) * 162 + nP * 3;
                    o[0] = e0 * inv; o[1] = e1 * inv; o[2] = e2 * inv;
                }
                {
                    float l0 = lP[mt][3] + cP0, l1 = lP[mt][4] + cP1, l2 = lP[mt][5] + cP2;
                    float mx = fmaxf(l0, fmaxf(l1, l2));
                    float e0 = __expf(l0 - mx), e1 = __expf(l1 - mx), e2 = __expf(l2 - mx);
                    float inv = 1.f / (e0 + e1 + e2);
                    float* o = out + (size_t)(row0 + rB) * 162 + nP * 3;
                    o[0] = e0 * inv; o[1] = e1 * inv; o[2] = e2 * inv;
                }
                {
                    float l0 = lQ[mt][0] + cQ0, l1 = lQ[mt][1] + cQ1, l2 = lQ[mt][2] + cQ2;
                    float mx = fmaxf(l0, fmaxf(l1, l2));
                    float e0 = __expf(l0 - mx), e1 = __expf(l1 - mx), e2 = __expf(l2 - mx);
                    float inv = 1.f / (e0 + e1 + e2);
                    float* o = out + (size_t)(row0 + rA) * 162 + nQ * 3;
                    o[0] = e0 * inv; o[1] = e1 * inv; o[2] = e2 * inv;
                }
                {
                    float l0 = lQ[mt][3] + cQ0, l1 = lQ[mt][4] + cQ1, l2 = lQ[mt][5] + cQ2;
                    float mx = fmaxf(l0, fmaxf(l1, l2));
                    float e0 = __expf(l0 - mx), e1 = __expf(l1 - mx), e2 = __expf(l2 - mx);
                    float inv = 1.f / (e0 + e1 + e2);
                    float* o = out + (size_t)(row0 + rB) * 162 + nQ * 3;
                    o[0] = e0 * inv; o[1] = e1 * inv; o[2] = e2 * inv;
                }
            }
        }
        __syncthreads();
    }
}

// ============================================================================
extern "C" void kernel_launch(void* const* d_in, const int* in_sizes, int n_in,
                              void* d_out, int out_size)
{
    const float* x   = (const float*)d_in[0];
    const float* Cw1 = (const float*)d_in[1];
    const float* Cb1 = (const float*)d_in[2];
    const float* Cw2 = (const float*)d_in[3];
    const float* Cb2 = (const float*)d_in[4];
    const float* Nw1 = (const float*)d_in[5];
    const float* Nb1 = (const float*)d_in[6];
    const float* Nw2 = (const float*)d_in[7];
    const float* Nb2 = (const float*)d_in[8];
    const float* Fw1 = (const float*)d_in[9];
    const float* Fb1 = (const float*)d_in[10];
    const float* Fw2 = (const float*)d_in[11];
    const float* Fb2 = (const float*)d_in[12];
    const float* Ow1 = (const float*)d_in[13];
    const float* Ob1 = (const float*)d_in[14];
    const float* Ow2 = (const float*)d_in[15];
    const float* Ob2 = (const float*)d_in[16];
    float* out = (float*)d_out;

    cudaFuncSetAttribute(k_fused, cudaFuncAttributeMaxDynamicSharedMemorySize, SM_TOT);

    const int conv_elems = NB * 8192 + 4 * 8192;
    k_convert<<<(conv_elems + 255) / 256, 256>>>(Ow1, Nw1, Nw2, Fw1, Fw2);

    k_fused<<<NTILES, 128, SM_TOT>>>(
        x, Cw1, Cb1, Cw2, Cb2, Nb1, Nb2, Fb1, Fb2, Ob1, Ow2, Ob2, out);
}

// round 8
// speedup vs baseline: 7.5125x; 1.0438x over previous
#include <cuda_runtime.h>
#include <cuda_fp16.h>
#include <cstdint>

#define NTILES 512
#define NB     54

// ========================= device scratch (fp16 B images) ===================
__device__ __align__(16) __half g_w1h[NB * 8192];  // O_w1: [j=128][k=64], k57=Ob1
__device__ __align__(16) __half g_bn1[8192];       // N_w1: [j=128][k=64], k54=Nb1
__device__ __align__(16) __half g_bn2[8192];       // N_w2: [m=64][k=128]
__device__ __align__(16) __half g_bf1[8192];       // F_w1: [j=128][k=64], k57=Fb1
__device__ __align__(16) __half g_bf2[8192];       // F_w2: [m=64][k=128]

// ============================= PTX helpers =================================
__device__ __forceinline__ uint32_t smem_u32(const void* p) {
    uint32_t a;
    asm("{ .reg .u64 t; cvta.to.shared.u64 t, %1; cvt.u32.u64 %0, t; }"
        : "=r"(a) : "l"(p));
    return a;
}
__device__ __forceinline__ void ldsm_x4(uint32_t addr, uint32_t& r0, uint32_t& r1,
                                        uint32_t& r2, uint32_t& r3) {
    asm volatile("ldmatrix.sync.aligned.m8n8.x4.shared.b16 {%0,%1,%2,%3}, [%4];"
                 : "=r"(r0), "=r"(r1), "=r"(r2), "=r"(r3) : "r"(addr));
}
__device__ __forceinline__ void mma16816(float& d0, float& d1, float& d2, float& d3,
                                         uint32_t a0, uint32_t a1, uint32_t a2, uint32_t a3,
                                         uint32_t b0, uint32_t b1) {
    asm volatile("mma.sync.aligned.m16n8k16.row.col.f32.f16.f16.f32 "
                 "{%0,%1,%2,%3}, {%4,%5,%6,%7}, {%8,%9}, {%0,%1,%2,%3};"
                 : "+f"(d0), "+f"(d1), "+f"(d2), "+f"(d3)
                 : "r"(a0), "r"(a1), "r"(a2), "r"(a3), "r"(b0), "r"(b1));
}
__device__ __forceinline__ uint32_t sw128(uint32_t off) {
    return off ^ ((off >> 3) & 0x70);
}

// ============================================================================
// Convert: weight images with first-layer biases BAKED at the constant-1 k-col.
// ============================================================================
__global__ __launch_bounds__(256) void k_convert(
    const float* __restrict__ Ow1, const float* __restrict__ Ob1,
    const float* __restrict__ Nw1, const float* __restrict__ Nb1,
    const float* __restrict__ Nw2,
    const float* __restrict__ Fw1, const float* __restrict__ Fb1,
    const float* __restrict__ Fw2)
{
    int idx = blockIdx.x * 256 + threadIdx.x;
    if (idx < NB * 8192) {
        int j = idx & 127, k = (idx >> 7) & 63, n = idx >> 13;
        float v = (k < 57) ? Ow1[n * 7296 + k * 128 + j]
                 : (k == 57 ? Ob1[n * 128 + j] : 0.f);
        g_w1h[n * 8192 + (sw128((unsigned)(j * 128 + k * 2)) >> 1)] = __float2half(v);
        return;
    }
    int t = idx - NB * 8192;
    if (t >= 4 * 8192) return;
    int img = t >> 13, e = t & 8191;
    if (img == 0) {
        int j = e >> 6, k = e & 63;
        float v = (k < 54) ? Nw1[k * 128 + j] : (k == 54 ? Nb1[j] : 0.f);
        g_bn1[sw128((unsigned)(j * 128 + k * 2)) >> 1] = __float2half(v);
    } else if (img == 1) {
        int j = e >> 6, k = e & 63;
        float v = (k < 57) ? Fw1[k * 128 + j] : (k == 57 ? Fb1[j] : 0.f);
        g_bf1[sw128((unsigned)(j * 128 + k * 2)) >> 1] = __float2half(v);
    } else if (img == 2) {
        int m = e >> 7, k = e & 127;
        float v = (m < 54) ? Nw2[k * 54 + m] : 0.f;
        g_bn2[sw128((unsigned)(m * 256 + k * 2)) >> 1] = __float2half(v);
    } else {
        int m = e >> 7, k = e & 127;
        float v = (m < 57) ? Fw2[k * 57 + m] : 0.f;
        g_bf2[sw128((unsigned)(m * 256 + k * 2)) >> 1] = __float2half(v);
    }
}

// ============================ SMEM layout (74.2 KB -> 3 CTAs/SM) ============
#define SM_X    0          // 16 KB: x/f image ; O pairbuf1 tile0
#define SM_W    16384      // 16 KB: weight image (seq) ; O pairbuf1 tile1
#define SM_H0   32768      // 16 KB: himg cols 0-63 ; O pairbuf0 tile0
#define SM_H1   49152      // 16 KB: himg cols 64-127 ; O pairbuf0 tile1
#define SM_W2S  65536      // 8 KB: O-phase w2 float4 [pair][br][j]; overlays C scratch
#define SM_XC   65536      // C-phase only
#define SM_CW1  67584
#define SM_CW2  69632
#define SM_CB1  71680
#define SM_CB2  72192
#define SM_BN2  73728      // 256 B
#define SM_BF2  73984      // 256 B
#define SM_TOT  74240

// ---- layer: 64-K HMMA, 128 out cols, relu (bias baked), fp16 -> H0/H1 ------
__device__ __forceinline__ void layer_wide(
    uint32_t sA, uint32_t sB, char* h0, char* h1, int wid, int lane)
{
    const int m01 = (lane >> 3) & 1, kh = lane >> 4;
    const int quad = lane & 3, qrow = lane >> 2;
    const int bjrow = lane & 7, bkt = lane >> 4, bkh = (lane >> 3) & 1;

    uint32_t a[2][4][4];
#pragma unroll
    for (int mt = 0; mt < 2; ++mt) {
        int rg = wid * 32 + mt * 16 + (lane & 7) + (m01 << 3);
#pragma unroll
        for (int kt = 0; kt < 4; ++kt) {
            uint32_t off = sw128((uint32_t)(rg * 128 + kt * 32 + kh * 16));
            ldsm_x4(sA + off, a[mt][kt][0], a[mt][kt][1], a[mt][kt][2], a[mt][kt][3]);
        }
    }
#pragma unroll 4
    for (int nt = 0; nt < 16; ++nt) {
        uint32_t off0 = sw128((uint32_t)((nt * 8 + bjrow) * 128 + bkt * 32 + bkh * 16));
        uint32_t off1 = sw128((uint32_t)((nt * 8 + bjrow) * 128 + (bkt + 2) * 32 + bkh * 16));
        uint32_t b[4][2];
        ldsm_x4(sB + off0, b[0][0], b[0][1], b[1][0], b[1][1]);
        ldsm_x4(sB + off1, b[2][0], b[2][1], b[3][0], b[3][1]);
        int j0 = nt * 8 + quad * 2;
        char* himg = (j0 < 64) ? h0 : h1;
        int   jc   = j0 & 63;
#pragma unroll
        for (int mt = 0; mt < 2; ++mt) {
            float d0 = 0.f, d1 = 0.f, d2 = 0.f, d3 = 0.f;
#pragma unroll
            for (int kt = 0; kt < 4; ++kt)
                mma16816(d0, d1, d2, d3,
                         a[mt][kt][0], a[mt][kt][1], a[mt][kt][2], a[mt][kt][3],
                         b[kt][0], b[kt][1]);
            int rA = wid * 32 + mt * 16 + qrow, rB = rA + 8;
            __half2 hA = __floats2half2_rn(fmaxf(d0, 0.f), fmaxf(d1, 0.f));
            __half2 hB = __floats2half2_rn(fmaxf(d2, 0.f), fmaxf(d3, 0.f));
            *(__half2*)(himg + sw128((uint32_t)(rA * 128 + jc * 2))) = hA;
            *(__half2*)(himg + sw128((uint32_t)(rB * 128 + jc * 2))) = hB;
        }
    }
}

// ---- layer: 128-K HMMA (H in two 64-col halves), bias, fp16 -> aimg --------
__device__ __forceinline__ void layer_narrow(
    uint32_t sH0, uint32_t sH1, uint32_t sB, const float* __restrict__ bias,
    char* outimg, int coff, int mlim, int ntn, int wid, int lane)
{
    const int m01 = (lane >> 3) & 1, kh = lane >> 4;
    const int quad = lane & 3, qrow = lane >> 2;
    const int bjrow = lane & 7, bkt = lane >> 4, bkh = (lane >> 3) & 1;

    for (int mt = 0; mt < 2; ++mt) {
        int rg = wid * 32 + mt * 16 + (lane & 7) + (m01 << 3);
        uint32_t a[8][4];
#pragma unroll
        for (int kt = 0; kt < 8; ++kt) {
            uint32_t src = (kt < 4) ? sH0 : sH1;
            int      ktl = kt & 3;
            uint32_t off = sw128((uint32_t)(rg * 128 + ktl * 32 + kh * 16));
            ldsm_x4(src + off, a[kt][0], a[kt][1], a[kt][2], a[kt][3]);
        }
        for (int nt = 0; nt < ntn; ++nt) {
            uint32_t b[8][2];
#pragma unroll
            for (int q = 0; q < 4; ++q) {
                uint32_t off = sw128((uint32_t)((nt * 8 + bjrow) * 256 + q * 64 + bkt * 32 + bkh * 16));
                ldsm_x4(sB + off, b[2 * q][0], b[2 * q][1], b[2 * q + 1][0], b[2 * q + 1][1]);
            }
            float d0 = 0.f, d1 = 0.f, d2 = 0.f, d3 = 0.f;
#pragma unroll
            for (int kt = 0; kt < 8; ++kt)
                mma16816(d0, d1, d2, d3, a[kt][0], a[kt][1], a[kt][2], a[kt][3],
                         b[kt][0], b[kt][1]);
            int m0 = nt * 8 + quad * 2, m1 = m0 + 1;
            int rA = wid * 32 + mt * 16 + qrow, rB = rA + 8;
            if (m0 < mlim) {
                *(__half*)(outimg + sw128((uint32_t)(rA * 128 + (m0 + coff) * 2))) =
                    __float2half(d0 + bias[m0]);
                *(__half*)(outimg + sw128((uint32_t)(rB * 128 + (m0 + coff) * 2))) =
                    __float2half(d2 + bias[m0]);
            }
            if (m1 < mlim) {
                *(__half*)(outimg + sw128((uint32_t)(rA * 128 + (m1 + coff) * 2))) =
                    __float2half(d1 + bias[m1]);
                *(__half*)(outimg + sw128((uint32_t)(rB * 128 + (m1 + coff) * 2))) =
                    __float2half(d3 + bias[m1]);
            }
        }
    }
}

// ============================================================================
// Fused kernel: 128 threads / 4 warps, 128 rows, 3 CTAs/SM.
// ============================================================================
__global__ void __launch_bounds__(128, 3) k_fused(
    const float* __restrict__ x,
    const float* __restrict__ Cw1, const float* __restrict__ Cb1v,
    const float* __restrict__ Cw2, const float* __restrict__ Cb2v,
    const float* __restrict__ Nb2v, const float* __restrict__ Fb2v,
    const float* __restrict__ Ow2, const float* __restrict__ Ob2,
    float* __restrict__ out)
{
    extern __shared__ char smem[];
    const uint32_t sbase = smem_u32(smem);
    float* xc   = (float*)(smem + SM_XC);
    float* cw1t = (float*)(smem + SM_CW1);
    float* cw2  = (float*)(smem + SM_CW2);
    float* cb1  = (float*)(smem + SM_CB1);
    float* cb2  = (float*)(smem + SM_CB2);
    float* bn2  = (float*)(smem + SM_BN2);
    float* bf2  = (float*)(smem + SM_BF2);
    float* w2s  = (float*)(smem + SM_W2S);   // [pair][branch][j] float4 {w2x,w2y,w2z,0}

    const int tid  = threadIdx.x;
    const int wid  = tid >> 5;
    const int lane = tid & 31;
    const int row0 = blockIdx.x * 128;

    // ---------------- phase 0: x image + Nw1 + small consts -----------------
    for (int i = tid; i < 128 * 58; i += 128) {
        int r = i / 58, c = i - r * 58;
        float v = x[(size_t)(row0 + r) * 58 + c];
        if (c < 4) xc[r * 4 + c] = v;
        else *(__half*)(smem + SM_X + sw128((uint32_t)(r * 128 + (c - 4) * 2))) =
                 __float2half(v);
    }
    for (int i = tid; i < 128 * 10; i += 128) {          // pad cols 54..63
        int r = i / 10, kk = 54 + (i - (i / 10) * 10);
        float v = (kk == 54 || kk == 57) ? 1.f : 0.f;    // bias-ride columns
        *(__half*)(smem + SM_X + sw128((uint32_t)(r * 128 + kk * 2))) = __float2half(v);
    }
    {
        const uint4* s = (const uint4*)g_bn1; uint4* d = (uint4*)(smem + SM_W);
#pragma unroll
        for (int i = 0; i < 8; ++i) d[tid + 128 * i] = s[tid + 128 * i];
    }
    cb1[tid] = Cb1v[tid];
    if (tid < 64) {
        bn2[tid] = (tid < 54) ? Nb2v[tid] : 0.f;
        bf2[tid] = (tid < 57) ? Fb2v[tid] : 0.f;
    }
    if (tid < 4) cb2[tid] = (tid < 3) ? Cb2v[tid] : 0.f;
    for (int i = tid; i < 512; i += 128) { int k = i >> 7, j = i & 127; cw1t[j * 4 + k] = Cw1[i]; }
    for (int i = tid; i < 384; i += 128) { int j = i / 3, m = i - j * 3; cw2[j * 4 + m] = Cw2[i]; }
    __syncthreads();

    // ---------------- stage C (one row per thread, fp32 scalar) -------------
    float c0, c1, c2;
    {
        float cx0 = xc[tid * 4 + 0], cx1 = xc[tid * 4 + 1];
        float cx2 = xc[tid * 4 + 2], cx3 = xc[tid * 4 + 3];
        c0 = cb2[0]; c1 = cb2[1]; c2 = cb2[2];
        for (int j = 0; j < 128; ++j) {
            const float* w = &cw1t[j * 4];
            float h = cb1[j] + cx0 * w[0] + cx1 * w[1] + cx2 * w[2] + cx3 * w[3];
            h = fmaxf(h, 0.f);
            const float* w2 = &cw2[j * 4];
            c0 += h * w2[0]; c1 += h * w2[1]; c2 += h * w2[2];
        }
    }

    // ---------------- N1 -> H0/H1 (bias baked) ------------------------------
    layer_wide(sbase + SM_X, sbase + SM_W, smem + SM_H0, smem + SM_H1, wid, lane);
    __syncthreads();
    {   // load Nw2 -> W
        const uint4* s = (const uint4*)g_bn2; uint4* d = (uint4*)(smem + SM_W);
#pragma unroll
        for (int i = 0; i < 8; ++i) d[tid + 128 * i] = s[tid + 128 * i];
    }
    __syncthreads();

    // ---------------- N2 -> X cols 3..56; c -> cols 0..2 --------------------
    layer_narrow(sbase + SM_H0, sbase + SM_H1, sbase + SM_W, bn2,
                 smem + SM_X, 3, 54, 7, wid, lane);
    {
        *(__half*)(smem + SM_X + sw128((uint32_t)(tid * 128 + 0))) = __float2half(c0);
        *(__half*)(smem + SM_X + sw128((uint32_t)(tid * 128 + 2))) = __float2half(c1);
        *(__half*)(smem + SM_X + sw128((uint32_t)(tid * 128 + 4))) = __float2half(c2);
    }
    __syncthreads();
    {   // load Fw1 -> W
        const uint4* s = (const uint4*)g_bf1; uint4* d = (uint4*)(smem + SM_W);
#pragma unroll
        for (int i = 0; i < 8; ++i) d[tid + 128 * i] = s[tid + 128 * i];
    }
    __syncthreads();

    // ---------------- F1 -> H0/H1 (bias baked) ------------------------------
    layer_wide(sbase + SM_X, sbase + SM_W, smem + SM_H0, smem + SM_H1, wid, lane);
    __syncthreads();
    {   // load Fw2 -> W ; also stage O w2 pair0
        const uint4* s = (const uint4*)g_bf2; uint4* d = (uint4*)(smem + SM_W);
#pragma unroll
        for (int i = 0; i < 8; ++i) d[tid + 128 * i] = s[tid + 128 * i];
        float4 p0, p1;
        p0.x = Ow2[tid * 3 + 0]; p0.y = Ow2[tid * 3 + 1]; p0.z = Ow2[tid * 3 + 2]; p0.w = 0.f;
        p1.x = Ow2[384 + tid * 3 + 0]; p1.y = Ow2[384 + tid * 3 + 1];
        p1.z = Ow2[384 + tid * 3 + 2]; p1.w = 0.f;
        ((float4*)w2s)[tid] = p0;
        ((float4*)w2s)[128 + tid] = p1;
    }
    __syncthreads();

    // ---------------- F2 -> X cols 0..56 (col57 stays 1 for O bias) ---------
    layer_narrow(sbase + SM_H0, sbase + SM_H1, sbase + SM_W, bf2,
                 smem + SM_X, 0, 57, 8, wid, lane);
    __syncthreads();

    // ---------------- O branches 0,1 -> H0,H1 ; A-frags from X --------------
    {
        const uint4* s0 = (const uint4*)g_w1h;
        const uint4* s1 = (const uint4*)(g_w1h + 8192);
        uint4* d0 = (uint4*)(smem + SM_H0);
        uint4* d1 = (uint4*)(smem + SM_H1);
#pragma unroll
        for (int i = 0; i < 8; ++i) {
            d0[tid + 128 * i] = s0[tid + 128 * i];
            d1[tid + 128 * i] = s1[tid + 128 * i];
        }
    }
    uint32_t a[2][4][4];
    {
        int m01 = (lane >> 3) & 1, kh = lane >> 4;
#pragma unroll
        for (int mt = 0; mt < 2; ++mt) {
            int rg = wid * 32 + mt * 16 + (lane & 7) + (m01 << 3);
#pragma unroll
            for (int kt = 0; kt < 4; ++kt) {
                uint32_t off = sw128((uint32_t)(rg * 128 + kt * 32 + kh * 16));
                ldsm_x4(sbase + SM_X + off,
                        a[mt][kt][0], a[mt][kt][1], a[mt][kt][2], a[mt][kt][3]);
            }
        }
    }
    __syncthreads();

    // ---------------- O loop: dual-branch, dual m-tile ----------------------
    const int quad = lane & 3;
    const int qrow = lane >> 2;
    const int bjrow = lane & 7;
    const int bkt   = lane >> 4;
    const int bkh   = (lane >> 3) & 1;

    for (int p = 0; p < 27; ++p) {
        const int buf = p & 1, nxt = buf ^ 1;
        const int nP = 2 * p, nQ = nP + 1;

        if (p < 26) {
            const uint4* s0 = (const uint4*)(g_w1h + (nP + 2) * 8192);
            const uint4* s1 = (const uint4*)(g_w1h + (nP + 3) * 8192);
            uint4* d0 = (uint4*)(smem + (nxt ? SM_X : SM_H0));
            uint4* d1 = (uint4*)(smem + (nxt ? SM_W : SM_H1));
#pragma unroll
            for (int i = 0; i < 8; ++i) {
                d0[tid + 128 * i] = s0[tid + 128 * i];
                d1[tid + 128 * i] = s1[tid + 128 * i];
            }
            float4 q0, q1;
            q0.x = Ow2[(nP + 2) * 384 + tid * 3 + 0];
            q0.y = Ow2[(nP + 2) * 384 + tid * 3 + 1];
            q0.z = Ow2[(nP + 2) * 384 + tid * 3 + 2];
            q0.w = 0.f;
            q1.x = Ow2[(nP + 3) * 384 + tid * 3 + 0];
            q1.y = Ow2[(nP + 3) * 384 + tid * 3 + 1];
            q1.z = Ow2[(nP + 3) * 384 + tid * 3 + 2];
            q1.w = 0.f;
            ((float4*)w2s)[nxt * 256 + tid] = q0;
            ((float4*)w2s)[nxt * 256 + 128 + tid] = q1;
        }

        const uint32_t sb0 = sbase + (buf ? SM_X : SM_H0);
        const uint32_t sb1 = sbase + (buf ? SM_W : SM_H1);
        const float4* w2P = (const float4*)w2s + buf * 256;
        const float4* w2Q = w2P + 128;

        float lP[2][6], lQ[2][6];
#pragma unroll
        for (int mt = 0; mt < 2; ++mt)
#pragma unroll
            for (int q = 0; q < 6; ++q) { lP[mt][q] = 0.f; lQ[mt][q] = 0.f; }

#pragma unroll 4
        for (int nt = 0; nt < 16; ++nt) {
            uint32_t off0 = sw128((uint32_t)((nt * 8 + bjrow) * 128 + bkt * 32 + bkh * 16));
            uint32_t off1 = sw128((uint32_t)((nt * 8 + bjrow) * 128 + (bkt + 2) * 32 + bkh * 16));
            uint32_t bP[4][2], bQ[4][2];
            ldsm_x4(sb0 + off0, bP[0][0], bP[0][1], bP[1][0], bP[1][1]);
            ldsm_x4(sb0 + off1, bP[2][0], bP[2][1], bP[3][0], bP[3][1]);
            ldsm_x4(sb1 + off0, bQ[0][0], bQ[0][1], bQ[1][0], bQ[1][1]);
            ldsm_x4(sb1 + off1, bQ[2][0], bQ[2][1], bQ[3][0], bQ[3][1]);

            const int j0 = nt * 8 + quad * 2;
            float4 waP = w2P[j0], wbP = w2P[j0 + 1];
            float4 waQ = w2Q[j0], wbQ = w2Q[j0 + 1];

#pragma unroll
            for (int mt = 0; mt < 2; ++mt) {
                float dP0 = 0.f, dP1 = 0.f, dP2 = 0.f, dP3 = 0.f;
                float dQ0 = 0.f, dQ1 = 0.f, dQ2 = 0.f, dQ3 = 0.f;
#pragma unroll
                for (int kt = 0; kt < 4; ++kt) {
                    mma16816(dP0, dP1, dP2, dP3,
                             a[mt][kt][0], a[mt][kt][1], a[mt][kt][2], a[mt][kt][3],
                             bP[kt][0], bP[kt][1]);
                    mma16816(dQ0, dQ1, dQ2, dQ3,
                             a[mt][kt][0], a[mt][kt][1], a[mt][kt][2], a[mt][kt][3],
                             bQ[kt][0], bQ[kt][1]);
                }
                float h;
                h = fmaxf(dP0, 0.f);
                lP[mt][0] = fmaf(h, waP.x, lP[mt][0]);
                lP[mt][1] = fmaf(h, waP.y, lP[mt][1]);
                lP[mt][2] = fmaf(h, waP.z, lP[mt][2]);
                h = fmaxf(dP1, 0.f);
                lP[mt][0] = fmaf(h, wbP.x, lP[mt][0]);
                lP[mt][1] = fmaf(h, wbP.y, lP[mt][1]);
                lP[mt][2] = fmaf(h, wbP.z, lP[mt][2]);
                h = fmaxf(dP2, 0.f);
                lP[mt][3] = fmaf(h, waP.x, lP[mt][3]);
                lP[mt][4] = fmaf(h, waP.y, lP[mt][4]);
                lP[mt][5] = fmaf(h, waP.z, lP[mt][5]);
                h = fmaxf(dP3, 0.f);
                lP[mt][3] = fmaf(h, wbP.x, lP[mt][3]);
                lP[mt][4] = fmaf(h, wbP.y, lP[mt][4]);
                lP[mt][5] = fmaf(h, wbP.z, lP[mt][5]);
                h = fmaxf(dQ0, 0.f);
                lQ[mt][0] = fmaf(h, waQ.x, lQ[mt][0]);
                lQ[mt][1] = fmaf(h, waQ.y, lQ[mt][1]);
                lQ[mt][2] = fmaf(h, waQ.z, lQ[mt][2]);
                h = fmaxf(dQ1, 0.f);
                lQ[mt][0] = fmaf(h, wbQ.x, lQ[mt][0]);
                lQ[mt][1] = fmaf(h, wbQ.y, lQ[mt][1]);
                lQ[mt][2] = fmaf(h, wbQ.z, lQ[mt][2]);
                h = fmaxf(dQ2, 0.f);
                lQ[mt][3] = fmaf(h, waQ.x, lQ[mt][3]);
                lQ[mt][4] = fmaf(h, waQ.y, lQ[mt][4]);
                lQ[mt][5] = fmaf(h, waQ.z, lQ[mt][5]);
                h = fmaxf(dQ3, 0.f);
                lQ[mt][3] = fmaf(h, wbQ.x, lQ[mt][3]);
                lQ[mt][4] = fmaf(h, wbQ.y, lQ[mt][4]);
                lQ[mt][5] = fmaf(h, wbQ.z, lQ[mt][5]);
            }
        }

#pragma unroll
        for (int m = 1; m <= 2; m <<= 1) {
#pragma unroll
            for (int mt = 0; mt < 2; ++mt)
#pragma unroll
                for (int q = 0; q < 6; ++q) {
                    lP[mt][q] += __shfl_xor_sync(0xffffffffu, lP[mt][q], m);
                    lQ[mt][q] += __shfl_xor_sync(0xffffffffu, lQ[mt][q], m);
                }
        }

        if (quad == 0) {
            float cP0 = Ob2[nP * 3 + 0], cP1 = Ob2[nP * 3 + 1], cP2 = Ob2[nP * 3 + 2];
            float cQ0 = Ob2[nQ * 3 + 0], cQ1 = Ob2[nQ * 3 + 1], cQ2 = Ob2[nQ * 3 + 2];
#pragma unroll
            for (int mt = 0; mt < 2; ++mt) {
                int rA = wid * 32 + mt * 16 + qrow, rB = rA + 8;
                {
                    float l0 = lP[mt][0] + cP0, l1 = lP[mt][1] + cP1, l2 = lP[mt][2] + cP2;
                    float mx = fmaxf(l0, fmaxf(l1, l2));
                    float e0 = __expf(l0 - mx), e1 = __expf(l1 - mx), e2 = __expf(l2 - mx);
                    float inv = 1.f / (e0 + e1 + e2);
                    float* o = out + (size_t)(row0 + rA) * 162 + nP * 3;
                    o[0] = e0 * inv; o[1] = e1 * inv; o[2] = e2 * inv;
                }
                {
                    float l0 = lP[mt][3] + cP0, l1 = lP[mt][4] + cP1, l2 = lP[mt][5] + cP2;
                    float mx = fmaxf(l0, fmaxf(l1, l2));
                    float e0 = __expf(l0 - mx), e1 = __expf(l1 - mx), e2 = __expf(l2 - mx);
                    float inv = 1.f / (e0 + e1 + e2);
                    float* o = out + (size_t)(row0 + rB) * 162 + nP * 3;
                    o[0] = e0 * inv; o[1] = e1 * inv; o[2] = e2 * inv;
                }
                {
                    float l0 = lQ[mt][0] + cQ0, l1 = lQ[mt][1] + cQ1, l2 = lQ[mt][2] + cQ2;
                    float mx = fmaxf(l0, fmaxf(l1, l2));
                    float e0 = __expf(l0 - mx), e1 = __expf(l1 - mx), e2 = __expf(l2 - mx);
                    float inv = 1.f / (e0 + e1 + e2);
                    float* o = out + (size_t)(row0 + rA) * 162 + nQ * 3;
                    o[0] = e0 * inv; o[1] = e1 * inv; o[2] = e2 * inv;
                }
                {
                    float l0 = lQ[mt][3] + cQ0, l1 = lQ[mt][4] + cQ1, l2 = lQ[mt][5] + cQ2;
                    float mx = fmaxf(l0, fmaxf(l1, l2));
                    float e0 = __expf(l0 - mx), e1 = __expf(l1 - mx), e2 = __expf(l2 - mx);
                    float inv = 1.f / (e0 + e1 + e2);
                    float* o = out + (size_t)(row0 + rB) * 162 + nQ * 3;
                    o[0] = e0 * inv; o[1] = e1 * inv; o[2] = e2 * inv;
                }
            }
        }
        __syncthreads();
    }
}

// ============================================================================
extern "C" void kernel_launch(void* const* d_in, const int* in_sizes, int n_in,
                              void* d_out, int out_size)
{
    const float* x   = (const float*)d_in[0];
    const float* Cw1 = (const float*)d_in[1];
    const float* Cb1 = (const float*)d_in[2];
    const float* Cw2 = (const float*)d_in[3];
    const float* Cb2 = (const float*)d_in[4];
    const float* Nw1 = (const float*)d_in[5];
    const float* Nb1 = (const float*)d_in[6];
    const float* Nw2 = (const float*)d_in[7];
    const float* Nb2 = (const float*)d_in[8];
    const float* Fw1 = (const float*)d_in[9];
    const float* Fb1 = (const float*)d_in[10];
    const float* Fw2 = (const float*)d_in[11];
    const float* Fb2 = (const float*)d_in[12];
    const float* Ow1 = (const float*)d_in[13];
    const float* Ob1 = (const float*)d_in[14];
    const float* Ow2 = (const float*)d_in[15];
    const float* Ob2 = (const float*)d_in[16];
    float* out = (float*)d_out;

    cudaFuncSetAttribute(k_fused, cudaFuncAttributeMaxDynamicSharedMemorySize, SM_TOT);

    const int conv_elems = NB * 8192 + 4 * 8192;
    k_convert<<<(conv_elems + 255) / 256, 256>>>(Ow1, Ob1, Nw1, Nb1, Nw2, Fw1, Fb1, Fw2);

    k_fused<<<NTILES, 128, SM_TOT>>>(
        x, Cw1, Cb1, Cw2, Cb2, Nb2, Fb2, Ow2, Ob2, out);
}

// round 9
// speedup vs baseline: 7.7887x; 1.0368x over previous
#include <cuda_runtime.h>
#include <cuda_fp16.h>
#include <cstdint>

#define NTILES 512
#define NB     54

// ========================= device scratch (fp16 images) =====================
__device__ __align__(16) __half g_w1h[NB * 8192];  // O_w1: [j=128][k=64], k57=Ob1
__device__ __align__(16) __half g_w2i[NB * 1024];  // O_w2: [n=8][k=128] (n<3 live)
__device__ __align__(16) __half g_bn1[8192];       // N_w1: [j=128][k=64], k54=Nb1
__device__ __align__(16) __half g_bn2[8192];       // N_w2: [m=64][k=128]
__device__ __align__(16) __half g_bf1[8192];       // F_w1: [j=128][k=64], k57=Fb1
__device__ __align__(16) __half g_bf2[8192];       // F_w2: [m=64][k=128]

// ============================= PTX helpers =================================
__device__ __forceinline__ uint32_t smem_u32(const void* p) {
    uint32_t a;
    asm("{ .reg .u64 t; cvta.to.shared.u64 t, %1; cvt.u32.u64 %0, t; }"
        : "=r"(a) : "l"(p));
    return a;
}
__device__ __forceinline__ void ldsm_x4(uint32_t addr, uint32_t& r0, uint32_t& r1,
                                        uint32_t& r2, uint32_t& r3) {
    asm volatile("ldmatrix.sync.aligned.m8n8.x4.shared.b16 {%0,%1,%2,%3}, [%4];"
                 : "=r"(r0), "=r"(r1), "=r"(r2), "=r"(r3) : "r"(addr));
}
__device__ __forceinline__ void mma16816(float& d0, float& d1, float& d2, float& d3,
                                         uint32_t a0, uint32_t a1, uint32_t a2, uint32_t a3,
                                         uint32_t b0, uint32_t b1) {
    asm volatile("mma.sync.aligned.m16n8k16.row.col.f32.f16.f16.f32 "
                 "{%0,%1,%2,%3}, {%4,%5,%6,%7}, {%8,%9}, {%0,%1,%2,%3};"
                 : "+f"(d0), "+f"(d1), "+f"(d2), "+f"(d3)
                 : "r"(a0), "r"(a1), "r"(a2), "r"(a3), "r"(b0), "r"(b1));
}
__device__ __forceinline__ uint32_t sw128(uint32_t off) {
    return off ^ ((off >> 3) & 0x70);
}
__device__ __forceinline__ uint32_t packh2(float lo, float hi) {
    __half2 h = __floats2half2_rn(lo, hi);
    return *reinterpret_cast<uint32_t*>(&h);
}

// ============================================================================
// Convert weights -> swizzled fp16 images (biases baked at constant-1 k-col).
// ============================================================================
__global__ __launch_bounds__(256) void k_convert(
    const float* __restrict__ Ow1, const float* __restrict__ Ob1,
    const float* __restrict__ Ow2,
    const float* __restrict__ Nw1, const float* __restrict__ Nb1,
    const float* __restrict__ Nw2,
    const float* __restrict__ Fw1, const float* __restrict__ Fb1,
    const float* __restrict__ Fw2)
{
    int idx = blockIdx.x * 256 + threadIdx.x;
    if (idx < NB * 8192) {
        int j = idx & 127, k = (idx >> 7) & 63, n = idx >> 13;
        float v = (k < 57) ? Ow1[n * 7296 + k * 128 + j]
                 : (k == 57 ? Ob1[n * 128 + j] : 0.f);
        g_w1h[n * 8192 + (sw128((unsigned)(j * 128 + k * 2)) >> 1)] = __float2half(v);
        return;
    }
    int t = idx - NB * 8192;
    if (t < 4 * 8192) {
        int img = t >> 13, e = t & 8191;
        if (img == 0) {
            int j = e >> 6, k = e & 63;
            float v = (k < 54) ? Nw1[k * 128 + j] : (k == 54 ? Nb1[j] : 0.f);
            g_bn1[sw128((unsigned)(j * 128 + k * 2)) >> 1] = __float2half(v);
        } else if (img == 1) {
            int j = e >> 6, k = e & 63;
            float v = (k < 57) ? Fw1[k * 128 + j] : (k == 57 ? Fb1[j] : 0.f);
            g_bf1[sw128((unsigned)(j * 128 + k * 2)) >> 1] = __float2half(v);
        } else if (img == 2) {
            int m = e >> 7, k = e & 127;
            float v = (m < 54) ? Nw2[k * 54 + m] : 0.f;
            g_bn2[sw128((unsigned)(m * 256 + k * 2)) >> 1] = __float2half(v);
        } else {
            int m = e >> 7, k = e & 127;
            float v = (m < 57) ? Fw2[k * 57 + m] : 0.f;
            g_bf2[sw128((unsigned)(m * 256 + k * 2)) >> 1] = __float2half(v);
        }
        return;
    }
    t -= 4 * 8192;
    if (t >= NB * 1024) return;
    {   // O_w2 image: [n=8][k=128], row m col k = Ow2[n][k][m] for m<3
        int n = t >> 10, e = t & 1023;
        int m = e >> 7, k = e & 127;
        float v = (m < 3) ? Ow2[n * 384 + k * 3 + m] : 0.f;
        g_w2i[n * 1024 + (sw128((unsigned)(m * 256 + k * 2)) >> 1)] = __float2half(v);
    }
}

// ============================ SMEM layout (74.2 KB -> 3 CTAs/SM) ============
#define SM_X    0          // 16 KB
#define SM_W    16384      // 16 KB
#define SM_H0   32768      // 16 KB
#define SM_H1   49152      // 16 KB
#define SM_W2S  65536      // 8 KB: O-phase W2 images [pair][br] 2 KB each; C overlay
#define SM_XC   65536
#define SM_CW1  67584
#define SM_CW2  69632
#define SM_CB1  71680
#define SM_CB2  72192
#define SM_BN2  73728
#define SM_BF2  73984
#define SM_TOT  74240

// ---- layer: 64-K HMMA, 128 out cols, relu (bias baked), fp16 -> H0/H1 ------
__device__ __forceinline__ void layer_wide(
    uint32_t sA, uint32_t sB, char* h0, char* h1, int wid, int lane)
{
    const int m01 = (lane >> 3) & 1, kh = lane >> 4;
    const int quad = lane & 3, qrow = lane >> 2;
    const int bjrow = lane & 7, bkt = lane >> 4, bkh = (lane >> 3) & 1;

    uint32_t a[2][4][4];
#pragma unroll
    for (int mt = 0; mt < 2; ++mt) {
        int rg = wid * 32 + mt * 16 + (lane & 7) + (m01 << 3);
#pragma unroll
        for (int kt = 0; kt < 4; ++kt) {
            uint32_t off = sw128((uint32_t)(rg * 128 + kt * 32 + kh * 16));
            ldsm_x4(sA + off, a[mt][kt][0], a[mt][kt][1], a[mt][kt][2], a[mt][kt][3]);
        }
    }
#pragma unroll 4
    for (int nt = 0; nt < 16; ++nt) {
        uint32_t off0 = sw128((uint32_t)((nt * 8 + bjrow) * 128 + bkt * 32 + bkh * 16));
        uint32_t off1 = sw128((uint32_t)((nt * 8 + bjrow) * 128 + (bkt + 2) * 32 + bkh * 16));
        uint32_t b[4][2];
        ldsm_x4(sB + off0, b[0][0], b[0][1], b[1][0], b[1][1]);
        ldsm_x4(sB + off1, b[2][0], b[2][1], b[3][0], b[3][1]);
        int j0 = nt * 8 + quad * 2;
        char* himg = (j0 < 64) ? h0 : h1;
        int   jc   = j0 & 63;
#pragma unroll
        for (int mt = 0; mt < 2; ++mt) {
            float d0 = 0.f, d1 = 0.f, d2 = 0.f, d3 = 0.f;
#pragma unroll
            for (int kt = 0; kt < 4; ++kt)
                mma16816(d0, d1, d2, d3,
                         a[mt][kt][0], a[mt][kt][1], a[mt][kt][2], a[mt][kt][3],
                         b[kt][0], b[kt][1]);
            int rA = wid * 32 + mt * 16 + qrow, rB = rA + 8;
            __half2 hA = __floats2half2_rn(fmaxf(d0, 0.f), fmaxf(d1, 0.f));
            __half2 hB = __floats2half2_rn(fmaxf(d2, 0.f), fmaxf(d3, 0.f));
            *(__half2*)(himg + sw128((uint32_t)(rA * 128 + jc * 2))) = hA;
            *(__half2*)(himg + sw128((uint32_t)(rB * 128 + jc * 2))) = hB;
        }
    }
}

// ---- layer: 128-K HMMA (H in two 64-col halves), bias, fp16 -> aimg --------
__device__ __forceinline__ void layer_narrow(
    uint32_t sH0, uint32_t sH1, uint32_t sB, const float* __restrict__ bias,
    char* outimg, int coff, int mlim, int ntn, int wid, int lane)
{
    const int m01 = (lane >> 3) & 1, kh = lane >> 4;
    const int quad = lane & 3, qrow = lane >> 2;
    const int bjrow = lane & 7, bkt = lane >> 4, bkh = (lane >> 3) & 1;

    for (int mt = 0; mt < 2; ++mt) {
        int rg = wid * 32 + mt * 16 + (lane & 7) + (m01 << 3);
        uint32_t a[8][4];
#pragma unroll
        for (int kt = 0; kt < 8; ++kt) {
            uint32_t src = (kt < 4) ? sH0 : sH1;
            int      ktl = kt & 3;
            uint32_t off = sw128((uint32_t)(rg * 128 + ktl * 32 + kh * 16));
            ldsm_x4(src + off, a[kt][0], a[kt][1], a[kt][2], a[kt][3]);
        }
        for (int nt = 0; nt < ntn; ++nt) {
            uint32_t b[8][2];
#pragma unroll
            for (int q = 0; q < 4; ++q) {
                uint32_t off = sw128((uint32_t)((nt * 8 + bjrow) * 256 + q * 64 + bkt * 32 + bkh * 16));
                ldsm_x4(sB + off, b[2 * q][0], b[2 * q][1], b[2 * q + 1][0], b[2 * q + 1][1]);
            }
            float d0 = 0.f, d1 = 0.f, d2 = 0.f, d3 = 0.f;
#pragma unroll
            for (int kt = 0; kt < 8; ++kt)
                mma16816(d0, d1, d2, d3, a[kt][0], a[kt][1], a[kt][2], a[kt][3],
                         b[kt][0], b[kt][1]);
            int m0 = nt * 8 + quad * 2, m1 = m0 + 1;
            int rA = wid * 32 + mt * 16 + qrow, rB = rA + 8;
            if (m0 < mlim) {
                *(__half*)(outimg + sw128((uint32_t)(rA * 128 + (m0 + coff) * 2))) =
                    __float2half(d0 + bias[m0]);
                *(__half*)(outimg + sw128((uint32_t)(rB * 128 + (m0 + coff) * 2))) =
                    __float2half(d2 + bias[m0]);
            }
            if (m1 < mlim) {
                *(__half*)(outimg + sw128((uint32_t)(rA * 128 + (m1 + coff) * 2))) =
                    __float2half(d1 + bias[m1]);
                *(__half*)(outimg + sw128((uint32_t)(rB * 128 + (m1 + coff) * 2))) =
                    __float2half(d3 + bias[m1]);
            }
        }
    }
}

__device__ __forceinline__ void softmax_store(float* __restrict__ out,
                                              size_t row, int n,
                                              float l0, float l1, float l2)
{
    float mx = fmaxf(l0, fmaxf(l1, l2));
    float e0 = __expf(l0 - mx), e1 = __expf(l1 - mx), e2 = __expf(l2 - mx);
    float inv = 1.f / (e0 + e1 + e2);
    float* o = out + row * 162 + n * 3;
    o[0] = e0 * inv; o[1] = e1 * inv; o[2] = e2 * inv;
}

// ============================================================================
// Fused kernel: 128 threads / 4 warps, 128 rows, 3 CTAs/SM.
// O stage: both MLP layers on tensor cores; accumulator-chained fragments.
// ============================================================================
__global__ void __launch_bounds__(128, 3) k_fused(
    const float* __restrict__ x,
    const float* __restrict__ Cw1, const float* __restrict__ Cb1v,
    const float* __restrict__ Cw2, const float* __restrict__ Cb2v,
    const float* __restrict__ Nb2v, const float* __restrict__ Fb2v,
    const float* __restrict__ Ob2, float* __restrict__ out)
{
    extern __shared__ char smem[];
    const uint32_t sbase = smem_u32(smem);
    float* xc   = (float*)(smem + SM_XC);
    float* cw1t = (float*)(smem + SM_CW1);
    float* cw2  = (float*)(smem + SM_CW2);
    float* cb1  = (float*)(smem + SM_CB1);
    float* cb2  = (float*)(smem + SM_CB2);
    float* bn2  = (float*)(smem + SM_BN2);
    float* bf2  = (float*)(smem + SM_BF2);

    const int tid  = threadIdx.x;
    const int wid  = tid >> 5;
    const int lane = tid & 31;
    const int row0 = blockIdx.x * 128;

    // ---------------- phase 0: x image + Nw1 + small consts -----------------
    for (int i = tid; i < 128 * 58; i += 128) {
        int r = i / 58, c = i - r * 58;
        float v = x[(size_t)(row0 + r) * 58 + c];
        if (c < 4) xc[r * 4 + c] = v;
        else *(__half*)(smem + SM_X + sw128((uint32_t)(r * 128 + (c - 4) * 2))) =
                 __float2half(v);
    }
    for (int i = tid; i < 128 * 10; i += 128) {
        int r = i / 10, kk = 54 + (i - (i / 10) * 10);
        float v = (kk == 54 || kk == 57) ? 1.f : 0.f;
        *(__half*)(smem + SM_X + sw128((uint32_t)(r * 128 + kk * 2))) = __float2half(v);
    }
    {
        const uint4* s = (const uint4*)g_bn1; uint4* d = (uint4*)(smem + SM_W);
#pragma unroll
        for (int i = 0; i < 8; ++i) d[tid + 128 * i] = s[tid + 128 * i];
    }
    cb1[tid] = Cb1v[tid];
    if (tid < 64) {
        bn2[tid] = (tid < 54) ? Nb2v[tid] : 0.f;
        bf2[tid] = (tid < 57) ? Fb2v[tid] : 0.f;
    }
    if (tid < 4) cb2[tid] = (tid < 3) ? Cb2v[tid] : 0.f;
    for (int i = tid; i < 512; i += 128) { int k = i >> 7, j = i & 127; cw1t[j * 4 + k] = Cw1[i]; }
    for (int i = tid; i < 384; i += 128) { int j = i / 3, m = i - j * 3; cw2[j * 4 + m] = Cw2[i]; }
    __syncthreads();

    // ---------------- stage C (fp32 scalar) ---------------------------------
    float c0, c1, c2;
    {
        float cx0 = xc[tid * 4 + 0], cx1 = xc[tid * 4 + 1];
        float cx2 = xc[tid * 4 + 2], cx3 = xc[tid * 4 + 3];
        c0 = cb2[0]; c1 = cb2[1]; c2 = cb2[2];
        for (int j = 0; j < 128; ++j) {
            const float* w = &cw1t[j * 4];
            float h = cb1[j] + cx0 * w[0] + cx1 * w[1] + cx2 * w[2] + cx3 * w[3];
            h = fmaxf(h, 0.f);
            const float* w2 = &cw2[j * 4];
            c0 += h * w2[0]; c1 += h * w2[1]; c2 += h * w2[2];
        }
    }

    // ---------------- N1 -> H0/H1 -------------------------------------------
    layer_wide(sbase + SM_X, sbase + SM_W, smem + SM_H0, smem + SM_H1, wid, lane);
    __syncthreads();
    {
        const uint4* s = (const uint4*)g_bn2; uint4* d = (uint4*)(smem + SM_W);
#pragma unroll
        for (int i = 0; i < 8; ++i) d[tid + 128 * i] = s[tid + 128 * i];
    }
    __syncthreads();

    // ---------------- N2 -> X cols 3..56; c -> cols 0..2 --------------------
    layer_narrow(sbase + SM_H0, sbase + SM_H1, sbase + SM_W, bn2,
                 smem + SM_X, 3, 54, 7, wid, lane);
    {
        *(__half*)(smem + SM_X + sw128((uint32_t)(tid * 128 + 0))) = __float2half(c0);
        *(__half*)(smem + SM_X + sw128((uint32_t)(tid * 128 + 2))) = __float2half(c1);
        *(__half*)(smem + SM_X + sw128((uint32_t)(tid * 128 + 4))) = __float2half(c2);
    }
    __syncthreads();
    {
        const uint4* s = (const uint4*)g_bf1; uint4* d = (uint4*)(smem + SM_W);
#pragma unroll
        for (int i = 0; i < 8; ++i) d[tid + 128 * i] = s[tid + 128 * i];
    }
    __syncthreads();

    // ---------------- F1 -> H0/H1 -------------------------------------------
    layer_wide(sbase + SM_X, sbase + SM_W, smem + SM_H0, smem + SM_H1, wid, lane);
    __syncthreads();
    {   // load Fw2 -> W ; stage O W2 images pair0 (branches 0,1)
        const uint4* s = (const uint4*)g_bf2; uint4* d = (uint4*)(smem + SM_W);
#pragma unroll
        for (int i = 0; i < 8; ++i) d[tid + 128 * i] = s[tid + 128 * i];
        ((uint4*)(smem + SM_W2S))[tid]        = ((const uint4*)g_w2i)[tid];
        ((uint4*)(smem + SM_W2S + 2048))[tid] = ((const uint4*)(g_w2i + 1024))[tid];
    }
    __syncthreads();

    // ---------------- F2 -> X cols 0..56 -------------------------------------
    layer_narrow(sbase + SM_H0, sbase + SM_H1, sbase + SM_W, bf2,
                 smem + SM_X, 0, 57, 8, wid, lane);
    __syncthreads();

    // ---------------- O branches 0,1 -> H0,H1 ; A-frags from X ---------------
    {
        const uint4* s0 = (const uint4*)g_w1h;
        const uint4* s1 = (const uint4*)(g_w1h + 8192);
        uint4* d0 = (uint4*)(smem + SM_H0);
        uint4* d1 = (uint4*)(smem + SM_H1);
#pragma unroll
        for (int i = 0; i < 8; ++i) {
            d0[tid + 128 * i] = s0[tid + 128 * i];
            d1[tid + 128 * i] = s1[tid + 128 * i];
        }
    }
    uint32_t a[2][4][4];
    {
        int m01 = (lane >> 3) & 1, kh = lane >> 4;
#pragma unroll
        for (int mt = 0; mt < 2; ++mt) {
            int rg = wid * 32 + mt * 16 + (lane & 7) + (m01 << 3);
#pragma unroll
            for (int kt = 0; kt < 4; ++kt) {
                uint32_t off = sw128((uint32_t)(rg * 128 + kt * 32 + kh * 16));
                ldsm_x4(sbase + SM_X + off,
                        a[mt][kt][0], a[mt][kt][1], a[mt][kt][2], a[mt][kt][3]);
            }
        }
    }
    __syncthreads();

    // ---------------- O loop: both layers on tensor cores --------------------
    const int quad = lane & 3;
    const int qrow = lane >> 2;
    const int bjrow = lane & 7;
    const int bkt   = lane >> 4;
    const int bkh   = (lane >> 3) & 1;
    const uint32_t w2rowb = (uint32_t)((lane & 7) * 256 + (lane >> 3) * 16);

    for (int p = 0; p < 27; ++p) {
        const int buf = p & 1, nxt = buf ^ 1;
        const int nP = 2 * p, nQ = nP + 1;

        if (p < 26) {
            const uint4* s0 = (const uint4*)(g_w1h + (nP + 2) * 8192);
            const uint4* s1 = (const uint4*)(g_w1h + (nP + 3) * 8192);
            uint4* d0 = (uint4*)(smem + (nxt ? SM_X : SM_H0));
            uint4* d1 = (uint4*)(smem + (nxt ? SM_W : SM_H1));
#pragma unroll
            for (int i = 0; i < 8; ++i) {
                d0[tid + 128 * i] = s0[tid + 128 * i];
                d1[tid + 128 * i] = s1[tid + 128 * i];
            }
            ((uint4*)(smem + SM_W2S + nxt * 4096))[tid] =
                ((const uint4*)(g_w2i + (nP + 2) * 1024))[tid];
            ((uint4*)(smem + SM_W2S + nxt * 4096 + 2048))[tid] =
                ((const uint4*)(g_w2i + (nP + 3) * 1024))[tid];
        }

        const uint32_t sb0  = sbase + (buf ? SM_X : SM_H0);
        const uint32_t sb1  = sbase + (buf ? SM_W : SM_H1);
        const uint32_t sw2P = sbase + SM_W2S + (uint32_t)buf * 4096;
        const uint32_t sw2Q = sw2P + 2048;

        // W2 B-fragments: 8 k-tiles x 2 regs per branch
        uint32_t b2P[8][2], b2Q[8][2];
#pragma unroll
        for (int c = 0; c < 4; ++c) {
            uint32_t off = sw128(w2rowb + (uint32_t)c * 64);
            ldsm_x4(sw2P + off, b2P[2 * c][0], b2P[2 * c][1],
                                b2P[2 * c + 1][0], b2P[2 * c + 1][1]);
            ldsm_x4(sw2Q + off, b2Q[2 * c][0], b2Q[2 * c][1],
                                b2Q[2 * c + 1][0], b2Q[2 * c + 1][1]);
        }

        // logit accumulators, init with Ob2 at this thread's columns
        float lgP[2][4], lgQ[2][4];
        {
            int cc0 = 2 * quad, cc1 = cc0 + 1;
            float p0 = (cc0 < 3) ? Ob2[nP * 3 + cc0] : 0.f;
            float p1 = (cc1 < 3) ? Ob2[nP * 3 + cc1] : 0.f;
            float q0 = (cc0 < 3) ? Ob2[nQ * 3 + cc0] : 0.f;
            float q1 = (cc1 < 3) ? Ob2[nQ * 3 + cc1] : 0.f;
#pragma unroll
            for (int mt = 0; mt < 2; ++mt) {
                lgP[mt][0] = p0; lgP[mt][1] = p1; lgP[mt][2] = p0; lgP[mt][3] = p1;
                lgQ[mt][0] = q0; lgQ[mt][1] = q1; lgQ[mt][2] = q0; lgQ[mt][3] = q1;
            }
        }

#pragma unroll 4
        for (int kt = 0; kt < 8; ++kt) {
            uint32_t a2P[2][4], a2Q[2][4];
#pragma unroll
            for (int e = 0; e < 2; ++e) {
                const int nt = 2 * kt + e;
                uint32_t off0 = sw128((uint32_t)((nt * 8 + bjrow) * 128 + bkt * 32 + bkh * 16));
                uint32_t off1 = sw128((uint32_t)((nt * 8 + bjrow) * 128 + (bkt + 2) * 32 + bkh * 16));
                uint32_t bP[4][2], bQ[4][2];
                ldsm_x4(sb0 + off0, bP[0][0], bP[0][1], bP[1][0], bP[1][1]);
                ldsm_x4(sb0 + off1, bP[2][0], bP[2][1], bP[3][0], bP[3][1]);
                ldsm_x4(sb1 + off0, bQ[0][0], bQ[0][1], bQ[1][0], bQ[1][1]);
                ldsm_x4(sb1 + off1, bQ[2][0], bQ[2][1], bQ[3][0], bQ[3][1]);
#pragma unroll
                for (int mt = 0; mt < 2; ++mt) {
                    float dP0 = 0.f, dP1 = 0.f, dP2 = 0.f, dP3 = 0.f;
                    float dQ0 = 0.f, dQ1 = 0.f, dQ2 = 0.f, dQ3 = 0.f;
#pragma unroll
                    for (int k4 = 0; k4 < 4; ++k4) {
                        mma16816(dP0, dP1, dP2, dP3,
                                 a[mt][k4][0], a[mt][k4][1], a[mt][k4][2], a[mt][k4][3],
                                 bP[k4][0], bP[k4][1]);
                        mma16816(dQ0, dQ1, dQ2, dQ3,
                                 a[mt][k4][0], a[mt][k4][1], a[mt][k4][2], a[mt][k4][3],
                                 bQ[k4][0], bQ[k4][1]);
                    }
                    a2P[mt][2 * e]     = packh2(fmaxf(dP0, 0.f), fmaxf(dP1, 0.f));
                    a2P[mt][2 * e + 1] = packh2(fmaxf(dP2, 0.f), fmaxf(dP3, 0.f));
                    a2Q[mt][2 * e]     = packh2(fmaxf(dQ0, 0.f), fmaxf(dQ1, 0.f));
                    a2Q[mt][2 * e + 1] = packh2(fmaxf(dQ2, 0.f), fmaxf(dQ3, 0.f));
                }
            }
#pragma unroll
            for (int mt = 0; mt < 2; ++mt) {
                mma16816(lgP[mt][0], lgP[mt][1], lgP[mt][2], lgP[mt][3],
                         a2P[mt][0], a2P[mt][1], a2P[mt][2], a2P[mt][3],
                         b2P[kt][0], b2P[kt][1]);
                mma16816(lgQ[mt][0], lgQ[mt][1], lgQ[mt][2], lgQ[mt][3],
                         a2Q[mt][0], a2Q[mt][1], a2Q[mt][2], a2Q[mt][3],
                         b2Q[kt][0], b2Q[kt][1]);
            }
        }

        // epilogue: quad1 holds col2; pull it into quad0, softmax, store
#pragma unroll
        for (int mt = 0; mt < 2; ++mt) {
            float tP0 = __shfl_xor_sync(0xffffffffu, lgP[mt][0], 1);
            float tP2 = __shfl_xor_sync(0xffffffffu, lgP[mt][2], 1);
            float tQ0 = __shfl_xor_sync(0xffffffffu, lgQ[mt][0], 1);
            float tQ2 = __shfl_xor_sync(0xffffffffu, lgQ[mt][2], 1);
            if (quad == 0) {
                size_t rA = (size_t)(row0 + wid * 32 + mt * 16 + qrow);
                size_t rB = rA + 8;
                softmax_store(out, rA, nP, lgP[mt][0], lgP[mt][1], tP0);
                softmax_store(out, rB, nP, lgP[mt][2], lgP[mt][3], tP2);
                softmax_store(out, rA, nQ, lgQ[mt][0], lgQ[mt][1], tQ0);
                softmax_store(out, rB, nQ, lgQ[mt][2], lgQ[mt][3], tQ2);
            }
        }
        __syncthreads();
    }
}

// ============================================================================
extern "C" void kernel_launch(void* const* d_in, const int* in_sizes, int n_in,
                              void* d_out, int out_size)
{
    const float* x   = (const float*)d_in[0];
    const float* Cw1 = (const float*)d_in[1];
    const float* Cb1 = (const float*)d_in[2];
    const float* Cw2 = (const float*)d_in[3];
    const float* Cb2 = (const float*)d_in[4];
    const float* Nw1 = (const float*)d_in[5];
    const float* Nb1 = (const float*)d_in[6];
    const float* Nw2 = (const float*)d_in[7];
    const float* Nb2 = (const float*)d_in[8];
    const float* Fw1 = (const float*)d_in[9];
    const float* Fb1 = (const float*)d_in[10];
    const float* Fw2 = (const float*)d_in[11];
    const float* Fb2 = (const float*)d_in[12];
    const float* Ow1 = (const float*)d_in[13];
    const float* Ob1 = (const float*)d_in[14];
    const float* Ow2 = (const float*)d_in[15];
    const float* Ob2 = (const float*)d_in[16];
    float* out = (float*)d_out;

    cudaFuncSetAttribute(k_fused, cudaFuncAttributeMaxDynamicSharedMemorySize, SM_TOT);

    const int conv_elems = NB * 8192 + 4 * 8192 + NB * 1024;
    k_convert<<<(conv_elems + 255) / 256, 256>>>(Ow1, Ob1, Ow2, Nw1, Nb1, Nw2,
                                                 Fw1, Fb1, Fw2);

    k_fused<<<NTILES, 128, SM_TOT>>>(
        x, Cw1, Cb1, Cw2, Cb2, Nb2, Fb2, Ob2, out);
}

// round 10
// speedup vs baseline: 9.0224x; 1.1584x over previous
#include <cuda_runtime.h>
#include <cuda_fp16.h>
#include <cstdint>

#define NTILES 512
#define NB     54

// ========================= device scratch (fp16 images) =====================
__device__ __align__(16) __half g_w1h[NB * 8192];  // O_w1: [j=128][k=64], k57=Ob1
__device__ __align__(16) __half g_w2i[NB * 1024];  // O_w2: [n=8][k=128] (n<3 live)
__device__ __align__(16) __half g_bn1[8192];       // N_w1: [j=128][k=64], k54=Nb1
__device__ __align__(16) __half g_bn2[8192];       // N_w2: [m=64][k=128]
__device__ __align__(16) __half g_bf1[8192];       // F_w1: [j=128][k=64], k57=Fb1
__device__ __align__(16) __half g_bf2[8192];       // F_w2: [m=64][k=128]
__device__ __align__(16) __half g_fimg[NTILES * 8192]; // f images (swizzled, col57=1)

// ============================= PTX helpers =================================
__device__ __forceinline__ uint32_t smem_u32(const void* p) {
    uint32_t a;
    asm("{ .reg .u64 t; cvta.to.shared.u64 t, %1; cvt.u32.u64 %0, t; }"
        : "=r"(a) : "l"(p));
    return a;
}
__device__ __forceinline__ void ldsm_x4(uint32_t addr, uint32_t& r0, uint32_t& r1,
                                        uint32_t& r2, uint32_t& r3) {
    asm volatile("ldmatrix.sync.aligned.m8n8.x4.shared.b16 {%0,%1,%2,%3}, [%4];"
                 : "=r"(r0), "=r"(r1), "=r"(r2), "=r"(r3) : "r"(addr));
}
__device__ __forceinline__ void mma16816(float& d0, float& d1, float& d2, float& d3,
                                         uint32_t a0, uint32_t a1, uint32_t a2, uint32_t a3,
                                         uint32_t b0, uint32_t b1) {
    asm volatile("mma.sync.aligned.m16n8k16.row.col.f32.f16.f16.f32 "
                 "{%0,%1,%2,%3}, {%4,%5,%6,%7}, {%8,%9}, {%0,%1,%2,%3};"
                 : "+f"(d0), "+f"(d1), "+f"(d2), "+f"(d3)
                 : "r"(a0), "r"(a1), "r"(a2), "r"(a3), "r"(b0), "r"(b1));
}
__device__ __forceinline__ uint32_t sw128(uint32_t off) {
    return off ^ ((off >> 3) & 0x70);
}
__device__ __forceinline__ uint32_t packh2(float lo, float hi) {
    __half2 h = __floats2half2_rn(lo, hi);
    return *reinterpret_cast<uint32_t*>(&h);
}

// ============================================================================
// Convert weights -> swizzled fp16 images (biases baked at constant-1 k-col).
// ============================================================================
__global__ __launch_bounds__(256) void k_convert(
    const float* __restrict__ Ow1, const float* __restrict__ Ob1,
    const float* __restrict__ Ow2,
    const float* __restrict__ Nw1, const float* __restrict__ Nb1,
    const float* __restrict__ Nw2,
    const float* __restrict__ Fw1, const float* __restrict__ Fb1,
    const float* __restrict__ Fw2)
{
    int idx = blockIdx.x * 256 + threadIdx.x;
    if (idx < NB * 8192) {
        int j = idx & 127, k = (idx >> 7) & 63, n = idx >> 13;
        float v = (k < 57) ? Ow1[n * 7296 + k * 128 + j]
                 : (k == 57 ? Ob1[n * 128 + j] : 0.f);
        g_w1h[n * 8192 + (sw128((unsigned)(j * 128 + k * 2)) >> 1)] = __float2half(v);
        return;
    }
    int t = idx - NB * 8192;
    if (t < 4 * 8192) {
        int img = t >> 13, e = t & 8191;
        if (img == 0) {
            int j = e >> 6, k = e & 63;
            float v = (k < 54) ? Nw1[k * 128 + j] : (k == 54 ? Nb1[j] : 0.f);
            g_bn1[sw128((unsigned)(j * 128 + k * 2)) >> 1] = __float2half(v);
        } else if (img == 1) {
            int j = e >> 6, k = e & 63;
            float v = (k < 57) ? Fw1[k * 128 + j] : (k == 57 ? Fb1[j] : 0.f);
            g_bf1[sw128((unsigned)(j * 128 + k * 2)) >> 1] = __float2half(v);
        } else if (img == 2) {
            int m = e >> 7, k = e & 127;
            float v = (m < 54) ? Nw2[k * 54 + m] : 0.f;
            g_bn2[sw128((unsigned)(m * 256 + k * 2)) >> 1] = __float2half(v);
        } else {
            int m = e >> 7, k = e & 127;
            float v = (m < 57) ? Fw2[k * 57 + m] : 0.f;
            g_bf2[sw128((unsigned)(m * 256 + k * 2)) >> 1] = __float2half(v);
        }
        return;
    }
    t -= 4 * 8192;
    if (t >= NB * 1024) return;
    {
        int n = t >> 10, e = t & 1023;
        int m = e >> 7, k = e & 127;
        float v = (m < 3) ? Ow2[n * 384 + k * 3 + m] : 0.f;
        g_w2i[n * 1024 + (sw128((unsigned)(m * 256 + k * 2)) >> 1)] = __float2half(v);
    }
}

// ============================ SMEM layout ===================================
#define SM_X    0          // 16 KB
#define SM_W    16384      // 16 KB
#define SM_H0   32768      // 16 KB
#define SM_H1   49152      // 16 KB
#define SM_W2S  65536      // 8 KB (O kernel) / C-scratch overlay (features)
#define SM_XC   65536
#define SM_CW1  67584
#define SM_CW2  69632
#define SM_CB1  71680
#define SM_CB2  72192
#define SM_BN2  73728
#define SM_BF2  73984
#define SM_TOT  74240

// ---- layer: 64-K HMMA, 128 out cols, relu (bias baked), fp16 -> H0/H1 ------
__device__ __forceinline__ void layer_wide(
    uint32_t sA, uint32_t sB, char* h0, char* h1, int wid, int lane)
{
    const int m01 = (lane >> 3) & 1, kh = lane >> 4;
    const int quad = lane & 3, qrow = lane >> 2;
    const int bjrow = lane & 7, bkt = lane >> 4, bkh = (lane >> 3) & 1;

    uint32_t a[2][4][4];
#pragma unroll
    for (int mt = 0; mt < 2; ++mt) {
        int rg = wid * 32 + mt * 16 + (lane & 7) + (m01 << 3);
#pragma unroll
        for (int kt = 0; kt < 4; ++kt) {
            uint32_t off = sw128((uint32_t)(rg * 128 + kt * 32 + kh * 16));
            ldsm_x4(sA + off, a[mt][kt][0], a[mt][kt][1], a[mt][kt][2], a[mt][kt][3]);
        }
    }
#pragma unroll 4
    for (int nt = 0; nt < 16; ++nt) {
        uint32_t off0 = sw128((uint32_t)((nt * 8 + bjrow) * 128 + bkt * 32 + bkh * 16));
        uint32_t off1 = sw128((uint32_t)((nt * 8 + bjrow) * 128 + (bkt + 2) * 32 + bkh * 16));
        uint32_t b[4][2];
        ldsm_x4(sB + off0, b[0][0], b[0][1], b[1][0], b[1][1]);
        ldsm_x4(sB + off1, b[2][0], b[2][1], b[3][0], b[3][1]);
        int j0 = nt * 8 + quad * 2;
        char* himg = (j0 < 64) ? h0 : h1;
        int   jc   = j0 & 63;
#pragma unroll
        for (int mt = 0; mt < 2; ++mt) {
            float d0 = 0.f, d1 = 0.f, d2 = 0.f, d3 = 0.f;
#pragma unroll
            for (int kt = 0; kt < 4; ++kt)
                mma16816(d0, d1, d2, d3,
                         a[mt][kt][0], a[mt][kt][1], a[mt][kt][2], a[mt][kt][3],
                         b[kt][0], b[kt][1]);
            int rA = wid * 32 + mt * 16 + qrow, rB = rA + 8;
            __half2 hA = __floats2half2_rn(fmaxf(d0, 0.f), fmaxf(d1, 0.f));
            __half2 hB = __floats2half2_rn(fmaxf(d2, 0.f), fmaxf(d3, 0.f));
            *(__half2*)(himg + sw128((uint32_t)(rA * 128 + jc * 2))) = hA;
            *(__half2*)(himg + sw128((uint32_t)(rB * 128 + jc * 2))) = hB;
        }
    }
}

// ---- layer: 128-K HMMA (H in two 64-col halves), bias, fp16 -> aimg --------
__device__ __forceinline__ void layer_narrow(
    uint32_t sH0, uint32_t sH1, uint32_t sB, const float* __restrict__ bias,
    char* outimg, int coff, int mlim, int ntn, int wid, int lane)
{
    const int m01 = (lane >> 3) & 1, kh = lane >> 4;
    const int quad = lane & 3, qrow = lane >> 2;
    const int bjrow = lane & 7, bkt = lane >> 4, bkh = (lane >> 3) & 1;

    for (int mt = 0; mt < 2; ++mt) {
        int rg = wid * 32 + mt * 16 + (lane & 7) + (m01 << 3);
        uint32_t a[8][4];
#pragma unroll
        for (int kt = 0; kt < 8; ++kt) {
            uint32_t src = (kt < 4) ? sH0 : sH1;
            int      ktl = kt & 3;
            uint32_t off = sw128((uint32_t)(rg * 128 + ktl * 32 + kh * 16));
            ldsm_x4(src + off, a[kt][0], a[kt][1], a[kt][2], a[kt][3]);
        }
        for (int nt = 0; nt < ntn; ++nt) {
            uint32_t b[8][2];
#pragma unroll
            for (int q = 0; q < 4; ++q) {
                uint32_t off = sw128((uint32_t)((nt * 8 + bjrow) * 256 + q * 64 + bkt * 32 + bkh * 16));
                ldsm_x4(sB + off, b[2 * q][0], b[2 * q][1], b[2 * q + 1][0], b[2 * q + 1][1]);
            }
            float d0 = 0.f, d1 = 0.f, d2 = 0.f, d3 = 0.f;
#pragma unroll
            for (int kt = 0; kt < 8; ++kt)
                mma16816(d0, d1, d2, d3, a[kt][0], a[kt][1], a[kt][2], a[kt][3],
                         b[kt][0], b[kt][1]);
            int m0 = nt * 8 + quad * 2, m1 = m0 + 1;
            int rA = wid * 32 + mt * 16 + qrow, rB = rA + 8;
            if (m0 < mlim) {
                *(__half*)(outimg + sw128((uint32_t)(rA * 128 + (m0 + coff) * 2))) =
                    __float2half(d0 + bias[m0]);
                *(__half*)(outimg + sw128((uint32_t)(rB * 128 + (m0 + coff) * 2))) =
                    __float2half(d2 + bias[m0]);
            }
            if (m1 < mlim) {
                *(__half*)(outimg + sw128((uint32_t)(rA * 128 + (m1 + coff) * 2))) =
                    __float2half(d1 + bias[m1]);
                *(__half*)(outimg + sw128((uint32_t)(rB * 128 + (m1 + coff) * 2))) =
                    __float2half(d3 + bias[m1]);
            }
        }
    }
}

__device__ __forceinline__ void softmax_store(float* __restrict__ out,
                                              size_t row, int n,
                                              float l0, float l1, float l2)
{
    float mx = fmaxf(l0, fmaxf(l1, l2));
    float e0 = __expf(l0 - mx), e1 = __expf(l1 - mx), e2 = __expf(l2 - mx);
    float inv = 1.f / (e0 + e1 + e2);
    float* o = out + row * 162 + n * 3;
    o[0] = e0 * inv; o[1] = e1 * inv; o[2] = e2 * inv;
}

// ============================================================================
// Kernel 1: features (C scalar + N/F HMMA); writes f image to g_fimg.
// ============================================================================
__global__ void __launch_bounds__(128, 3) k_features(
    const float* __restrict__ x,
    const float* __restrict__ Cw1, const float* __restrict__ Cb1v,
    const float* __restrict__ Cw2, const float* __restrict__ Cb2v,
    const float* __restrict__ Nb2v, const float* __restrict__ Fb2v)
{
    extern __shared__ char smem[];
    const uint32_t sbase = smem_u32(smem);
    float* xc   = (float*)(smem + SM_XC);
    float* cw1t = (float*)(smem + SM_CW1);
    float* cw2  = (float*)(smem + SM_CW2);
    float* cb1  = (float*)(smem + SM_CB1);
    float* cb2  = (float*)(smem + SM_CB2);
    float* bn2  = (float*)(smem + SM_BN2);
    float* bf2  = (float*)(smem + SM_BF2);

    const int tid  = threadIdx.x;
    const int wid  = tid >> 5;
    const int lane = tid & 31;
    const int row0 = blockIdx.x * 128;

    for (int i = tid; i < 128 * 58; i += 128) {
        int r = i / 58, c = i - r * 58;
        float v = x[(size_t)(row0 + r) * 58 + c];
        if (c < 4) xc[r * 4 + c] = v;
        else *(__half*)(smem + SM_X + sw128((uint32_t)(r * 128 + (c - 4) * 2))) =
                 __float2half(v);
    }
    for (int i = tid; i < 128 * 10; i += 128) {
        int r = i / 10, kk = 54 + (i - (i / 10) * 10);
        float v = (kk == 54 || kk == 57) ? 1.f : 0.f;
        *(__half*)(smem + SM_X + sw128((uint32_t)(r * 128 + kk * 2))) = __float2half(v);
    }
    {
        const uint4* s = (const uint4*)g_bn1; uint4* d = (uint4*)(smem + SM_W);
#pragma unroll
        for (int i = 0; i < 8; ++i) d[tid + 128 * i] = s[tid + 128 * i];
    }
    cb1[tid] = Cb1v[tid];
    if (tid < 64) {
        bn2[tid] = (tid < 54) ? Nb2v[tid] : 0.f;
        bf2[tid] = (tid < 57) ? Fb2v[tid] : 0.f;
    }
    if (tid < 4) cb2[tid] = (tid < 3) ? Cb2v[tid] : 0.f;
    for (int i = tid; i < 512; i += 128) { int k = i >> 7, j = i & 127; cw1t[j * 4 + k] = Cw1[i]; }
    for (int i = tid; i < 384; i += 128) { int j = i / 3, m = i - j * 3; cw2[j * 4 + m] = Cw2[i]; }
    __syncthreads();

    // stage C (fp32 scalar)
    float c0, c1, c2;
    {
        float cx0 = xc[tid * 4 + 0], cx1 = xc[tid * 4 + 1];
        float cx2 = xc[tid * 4 + 2], cx3 = xc[tid * 4 + 3];
        c0 = cb2[0]; c1 = cb2[1]; c2 = cb2[2];
        for (int j = 0; j < 128; ++j) {
            const float* w = &cw1t[j * 4];
            float h = cb1[j] + cx0 * w[0] + cx1 * w[1] + cx2 * w[2] + cx3 * w[3];
            h = fmaxf(h, 0.f);
            const float* w2 = &cw2[j * 4];
            c0 += h * w2[0]; c1 += h * w2[1]; c2 += h * w2[2];
        }
    }

    layer_wide(sbase + SM_X, sbase + SM_W, smem + SM_H0, smem + SM_H1, wid, lane);
    __syncthreads();
    {
        const uint4* s = (const uint4*)g_bn2; uint4* d = (uint4*)(smem + SM_W);
#pragma unroll
        for (int i = 0; i < 8; ++i) d[tid + 128 * i] = s[tid + 128 * i];
    }
    __syncthreads();

    layer_narrow(sbase + SM_H0, sbase + SM_H1, sbase + SM_W, bn2,
                 smem + SM_X, 3, 54, 7, wid, lane);
    {
        *(__half*)(smem + SM_X + sw128((uint32_t)(tid * 128 + 0))) = __float2half(c0);
        *(__half*)(smem + SM_X + sw128((uint32_t)(tid * 128 + 2))) = __float2half(c1);
        *(__half*)(smem + SM_X + sw128((uint32_t)(tid * 128 + 4))) = __float2half(c2);
    }
    __syncthreads();
    {
        const uint4* s = (const uint4*)g_bf1; uint4* d = (uint4*)(smem + SM_W);
#pragma unroll
        for (int i = 0; i < 8; ++i) d[tid + 128 * i] = s[tid + 128 * i];
    }
    __syncthreads();

    layer_wide(sbase + SM_X, sbase + SM_W, smem + SM_H0, smem + SM_H1, wid, lane);
    __syncthreads();
    {
        const uint4* s = (const uint4*)g_bf2; uint4* d = (uint4*)(smem + SM_W);
#pragma unroll
        for (int i = 0; i < 8; ++i) d[tid + 128 * i] = s[tid + 128 * i];
    }
    __syncthreads();

    layer_narrow(sbase + SM_H0, sbase + SM_H1, sbase + SM_W, bf2,
                 smem + SM_X, 0, 57, 8, wid, lane);
    __syncthreads();

    // copy f image (swizzled; col57 stays 1 for O-stage bias ride) to global
    {
        const uint4* s = (const uint4*)(smem + SM_X);
        uint4* d = (uint4*)(g_fimg + (size_t)blockIdx.x * 8192);
#pragma unroll
        for (int i = 0; i < 8; ++i) d[tid + 128 * i] = s[tid + 128 * i];
    }
}

// ============================================================================
// Kernel 2: O stage, grid (512 tiles, 9 groups); 3 branch-pairs per CTA.
// Both MLP layers on tensor cores (R9 inner loop).
// ============================================================================
__global__ void __launch_bounds__(128, 3) k_ogemm(
    const float* __restrict__ Ob2, float* __restrict__ out)
{
    extern __shared__ char smem[];
    const uint32_t sbase = smem_u32(smem);

    const int tid  = threadIdx.x;
    const int wid  = tid >> 5;
    const int lane = tid & 31;
    const int row0 = blockIdx.x * 128;
    const int n0   = blockIdx.y * 6;      // first branch of this group

    // ---- prologue: A image -> X, pair0 tiles -> H0/H1, W2 pair0 ------------
    {
        const uint4* sa = (const uint4*)(g_fimg + (size_t)blockIdx.x * 8192);
        uint4* dx = (uint4*)(smem + SM_X);
        const uint4* s0 = (const uint4*)(g_w1h + n0 * 8192);
        const uint4* s1 = (const uint4*)(g_w1h + (n0 + 1) * 8192);
        uint4* d0 = (uint4*)(smem + SM_H0);
        uint4* d1 = (uint4*)(smem + SM_H1);
#pragma unroll
        for (int i = 0; i < 8; ++i) {
            dx[tid + 128 * i] = sa[tid + 128 * i];
            d0[tid + 128 * i] = s0[tid + 128 * i];
            d1[tid + 128 * i] = s1[tid + 128 * i];
        }
        ((uint4*)(smem + SM_W2S))[tid]        = ((const uint4*)(g_w2i + n0 * 1024))[tid];
        ((uint4*)(smem + SM_W2S + 2048))[tid] = ((const uint4*)(g_w2i + (n0 + 1) * 1024))[tid];
    }
    __syncthreads();

    uint32_t a[2][4][4];
    {
        int m01 = (lane >> 3) & 1, kh = lane >> 4;
#pragma unroll
        for (int mt = 0; mt < 2; ++mt) {
            int rg = wid * 32 + mt * 16 + (lane & 7) + (m01 << 3);
#pragma unroll
            for (int kt = 0; kt < 4; ++kt) {
                uint32_t off = sw128((uint32_t)(rg * 128 + kt * 32 + kh * 16));
                ldsm_x4(sbase + SM_X + off,
                        a[mt][kt][0], a[mt][kt][1], a[mt][kt][2], a[mt][kt][3]);
            }
        }
    }
    __syncthreads();    // X free for pair1

    const int quad = lane & 3;
    const int qrow = lane >> 2;
    const int bjrow = lane & 7;
    const int bkt   = lane >> 4;
    const int bkh   = (lane >> 3) & 1;
    const uint32_t w2rowb = (uint32_t)((lane & 7) * 256 + (lane >> 3) * 16);

    for (int p = 0; p < 3; ++p) {
        const int buf = p & 1, nxt = buf ^ 1;
        const int nP = n0 + 2 * p, nQ = nP + 1;

        if (p < 2) {
            const uint4* s0 = (const uint4*)(g_w1h + (nP + 2) * 8192);
            const uint4* s1 = (const uint4*)(g_w1h + (nP + 3) * 8192);
            uint4* d0 = (uint4*)(smem + (nxt ? SM_X : SM_H0));
            uint4* d1 = (uint4*)(smem + (nxt ? SM_W : SM_H1));
#pragma unroll
            for (int i = 0; i < 8; ++i) {
                d0[tid + 128 * i] = s0[tid + 128 * i];
                d1[tid + 128 * i] = s1[tid + 128 * i];
            }
            ((uint4*)(smem + SM_W2S + nxt * 4096))[tid] =
                ((const uint4*)(g_w2i + (nP + 2) * 1024))[tid];
            ((uint4*)(smem + SM_W2S + nxt * 4096 + 2048))[tid] =
                ((const uint4*)(g_w2i + (nP + 3) * 1024))[tid];
        }

        const uint32_t sb0  = sbase + (buf ? SM_X : SM_H0);
        const uint32_t sb1  = sbase + (buf ? SM_W : SM_H1);
        const uint32_t sw2P = sbase + SM_W2S + (uint32_t)buf * 4096;
        const uint32_t sw2Q = sw2P + 2048;

        uint32_t b2P[8][2], b2Q[8][2];
#pragma unroll
        for (int c = 0; c < 4; ++c) {
            uint32_t off = sw128(w2rowb + (uint32_t)c * 64);
            ldsm_x4(sw2P + off, b2P[2 * c][0], b2P[2 * c][1],
                                b2P[2 * c + 1][0], b2P[2 * c + 1][1]);
            ldsm_x4(sw2Q + off, b2Q[2 * c][0], b2Q[2 * c][1],
                                b2Q[2 * c + 1][0], b2Q[2 * c + 1][1]);
        }

        float lgP[2][4], lgQ[2][4];
        {
            int cc0 = 2 * quad, cc1 = cc0 + 1;
            float p0 = (cc0 < 3) ? Ob2[nP * 3 + cc0] : 0.f;
            float p1 = (cc1 < 3) ? Ob2[nP * 3 + cc1] : 0.f;
            float q0 = (cc0 < 3) ? Ob2[nQ * 3 + cc0] : 0.f;
            float q1 = (cc1 < 3) ? Ob2[nQ * 3 + cc1] : 0.f;
#pragma unroll
            for (int mt = 0; mt < 2; ++mt) {
                lgP[mt][0] = p0; lgP[mt][1] = p1; lgP[mt][2] = p0; lgP[mt][3] = p1;
                lgQ[mt][0] = q0; lgQ[mt][1] = q1; lgQ[mt][2] = q0; lgQ[mt][3] = q1;
            }
        }

#pragma unroll 4
        for (int kt = 0; kt < 8; ++kt) {
            uint32_t a2P[2][4], a2Q[2][4];
#pragma unroll
            for (int e = 0; e < 2; ++e) {
                const int nt = 2 * kt + e;
                uint32_t off0 = sw128((uint32_t)((nt * 8 + bjrow) * 128 + bkt * 32 + bkh * 16));
                uint32_t off1 = sw128((uint32_t)((nt * 8 + bjrow) * 128 + (bkt + 2) * 32 + bkh * 16));
                uint32_t bP[4][2], bQ[4][2];
                ldsm_x4(sb0 + off0, bP[0][0], bP[0][1], bP[1][0], bP[1][1]);
                ldsm_x4(sb0 + off1, bP[2][0], bP[2][1], bP[3][0], bP[3][1]);
                ldsm_x4(sb1 + off0, bQ[0][0], bQ[0][1], bQ[1][0], bQ[1][1]);
                ldsm_x4(sb1 + off1, bQ[2][0], bQ[2][1], bQ[3][0], bQ[3][1]);
#pragma unroll
                for (int mt = 0; mt < 2; ++mt) {
                    float dP0 = 0.f, dP1 = 0.f, dP2 = 0.f, dP3 = 0.f;
                    float dQ0 = 0.f, dQ1 = 0.f, dQ2 = 0.f, dQ3 = 0.f;
#pragma unroll
                    for (int k4 = 0; k4 < 4; ++k4) {
                        mma16816(dP0, dP1, dP2, dP3,
                                 a[mt][k4][0], a[mt][k4][1], a[mt][k4][2], a[mt][k4][3],
                                 bP[k4][0], bP[k4][1]);
                        mma16816(dQ0, dQ1, dQ2, dQ3,
                                 a[mt][k4][0], a[mt][k4][1], a[mt][k4][2], a[mt][k4][3],
                                 bQ[k4][0], bQ[k4][1]);
                    }
                    a2P[mt][2 * e]     = packh2(fmaxf(dP0, 0.f), fmaxf(dP1, 0.f));
                    a2P[mt][2 * e + 1] = packh2(fmaxf(dP2, 0.f), fmaxf(dP3, 0.f));
                    a2Q[mt][2 * e]     = packh2(fmaxf(dQ0, 0.f), fmaxf(dQ1, 0.f));
                    a2Q[mt][2 * e + 1] = packh2(fmaxf(dQ2, 0.f), fmaxf(dQ3, 0.f));
                }
            }
#pragma unroll
            for (int mt = 0; mt < 2; ++mt) {
                mma16816(lgP[mt][0], lgP[mt][1], lgP[mt][2], lgP[mt][3],
                         a2P[mt][0], a2P[mt][1], a2P[mt][2], a2P[mt][3],
                         b2P[kt][0], b2P[kt][1]);
                mma16816(lgQ[mt][0], lgQ[mt][1], lgQ[mt][2], lgQ[mt][3],
                         a2Q[mt][0], a2Q[mt][1], a2Q[mt][2], a2Q[mt][3],
                         b2Q[kt][0], b2Q[kt][1]);
            }
        }

#pragma unroll
        for (int mt = 0; mt < 2; ++mt) {
            float tP0 = __shfl_xor_sync(0xffffffffu, lgP[mt][0], 1);
            float tP2 = __shfl_xor_sync(0xffffffffu, lgP[mt][2], 1);
            float tQ0 = __shfl_xor_sync(0xffffffffu, lgQ[mt][0], 1);
            float tQ2 = __shfl_xor_sync(0xffffffffu, lgQ[mt][2], 1);
            if (quad == 0) {
                size_t rA = (size_t)(row0 + wid * 32 + mt * 16 + qrow);
                size_t rB = rA + 8;
                softmax_store(out, rA, nP, lgP[mt][0], lgP[mt][1], tP0);
                softmax_store(out, rB, nP, lgP[mt][2], lgP[mt][3], tP2);
                softmax_store(out, rA, nQ, lgQ[mt][0], lgQ[mt][1], tQ0);
                softmax_store(out, rB, nQ, lgQ[mt][2], lgQ[mt][3], tQ2);
            }
        }
        __syncthreads();
    }
}

// ============================================================================
extern "C" void kernel_launch(void* const* d_in, const int* in_sizes, int n_in,
                              void* d_out, int out_size)
{
    const float* x   = (const float*)d_in[0];
    const float* Cw1 = (const float*)d_in[1];
    const float* Cb1 = (const float*)d_in[2];
    const float* Cw2 = (const float*)d_in[3];
    const float* Cb2 = (const float*)d_in[4];
    const float* Nw1 = (const float*)d_in[5];
    const float* Nb1 = (const float*)d_in[6];
    const float* Nw2 = (const float*)d_in[7];
    const float* Nb2 = (const float*)d_in[8];
    const float* Fw1 = (const float*)d_in[9];
    const float* Fb1 = (const float*)d_in[10];
    const float* Fw2 = (const float*)d_in[11];
    const float* Fb2 = (const float*)d_in[12];
    const float* Ow1 = (const float*)d_in[13];
    const float* Ob1 = (const float*)d_in[14];
    const float* Ow2 = (const float*)d_in[15];
    const float* Ob2 = (const float*)d_in[16];
    float* out = (float*)d_out;

    cudaFuncSetAttribute(k_features, cudaFuncAttributeMaxDynamicSharedMemorySize, SM_TOT);
    cudaFuncSetAttribute(k_ogemm,    cudaFuncAttributeMaxDynamicSharedMemorySize, SM_TOT);

    const int conv_elems = NB * 8192 + 4 * 8192 + NB * 1024;
    k_convert<<<(conv_elems + 255) / 256, 256>>>(Ow1, Ob1, Ow2, Nw1, Nb1, Nw2,
                                                 Fw1, Fb1, Fw2);

    k_features<<<NTILES, 128, SM_TOT>>>(x, Cw1, Cb1, Cw2, Cb2, Nb2, Fb2);

    dim3 grid2(NTILES, 9);
    k_ogemm<<<grid2, 128, SM_TOT>>>(Ob2, out);
}

// round 11
// speedup vs baseline: 10.4247x; 1.1554x over previous
#include <cuda_runtime.h>
#include <cuda_fp16.h>
#include <cstdint>

#define NTILES 512
#define NB     54

// ========================= device scratch (fp16 images) =====================
__device__ __align__(16) __half g_w1h[NB * 8192];  // O_w1: [j=128][k=64], k57=Ob1
__device__ __align__(16) __half g_w2i[NB * 1024];  // O_w2: [n=8][k=128] (n<3 live)
__device__ __align__(16) __half g_bn1[8192];       // N_w1
__device__ __align__(16) __half g_bn2[8192];       // N_w2
__device__ __align__(16) __half g_bf1[8192];       // F_w1
__device__ __align__(16) __half g_bf2[8192];       // F_w2
__device__ __align__(16) __half g_fimg[NTILES * 8192]; // f images (swizzled, col57=1)

// ============================= PTX helpers =================================
__device__ __forceinline__ uint32_t smem_u32(const void* p) {
    uint32_t a;
    asm("{ .reg .u64 t; cvta.to.shared.u64 t, %1; cvt.u32.u64 %0, t; }"
        : "=r"(a) : "l"(p));
    return a;
}
__device__ __forceinline__ void ldsm_x4(uint32_t addr, uint32_t& r0, uint32_t& r1,
                                        uint32_t& r2, uint32_t& r3) {
    asm volatile("ldmatrix.sync.aligned.m8n8.x4.shared.b16 {%0,%1,%2,%3}, [%4];"
                 : "=r"(r0), "=r"(r1), "=r"(r2), "=r"(r3) : "r"(addr));
}
__device__ __forceinline__ void mma16816(float& d0, float& d1, float& d2, float& d3,
                                         uint32_t a0, uint32_t a1, uint32_t a2, uint32_t a3,
                                         uint32_t b0, uint32_t b1) {
    asm volatile("mma.sync.aligned.m16n8k16.row.col.f32.f16.f16.f32 "
                 "{%0,%1,%2,%3}, {%4,%5,%6,%7}, {%8,%9}, {%0,%1,%2,%3};"
                 : "+f"(d0), "+f"(d1), "+f"(d2), "+f"(d3)
                 : "r"(a0), "r"(a1), "r"(a2), "r"(a3), "r"(b0), "r"(b1));
}
__device__ __forceinline__ uint32_t sw128(uint32_t off) {
    return off ^ ((off >> 3) & 0x70);
}
__device__ __forceinline__ uint32_t packh2(float lo, float hi) {
    __half2 h = __floats2half2_rn(lo, hi);
    return *reinterpret_cast<uint32_t*>(&h);
}

// ============================================================================
// Convert weights -> swizzled fp16 images (biases baked at constant-1 k-col).
// ============================================================================
__global__ __launch_bounds__(256) void k_convert(
    const float* __restrict__ Ow1, const float* __restrict__ Ob1,
    const float* __restrict__ Ow2,
    const float* __restrict__ Nw1, const float* __restrict__ Nb1,
    const float* __restrict__ Nw2,
    const float* __restrict__ Fw1, const float* __restrict__ Fb1,
    const float* __restrict__ Fw2)
{
    int idx = blockIdx.x * 256 + threadIdx.x;
    if (idx < NB * 8192) {
        int j = idx & 127, k = (idx >> 7) & 63, n = idx >> 13;
        float v = (k < 57) ? Ow1[n * 7296 + k * 128 + j]
                 : (k == 57 ? Ob1[n * 128 + j] : 0.f);
        g_w1h[n * 8192 + (sw128((unsigned)(j * 128 + k * 2)) >> 1)] = __float2half(v);
        return;
    }
    int t = idx - NB * 8192;
    if (t < 4 * 8192) {
        int img = t >> 13, e = t & 8191;
        if (img == 0) {
            int j = e >> 6, k = e & 63;
            float v = (k < 54) ? Nw1[k * 128 + j] : (k == 54 ? Nb1[j] : 0.f);
            g_bn1[sw128((unsigned)(j * 128 + k * 2)) >> 1] = __float2half(v);
        } else if (img == 1) {
            int j = e >> 6, k = e & 63;
            float v = (k < 57) ? Fw1[k * 128 + j] : (k == 57 ? Fb1[j] : 0.f);
            g_bf1[sw128((unsigned)(j * 128 + k * 2)) >> 1] = __float2half(v);
        } else if (img == 2) {
            int m = e >> 7, k = e & 127;
            float v = (m < 54) ? Nw2[k * 54 + m] : 0.f;
            g_bn2[sw128((unsigned)(m * 256 + k * 2)) >> 1] = __float2half(v);
        } else {
            int m = e >> 7, k = e & 127;
            float v = (m < 57) ? Fw2[k * 57 + m] : 0.f;
            g_bf2[sw128((unsigned)(m * 256 + k * 2)) >> 1] = __float2half(v);
        }
        return;
    }
    t -= 4 * 8192;
    if (t >= NB * 1024) return;
    {
        int n = t >> 10, e = t & 1023;
        int m = e >> 7, k = e & 127;
        float v = (m < 3) ? Ow2[n * 384 + k * 3 + m] : 0.f;
        g_w2i[n * 1024 + (sw128((unsigned)(m * 256 + k * 2)) >> 1)] = __float2half(v);
    }
}

// ==================== features-kernel SMEM layout (74.2 KB) =================
#define SM_X    0
#define SM_W    16384
#define SM_H0   32768
#define SM_H1   49152
#define SM_XC   65536
#define SM_CW1  67584
#define SM_CW2  69632
#define SM_CB1  71680
#define SM_CB2  72192
#define SM_BN2  73728
#define SM_BF2  73984
#define SM_TOT  74240

// ---- layer: 64-K HMMA, 128 out cols, relu (bias baked), fp16 -> H0/H1 ------
__device__ __forceinline__ void layer_wide(
    uint32_t sA, uint32_t sB, char* h0, char* h1, int wid, int lane)
{
    const int m01 = (lane >> 3) & 1, kh = lane >> 4;
    const int quad = lane & 3, qrow = lane >> 2;
    const int bjrow = lane & 7, bkt = lane >> 4, bkh = (lane >> 3) & 1;

    uint32_t a[2][4][4];
#pragma unroll
    for (int mt = 0; mt < 2; ++mt) {
        int rg = wid * 32 + mt * 16 + (lane & 7) + (m01 << 3);
#pragma unroll
        for (int kt = 0; kt < 4; ++kt) {
            uint32_t off = sw128((uint32_t)(rg * 128 + kt * 32 + kh * 16));
            ldsm_x4(sA + off, a[mt][kt][0], a[mt][kt][1], a[mt][kt][2], a[mt][kt][3]);
        }
    }
#pragma unroll 4
    for (int nt = 0; nt < 16; ++nt) {
        uint32_t off0 = sw128((uint32_t)((nt * 8 + bjrow) * 128 + bkt * 32 + bkh * 16));
        uint32_t off1 = sw128((uint32_t)((nt * 8 + bjrow) * 128 + (bkt + 2) * 32 + bkh * 16));
        uint32_t b[4][2];
        ldsm_x4(sB + off0, b[0][0], b[0][1], b[1][0], b[1][1]);
        ldsm_x4(sB + off1, b[2][0], b[2][1], b[3][0], b[3][1]);
        int j0 = nt * 8 + quad * 2;
        char* himg = (j0 < 64) ? h0 : h1;
        int   jc   = j0 & 63;
#pragma unroll
        for (int mt = 0; mt < 2; ++mt) {
            float d0 = 0.f, d1 = 0.f, d2 = 0.f, d3 = 0.f;
#pragma unroll
            for (int kt = 0; kt < 4; ++kt)
                mma16816(d0, d1, d2, d3,
                         a[mt][kt][0], a[mt][kt][1], a[mt][kt][2], a[mt][kt][3],
                         b[kt][0], b[kt][1]);
            int rA = wid * 32 + mt * 16 + qrow, rB = rA + 8;
            __half2 hA = __floats2half2_rn(fmaxf(d0, 0.f), fmaxf(d1, 0.f));
            __half2 hB = __floats2half2_rn(fmaxf(d2, 0.f), fmaxf(d3, 0.f));
            *(__half2*)(himg + sw128((uint32_t)(rA * 128 + jc * 2))) = hA;
            *(__half2*)(himg + sw128((uint32_t)(rB * 128 + jc * 2))) = hB;
        }
    }
}

// ---- layer: 128-K HMMA (H in two 64-col halves), bias, fp16 -> aimg --------
__device__ __forceinline__ void layer_narrow(
    uint32_t sH0, uint32_t sH1, uint32_t sB, const float* __restrict__ bias,
    char* outimg, int coff, int mlim, int ntn, int wid, int lane)
{
    const int m01 = (lane >> 3) & 1, kh = lane >> 4;
    const int quad = lane & 3, qrow = lane >> 2;
    const int bjrow = lane & 7, bkt = lane >> 4, bkh = (lane >> 3) & 1;

    for (int mt = 0; mt < 2; ++mt) {
        int rg = wid * 32 + mt * 16 + (lane & 7) + (m01 << 3);
        uint32_t a[8][4];
#pragma unroll
        for (int kt = 0; kt < 8; ++kt) {
            uint32_t src = (kt < 4) ? sH0 : sH1;
            int      ktl = kt & 3;
            uint32_t off = sw128((uint32_t)(rg * 128 + ktl * 32 + kh * 16));
            ldsm_x4(src + off, a[kt][0], a[kt][1], a[kt][2], a[kt][3]);
        }
        for (int nt = 0; nt < ntn; ++nt) {
            uint32_t b[8][2];
#pragma unroll
            for (int q = 0; q < 4; ++q) {
                uint32_t off = sw128((uint32_t)((nt * 8 + bjrow) * 256 + q * 64 + bkt * 32 + bkh * 16));
                ldsm_x4(sB + off, b[2 * q][0], b[2 * q][1], b[2 * q + 1][0], b[2 * q + 1][1]);
            }
            float d0 = 0.f, d1 = 0.f, d2 = 0.f, d3 = 0.f;
#pragma unroll
            for (int kt = 0; kt < 8; ++kt)
                mma16816(d0, d1, d2, d3, a[kt][0], a[kt][1], a[kt][2], a[kt][3],
                         b[kt][0], b[kt][1]);
            int m0 = nt * 8 + quad * 2, m1 = m0 + 1;
            int rA = wid * 32 + mt * 16 + qrow, rB = rA + 8;
            if (m0 < mlim) {
                *(__half*)(outimg + sw128((uint32_t)(rA * 128 + (m0 + coff) * 2))) =
                    __float2half(d0 + bias[m0]);
                *(__half*)(outimg + sw128((uint32_t)(rB * 128 + (m0 + coff) * 2))) =
                    __float2half(d2 + bias[m0]);
            }
            if (m1 < mlim) {
                *(__half*)(outimg + sw128((uint32_t)(rA * 128 + (m1 + coff) * 2))) =
                    __float2half(d1 + bias[m1]);
                *(__half*)(outimg + sw128((uint32_t)(rB * 128 + (m1 + coff) * 2))) =
                    __float2half(d3 + bias[m1]);
            }
        }
    }
}

__device__ __forceinline__ void softmax_store(float* __restrict__ out,
                                              size_t row, int n,
                                              float l0, float l1, float l2)
{
    float mx = fmaxf(l0, fmaxf(l1, l2));
    float e0 = __expf(l0 - mx), e1 = __expf(l1 - mx), e2 = __expf(l2 - mx);
    float inv = 1.f / (e0 + e1 + e2);
    float* o = out + row * 162 + n * 3;
    o[0] = e0 * inv; o[1] = e1 * inv; o[2] = e2 * inv;
}

// ============================================================================
// Kernel 1: features (C scalar + N/F HMMA); writes f image to g_fimg.
// (unchanged from R10)
// ============================================================================
__global__ void __launch_bounds__(128, 3) k_features(
    const float* __restrict__ x,
    const float* __restrict__ Cw1, const float* __restrict__ Cb1v,
    const float* __restrict__ Cw2, const float* __restrict__ Cb2v,
    const float* __restrict__ Nb2v, const float* __restrict__ Fb2v)
{
    extern __shared__ char smem[];
    const uint32_t sbase = smem_u32(smem);
    float* xc   = (float*)(smem + SM_XC);
    float* cw1t = (float*)(smem + SM_CW1);
    float* cw2  = (float*)(smem + SM_CW2);
    float* cb1  = (float*)(smem + SM_CB1);
    float* cb2  = (float*)(smem + SM_CB2);
    float* bn2  = (float*)(smem + SM_BN2);
    float* bf2  = (float*)(smem + SM_BF2);

    const int tid  = threadIdx.x;
    const int wid  = tid >> 5;
    const int lane = tid & 31;
    const int row0 = blockIdx.x * 128;

    for (int i = tid; i < 128 * 58; i += 128) {
        int r = i / 58, c = i - r * 58;
        float v = x[(size_t)(row0 + r) * 58 + c];
        if (c < 4) xc[r * 4 + c] = v;
        else *(__half*)(smem + SM_X + sw128((uint32_t)(r * 128 + (c - 4) * 2))) =
                 __float2half(v);
    }
    for (int i = tid; i < 128 * 10; i += 128) {
        int r = i / 10, kk = 54 + (i - (i / 10) * 10);
        float v = (kk == 54 || kk == 57) ? 1.f : 0.f;
        *(__half*)(smem + SM_X + sw128((uint32_t)(r * 128 + kk * 2))) = __float2half(v);
    }
    {
        const uint4* s = (const uint4*)g_bn1; uint4* d = (uint4*)(smem + SM_W);
#pragma unroll
        for (int i = 0; i < 8; ++i) d[tid + 128 * i] = s[tid + 128 * i];
    }
    cb1[tid] = Cb1v[tid];
    if (tid < 64) {
        bn2[tid] = (tid < 54) ? Nb2v[tid] : 0.f;
        bf2[tid] = (tid < 57) ? Fb2v[tid] : 0.f;
    }
    if (tid < 4) cb2[tid] = (tid < 3) ? Cb2v[tid] : 0.f;
    for (int i = tid; i < 512; i += 128) { int k = i >> 7, j = i & 127; cw1t[j * 4 + k] = Cw1[i]; }
    for (int i = tid; i < 384; i += 128) { int j = i / 3, m = i - j * 3; cw2[j * 4 + m] = Cw2[i]; }
    __syncthreads();

    float c0, c1, c2;
    {
        float cx0 = xc[tid * 4 + 0], cx1 = xc[tid * 4 + 1];
        float cx2 = xc[tid * 4 + 2], cx3 = xc[tid * 4 + 3];
        c0 = cb2[0]; c1 = cb2[1]; c2 = cb2[2];
        for (int j = 0; j < 128; ++j) {
            const float* w = &cw1t[j * 4];
            float h = cb1[j] + cx0 * w[0] + cx1 * w[1] + cx2 * w[2] + cx3 * w[3];
            h = fmaxf(h, 0.f);
            const float* w2 = &cw2[j * 4];
            c0 += h * w2[0]; c1 += h * w2[1]; c2 += h * w2[2];
        }
    }

    layer_wide(sbase + SM_X, sbase + SM_W, smem + SM_H0, smem + SM_H1, wid, lane);
    __syncthreads();
    {
        const uint4* s = (const uint4*)g_bn2; uint4* d = (uint4*)(smem + SM_W);
#pragma unroll
        for (int i = 0; i < 8; ++i) d[tid + 128 * i] = s[tid + 128 * i];
    }
    __syncthreads();

    layer_narrow(sbase + SM_H0, sbase + SM_H1, sbase + SM_W, bn2,
                 smem + SM_X, 3, 54, 7, wid, lane);
    {
        *(__half*)(smem + SM_X + sw128((uint32_t)(tid * 128 + 0))) = __float2half(c0);
        *(__half*)(smem + SM_X + sw128((uint32_t)(tid * 128 + 2))) = __float2half(c1);
        *(__half*)(smem + SM_X + sw128((uint32_t)(tid * 128 + 4))) = __float2half(c2);
    }
    __syncthreads();
    {
        const uint4* s = (const uint4*)g_bf1; uint4* d = (uint4*)(smem + SM_W);
#pragma unroll
        for (int i = 0; i < 8; ++i) d[tid + 128 * i] = s[tid + 128 * i];
    }
    __syncthreads();

    layer_wide(sbase + SM_X, sbase + SM_W, smem + SM_H0, smem + SM_H1, wid, lane);
    __syncthreads();
    {
        const uint4* s = (const uint4*)g_bf2; uint4* d = (uint4*)(smem + SM_W);
#pragma unroll
        for (int i = 0; i < 8; ++i) d[tid + 128 * i] = s[tid + 128 * i];
    }
    __syncthreads();

    layer_narrow(sbase + SM_H0, sbase + SM_H1, sbase + SM_W, bf2,
                 smem + SM_X, 0, 57, 8, wid, lane);
    __syncthreads();

    {
        const uint4* s = (const uint4*)(smem + SM_X);
        uint4* d = (uint4*)(g_fimg + (size_t)blockIdx.x * 8192);
#pragma unroll
        for (int i = 0; i < 8; ++i) d[tid + 128 * i] = s[tid + 128 * i];
    }
}

// ==================== O-kernel SMEM layout (106.5 KB, 2 CTAs/SM) ============
#define OG_A    0          // 32 KB: two A tile images (rows 0-127, 128-255)
#define OG_B0   32768      // 16 KB: pairbuf0 branch P
#define OG_B1   49152      // 16 KB: pairbuf0 branch Q
#define OG_B2   65536      // 16 KB: pairbuf1 branch P
#define OG_B3   81920      // 16 KB: pairbuf1 branch Q
#define OG_W2S  98304      // 8 KB: W2 images [pair][branch]
#define OG_TOT  106496

// ============================================================================
// Kernel 2: O stage, 256 threads / 8 warps / 256 rows, 2 CTAs/SM (16 warps).
// grid (256 row-tiles, 9 branch-groups); 3 branch-pairs per CTA.
// ============================================================================
__global__ void __launch_bounds__(256, 2) k_ogemm(
    const float* __restrict__ Ob2, float* __restrict__ out)
{
    extern __shared__ char smem[];
    const uint32_t sbase = smem_u32(smem);

    const int tid  = threadIdx.x;
    const int wid  = tid >> 5;
    const int lane = tid & 31;
    const int row0 = blockIdx.x * 256;
    const int n0   = blockIdx.y * 6;

    // ---- prologue: A images (32 KB) + pair0 tiles + W2 pair0 ---------------
    {
        const uint4* sa = (const uint4*)(g_fimg + (size_t)blockIdx.x * 16384);
        uint4* dx = (uint4*)(smem + OG_A);
#pragma unroll
        for (int i = 0; i < 8; ++i) dx[tid + 256 * i] = sa[tid + 256 * i];
        const uint4* s0 = (const uint4*)(g_w1h + n0 * 8192);   // branches n0,n0+1 contiguous
        uint4* d0 = (uint4*)(smem + OG_B0);
#pragma unroll
        for (int i = 0; i < 8; ++i) d0[tid + 256 * i] = s0[tid + 256 * i];
        ((uint4*)(smem + OG_W2S))[tid] = ((const uint4*)(g_w2i + n0 * 1024))[tid];
    }
    __syncthreads();

    // ---- A fragments: warp owns rows 32*wid .. 32*wid+31 --------------------
    uint32_t a[2][4][4];
    {
        int m01 = (lane >> 3) & 1, kh = lane >> 4;
#pragma unroll
        for (int mt = 0; mt < 2; ++mt) {
            int rg = wid * 32 + mt * 16 + (lane & 7) + (m01 << 3);
            uint32_t base = sbase + OG_A + (uint32_t)(rg >> 7) * 16384;
            int rl = rg & 127;
#pragma unroll
            for (int kt = 0; kt < 4; ++kt) {
                uint32_t off = sw128((uint32_t)(rl * 128 + kt * 32 + kh * 16));
                ldsm_x4(base + off,
                        a[mt][kt][0], a[mt][kt][1], a[mt][kt][2], a[mt][kt][3]);
            }
        }
    }

    const int quad = lane & 3;
    const int qrow = lane >> 2;
    const int bjrow = lane & 7;
    const int bkt   = lane >> 4;
    const int bkh   = (lane >> 3) & 1;
    const uint32_t w2rowb = (uint32_t)((lane & 7) * 256 + (lane >> 3) * 16);

    for (int p = 0; p < 3; ++p) {
        const int buf = p & 1, nxt = buf ^ 1;
        const int nP = n0 + 2 * p, nQ = nP + 1;

        if (p < 2) {
            const uint4* s0 = (const uint4*)(g_w1h + (nP + 2) * 8192);
            uint4* d0 = (uint4*)(smem + (nxt ? OG_B2 : OG_B0));
#pragma unroll
            for (int i = 0; i < 8; ++i) d0[tid + 256 * i] = s0[tid + 256 * i];
            ((uint4*)(smem + OG_W2S + nxt * 4096))[tid] =
                ((const uint4*)(g_w2i + (nP + 2) * 1024))[tid];
        }

        const uint32_t sb0  = sbase + (buf ? OG_B2 : OG_B0);
        const uint32_t sb1  = sb0 + 16384;
        const uint32_t sw2P = sbase + OG_W2S + (uint32_t)buf * 4096;
        const uint32_t sw2Q = sw2P + 2048;

        float lgP[2][4], lgQ[2][4];
        {
            int cc0 = 2 * quad, cc1 = cc0 + 1;
            float p0 = (cc0 < 3) ? Ob2[nP * 3 + cc0] : 0.f;
            float p1 = (cc1 < 3) ? Ob2[nP * 3 + cc1] : 0.f;
            float q0 = (cc0 < 3) ? Ob2[nQ * 3 + cc0] : 0.f;
            float q1 = (cc1 < 3) ? Ob2[nQ * 3 + cc1] : 0.f;
#pragma unroll
            for (int mt = 0; mt < 2; ++mt) {
                lgP[mt][0] = p0; lgP[mt][1] = p1; lgP[mt][2] = p0; lgP[mt][3] = p1;
                lgQ[mt][0] = q0; lgQ[mt][1] = q1; lgQ[mt][2] = q0; lgQ[mt][3] = q1;
            }
        }

        uint32_t b2P[2][2], b2Q[2][2];
#pragma unroll
        for (int kt = 0; kt < 8; ++kt) {
            if ((kt & 1) == 0) {   // load W2 frags for kt, kt+1
                uint32_t off = sw128(w2rowb + (uint32_t)(kt >> 1) * 64);
                ldsm_x4(sw2P + off, b2P[0][0], b2P[0][1], b2P[1][0], b2P[1][1]);
                ldsm_x4(sw2Q + off, b2Q[0][0], b2Q[0][1], b2Q[1][0], b2Q[1][1]);
            }
            uint32_t a2P[2][4], a2Q[2][4];
#pragma unroll
            for (int e = 0; e < 2; ++e) {
                const int nt = 2 * kt + e;
                uint32_t off0 = sw128((uint32_t)((nt * 8 + bjrow) * 128 + bkt * 32 + bkh * 16));
                uint32_t off1 = sw128((uint32_t)((nt * 8 + bjrow) * 128 + (bkt + 2) * 32 + bkh * 16));
                uint32_t bP[4][2], bQ[4][2];
                ldsm_x4(sb0 + off0, bP[0][0], bP[0][1], bP[1][0], bP[1][1]);
                ldsm_x4(sb0 + off1, bP[2][0], bP[2][1], bP[3][0], bP[3][1]);
                ldsm_x4(sb1 + off0, bQ[0][0], bQ[0][1], bQ[1][0], bQ[1][1]);
                ldsm_x4(sb1 + off1, bQ[2][0], bQ[2][1], bQ[3][0], bQ[3][1]);
#pragma unroll
                for (int mt = 0; mt < 2; ++mt) {
                    float dP0 = 0.f, dP1 = 0.f, dP2 = 0.f, dP3 = 0.f;
                    float dQ0 = 0.f, dQ1 = 0.f, dQ2 = 0.f, dQ3 = 0.f;
#pragma unroll
                    for (int k4 = 0; k4 < 4; ++k4) {
                        mma16816(dP0, dP1, dP2, dP3,
                                 a[mt][k4][0], a[mt][k4][1], a[mt][k4][2], a[mt][k4][3],
                                 bP[k4][0], bP[k4][1]);
                        mma16816(dQ0, dQ1, dQ2, dQ3,
                                 a[mt][k4][0], a[mt][k4][1], a[mt][k4][2], a[mt][k4][3],
                                 bQ[k4][0], bQ[k4][1]);
                    }
                    a2P[mt][2 * e]     = packh2(fmaxf(dP0, 0.f), fmaxf(dP1, 0.f));
                    a2P[mt][2 * e + 1] = packh2(fmaxf(dP2, 0.f), fmaxf(dP3, 0.f));
                    a2Q[mt][2 * e]     = packh2(fmaxf(dQ0, 0.f), fmaxf(dQ1, 0.f));
                    a2Q[mt][2 * e + 1] = packh2(fmaxf(dQ2, 0.f), fmaxf(dQ3, 0.f));
                }
            }
#pragma unroll
            for (int mt = 0; mt < 2; ++mt) {
                mma16816(lgP[mt][0], lgP[mt][1], lgP[mt][2], lgP[mt][3],
                         a2P[mt][0], a2P[mt][1], a2P[mt][2], a2P[mt][3],
                         b2P[kt & 1][0], b2P[kt & 1][1]);
                mma16816(lgQ[mt][0], lgQ[mt][1], lgQ[mt][2], lgQ[mt][3],
                         a2Q[mt][0], a2Q[mt][1], a2Q[mt][2], a2Q[mt][3],
                         b2Q[kt & 1][0], b2Q[kt & 1][1]);
            }
        }

#pragma unroll
        for (int mt = 0; mt < 2; ++mt) {
            float tP0 = __shfl_xor_sync(0xffffffffu, lgP[mt][0], 1);
            float tP2 = __shfl_xor_sync(0xffffffffu, lgP[mt][2], 1);
            float tQ0 = __shfl_xor_sync(0xffffffffu, lgQ[mt][0], 1);
            float tQ2 = __shfl_xor_sync(0xffffffffu, lgQ[mt][2], 1);
            if (quad == 0) {
                size_t rA = (size_t)(row0 + wid * 32 + mt * 16 + qrow);
                size_t rB = rA + 8;
                softmax_store(out, rA, nP, lgP[mt][0], lgP[mt][1], tP0);
                softmax_store(out, rB, nP, lgP[mt][2], lgP[mt][3], tP2);
                softmax_store(out, rA, nQ, lgQ[mt][0], lgQ[mt][1], tQ0);
                softmax_store(out, rB, nQ, lgQ[mt][2], lgQ[mt][3], tQ2);
            }
        }
        __syncthreads();
    }
}

// ============================================================================
extern "C" void kernel_launch(void* const* d_in, const int* in_sizes, int n_in,
                              void* d_out, int out_size)
{
    const float* x   = (const float*)d_in[0];
    const float* Cw1 = (const float*)d_in[1];
    const float* Cb1 = (const float*)d_in[2];
    const float* Cw2 = (const float*)d_in[3];
    const float* Cb2 = (const float*)d_in[4];
    const float* Nw1 = (const float*)d_in[5];
    const float* Nb1 = (const float*)d_in[6];
    const float* Nw2 = (const float*)d_in[7];
    const float* Nb2 = (const float*)d_in[8];
    const float* Fw1 = (const float*)d_in[9];
    const float* Fb1 = (const float*)d_in[10];
    const float* Fw2 = (const float*)d_in[11];
    const float* Fb2 = (const float*)d_in[12];
    const float* Ow1 = (const float*)d_in[13];
    const float* Ob1 = (const float*)d_in[14];
    const float* Ow2 = (const float*)d_in[15];
    const float* Ob2 = (const float*)d_in[16];
    float* out = (float*)d_out;

    cudaFuncSetAttribute(k_features, cudaFuncAttributeMaxDynamicSharedMemorySize, SM_TOT);
    cudaFuncSetAttribute(k_ogemm,    cudaFuncAttributeMaxDynamicSharedMemorySize, OG_TOT);

    const int conv_elems = NB * 8192 + 4 * 8192 + NB * 1024;
    k_convert<<<(conv_elems + 255) / 256, 256>>>(Ow1, Ob1, Ow2, Nw1, Nb1, Nw2,
                                                 Fw1, Fb1, Fw2);

    k_features<<<NTILES, 128, SM_TOT>>>(x, Cw1, Cb1, Cw2, Cb2, Nb2, Fb2);

    dim3 grid2(NTILES / 2, 9);
    k_ogemm<<<grid2, 256, OG_TOT>>>(Ob2, out);
}

// round 12
// speedup vs baseline: 10.7175x; 1.0281x over previous
#include <cuda_runtime.h>
#include <cuda_fp16.h>
#include <cstdint>

#define NTILES 512
#define NB     54

// ========================= device scratch (fp16 images) =====================
__device__ __align__(16) __half g_w1h[NB * 8192];  // O_w1: [j=128][k=64], k57=Ob1
__device__ __align__(16) __half g_w2i[NB * 1024];  // O_w2: [n=8][k=128] (n<3 live)
__device__ __align__(16) __half g_bn1[8192];       // N_w1
__device__ __align__(16) __half g_bn2[8192];       // N_w2
__device__ __align__(16) __half g_bf1[8192];       // F_w1
__device__ __align__(16) __half g_bf2[8192];       // F_w2
__device__ __align__(16) __half g_fimg[NTILES * 8192]; // f images (swizzled, col57=1)

// ============================= PTX helpers =================================
__device__ __forceinline__ uint32_t smem_u32(const void* p) {
    uint32_t a;
    asm("{ .reg .u64 t; cvta.to.shared.u64 t, %1; cvt.u32.u64 %0, t; }"
        : "=r"(a) : "l"(p));
    return a;
}
__device__ __forceinline__ void ldsm_x4(uint32_t addr, uint32_t& r0, uint32_t& r1,
                                        uint32_t& r2, uint32_t& r3) {
    asm volatile("ldmatrix.sync.aligned.m8n8.x4.shared.b16 {%0,%1,%2,%3}, [%4];"
                 : "=r"(r0), "=r"(r1), "=r"(r2), "=r"(r3) : "r"(addr));
}
__device__ __forceinline__ void mma16816(float& d0, float& d1, float& d2, float& d3,
                                         uint32_t a0, uint32_t a1, uint32_t a2, uint32_t a3,
                                         uint32_t b0, uint32_t b1) {
    asm volatile("mma.sync.aligned.m16n8k16.row.col.f32.f16.f16.f32 "
                 "{%0,%1,%2,%3}, {%4,%5,%6,%7}, {%8,%9}, {%0,%1,%2,%3};"
                 : "+f"(d0), "+f"(d1), "+f"(d2), "+f"(d3)
                 : "r"(a0), "r"(a1), "r"(a2), "r"(a3), "r"(b0), "r"(b1));
}
__device__ __forceinline__ uint32_t sw128(uint32_t off) {
    return off ^ ((off >> 3) & 0x70);
}
__device__ __forceinline__ uint32_t packh2(float lo, float hi) {
    __half2 h = __floats2half2_rn(lo, hi);
    return *reinterpret_cast<uint32_t*>(&h);
}

// ============================================================================
// Convert weights -> swizzled fp16 images (biases baked at constant-1 k-col).
// ============================================================================
__global__ __launch_bounds__(256) void k_convert(
    const float* __restrict__ Ow1, const float* __restrict__ Ob1,
    const float* __restrict__ Ow2,
    const float* __restrict__ Nw1, const float* __restrict__ Nb1,
    const float* __restrict__ Nw2,
    const float* __restrict__ Fw1, const float* __restrict__ Fb1,
    const float* __restrict__ Fw2)
{
    int idx = blockIdx.x * 256 + threadIdx.x;
    if (idx < NB * 8192) {
        int j = idx & 127, k = (idx >> 7) & 63, n = idx >> 13;
        float v = (k < 57) ? Ow1[n * 7296 + k * 128 + j]
                 : (k == 57 ? Ob1[n * 128 + j] : 0.f);
        g_w1h[n * 8192 + (sw128((unsigned)(j * 128 + k * 2)) >> 1)] = __float2half(v);
        return;
    }
    int t = idx - NB * 8192;
    if (t < 4 * 8192) {
        int img = t >> 13, e = t & 8191;
        if (img == 0) {
            int j = e >> 6, k = e & 63;
            float v = (k < 54) ? Nw1[k * 128 + j] : (k == 54 ? Nb1[j] : 0.f);
            g_bn1[sw128((unsigned)(j * 128 + k * 2)) >> 1] = __float2half(v);
        } else if (img == 1) {
            int j = e >> 6, k = e & 63;
            float v = (k < 57) ? Fw1[k * 128 + j] : (k == 57 ? Fb1[j] : 0.f);
            g_bf1[sw128((unsigned)(j * 128 + k * 2)) >> 1] = __float2half(v);
        } else if (img == 2) {
            int m = e >> 7, k = e & 127;
            float v = (m < 54) ? Nw2[k * 54 + m] : 0.f;
            g_bn2[sw128((unsigned)(m * 256 + k * 2)) >> 1] = __float2half(v);
        } else {
            int m = e >> 7, k = e & 127;
            float v = (m < 57) ? Fw2[k * 57 + m] : 0.f;
            g_bf2[sw128((unsigned)(m * 256 + k * 2)) >> 1] = __float2half(v);
        }
        return;
    }
    t -= 4 * 8192;
    if (t >= NB * 1024) return;
    {
        int n = t >> 10, e = t & 1023;
        int m = e >> 7, k = e & 127;
        float v = (m < 3) ? Ow2[n * 384 + k * 3 + m] : 0.f;
        g_w2i[n * 1024 + (sw128((unsigned)(m * 256 + k * 2)) >> 1)] = __float2half(v);
    }
}

// ==================== features-kernel SMEM layout (91.2 KB, 2 CTAs/SM) ======
#define FX    0          // 16 KB: x/f image
#define FWA   16384      // 16 KB: weight buffer A
#define FWB   32768      // 16 KB: weight buffer B
#define FH0   49152      // 16 KB: hidden cols 0-63
#define FH1   65536      // 16 KB: hidden cols 64-127
#define FXC   81920      // 2048
#define FCW1  83968      // 2048
#define FCW2  86016      // 2048
#define FCB1  88064      // 512
#define FCB2  88576      // 32
#define FBN2  88608      // 256
#define FBF2  88864      // 256
#define FCP   89120      // 2048 (C-stage partials)
#define F_TOT 91168

// ---- 8-warp layer: 64-K HMMA, 128 out cols, relu (bias baked) -> H0/H1 -----
__device__ __forceinline__ void layer_wide8(
    uint32_t sA, uint32_t sB, char* h0, char* h1, int wid, int lane)
{
    const int m01 = (lane >> 3) & 1, kh = lane >> 4;
    const int quad = lane & 3, qrow = lane >> 2;
    const int bjrow = lane & 7, bkt = lane >> 4, bkh = (lane >> 3) & 1;
    const int rg = wid * 16 + (lane & 7) + (m01 << 3);

    uint32_t a[4][4];
#pragma unroll
    for (int kt = 0; kt < 4; ++kt) {
        uint32_t off = sw128((uint32_t)(rg * 128 + kt * 32 + kh * 16));
        ldsm_x4(sA + off, a[kt][0], a[kt][1], a[kt][2], a[kt][3]);
    }
#pragma unroll 4
    for (int nt = 0; nt < 16; ++nt) {
        uint32_t off0 = sw128((uint32_t)((nt * 8 + bjrow) * 128 + bkt * 32 + bkh * 16));
        uint32_t off1 = sw128((uint32_t)((nt * 8 + bjrow) * 128 + (bkt + 2) * 32 + bkh * 16));
        uint32_t b[4][2];
        ldsm_x4(sB + off0, b[0][0], b[0][1], b[1][0], b[1][1]);
        ldsm_x4(sB + off1, b[2][0], b[2][1], b[3][0], b[3][1]);
        float d0 = 0.f, d1 = 0.f, d2 = 0.f, d3 = 0.f;
#pragma unroll
        for (int kt = 0; kt < 4; ++kt)
            mma16816(d0, d1, d2, d3, a[kt][0], a[kt][1], a[kt][2], a[kt][3],
                     b[kt][0], b[kt][1]);
        int j0 = nt * 8 + quad * 2;
        char* himg = (j0 < 64) ? h0 : h1;
        int   jc   = j0 & 63;
        int rA = wid * 16 + qrow, rB = rA + 8;
        *(__half2*)(himg + sw128((uint32_t)(rA * 128 + jc * 2))) =
            __floats2half2_rn(fmaxf(d0, 0.f), fmaxf(d1, 0.f));
        *(__half2*)(himg + sw128((uint32_t)(rB * 128 + jc * 2))) =
            __floats2half2_rn(fmaxf(d2, 0.f), fmaxf(d3, 0.f));
    }
}

// ---- 8-warp layer: 128-K HMMA (H halves), bias, fp16 -> outimg -------------
__device__ __forceinline__ void layer_narrow8(
    uint32_t sH0, uint32_t sH1, uint32_t sB, const float* __restrict__ bias,
    char* outimg, int coff, int mlim, int ntn, int wid, int lane)
{
    const int m01 = (lane >> 3) & 1, kh = lane >> 4;
    const int quad = lane & 3, qrow = lane >> 2;
    const int bjrow = lane & 7, bkt = lane >> 4, bkh = (lane >> 3) & 1;
    const int rg = wid * 16 + (lane & 7) + (m01 << 3);

    uint32_t a[8][4];
#pragma unroll
    for (int kt = 0; kt < 8; ++kt) {
        uint32_t src = (kt < 4) ? sH0 : sH1;
        int      ktl = kt & 3;
        uint32_t off = sw128((uint32_t)(rg * 128 + ktl * 32 + kh * 16));
        ldsm_x4(src + off, a[kt][0], a[kt][1], a[kt][2], a[kt][3]);
    }
    for (int nt = 0; nt < ntn; ++nt) {
        uint32_t b[8][2];
#pragma unroll
        for (int q = 0; q < 4; ++q) {
            uint32_t off = sw128((uint32_t)((nt * 8 + bjrow) * 256 + q * 64 + bkt * 32 + bkh * 16));
            ldsm_x4(sB + off, b[2 * q][0], b[2 * q][1], b[2 * q + 1][0], b[2 * q + 1][1]);
        }
        float d0 = 0.f, d1 = 0.f, d2 = 0.f, d3 = 0.f;
#pragma unroll
        for (int kt = 0; kt < 8; ++kt)
            mma16816(d0, d1, d2, d3, a[kt][0], a[kt][1], a[kt][2], a[kt][3],
                     b[kt][0], b[kt][1]);
        int m0 = nt * 8 + quad * 2, m1 = m0 + 1;
        int rA = wid * 16 + qrow, rB = rA + 8;
        if (m0 < mlim) {
            *(__half*)(outimg + sw128((uint32_t)(rA * 128 + (m0 + coff) * 2))) =
                __float2half(d0 + bias[m0]);
            *(__half*)(outimg + sw128((uint32_t)(rB * 128 + (m0 + coff) * 2))) =
                __float2half(d2 + bias[m0]);
        }
        if (m1 < mlim) {
            *(__half*)(outimg + sw128((uint32_t)(rA * 128 + (m1 + coff) * 2))) =
                __float2half(d1 + bias[m1]);
            *(__half*)(outimg + sw128((uint32_t)(rB * 128 + (m1 + coff) * 2))) =
                __float2half(d3 + bias[m1]);
        }
    }
}

__device__ __forceinline__ void softmax_store(float* __restrict__ out,
                                              size_t row, int n,
                                              float l0, float l1, float l2)
{
    float mx = fmaxf(l0, fmaxf(l1, l2));
    float e0 = __expf(l0 - mx), e1 = __expf(l1 - mx), e2 = __expf(l2 - mx);
    float inv = 1.f / (e0 + e1 + e2);
    float* o = out + row * 162 + n * 3;
    o[0] = e0 * inv; o[1] = e1 * inv; o[2] = e2 * inv;
}

// ============================================================================
// Kernel 1: features, 256 threads / 8 warps, 128 rows; double-buffered weights.
// ============================================================================
__global__ void __launch_bounds__(256, 2) k_features(
    const float* __restrict__ x,
    const float* __restrict__ Cw1, const float* __restrict__ Cb1v,
    const float* __restrict__ Cw2, const float* __restrict__ Cb2v,
    const float* __restrict__ Nb2v, const float* __restrict__ Fb2v)
{
    extern __shared__ char smem[];
    const uint32_t sbase = smem_u32(smem);
    float* xc   = (float*)(smem + FXC);
    float* cw1t = (float*)(smem + FCW1);
    float* cw2  = (float*)(smem + FCW2);
    float* cb1  = (float*)(smem + FCB1);
    float* cb2  = (float*)(smem + FCB2);
    float* bn2  = (float*)(smem + FBN2);
    float* bf2  = (float*)(smem + FBF2);
    float* cp   = (float*)(smem + FCP);

    const int tid  = threadIdx.x;
    const int wid  = tid >> 5;
    const int lane = tid & 31;
    const int row0 = blockIdx.x * 128;

    // ---------------- phase 0: x image + Nw1/Nw2 + small consts -------------
    for (int i = tid; i < 128 * 58; i += 256) {
        int r = i / 58, c = i - r * 58;
        float v = x[(size_t)(row0 + r) * 58 + c];
        if (c < 4) xc[r * 4 + c] = v;
        else *(__half*)(smem + FX + sw128((uint32_t)(r * 128 + (c - 4) * 2))) =
                 __float2half(v);
    }
    for (int i = tid; i < 128 * 10; i += 256) {
        int r = i / 10, kk = 54 + (i - (i / 10) * 10);
        float v = (kk == 54 || kk == 57) ? 1.f : 0.f;
        *(__half*)(smem + FX + sw128((uint32_t)(r * 128 + kk * 2))) = __float2half(v);
    }
    {
        const uint4* sa = (const uint4*)g_bn1; uint4* da = (uint4*)(smem + FWA);
        const uint4* sb = (const uint4*)g_bn2; uint4* db = (uint4*)(smem + FWB);
#pragma unroll
        for (int i = 0; i < 4; ++i) {
            da[tid + 256 * i] = sa[tid + 256 * i];
            db[tid + 256 * i] = sb[tid + 256 * i];
        }
    }
    if (tid < 128) cb1[tid] = Cb1v[tid];
    else if (tid < 192) {
        int t = tid - 128;
        bn2[t] = (t < 54) ? Nb2v[t] : 0.f;
        bf2[t] = (t < 57) ? Fb2v[t] : 0.f;
    } else if (tid < 196) {
        int t = tid - 192;
        cb2[t] = (t < 3) ? Cb2v[t] : 0.f;
    }
    for (int i = tid; i < 512; i += 256) { int k = i >> 7, j = i & 127; cw1t[j * 4 + k] = Cw1[i]; }
    for (int i = tid; i < 384; i += 256) { int j = i / 3, m = i - j * 3; cw2[j * 4 + m] = Cw2[i]; }
    __syncthreads();

    // ---------------- stage C: 2 threads per row (split j) ------------------
    const int crow = tid & 127, cjh = tid >> 7;
    float c0, c1, c2;
    {
        float cx0 = xc[crow * 4 + 0], cx1 = xc[crow * 4 + 1];
        float cx2 = xc[crow * 4 + 2], cx3 = xc[crow * 4 + 3];
        c0 = cjh ? 0.f : cb2[0];
        c1 = cjh ? 0.f : cb2[1];
        c2 = cjh ? 0.f : cb2[2];
        const int j0 = cjh * 64;
        for (int j = j0; j < j0 + 64; ++j) {
            const float* w = &cw1t[j * 4];
            float h = cb1[j] + cx0 * w[0] + cx1 * w[1] + cx2 * w[2] + cx3 * w[3];
            h = fmaxf(h, 0.f);
            const float* w2 = &cw2[j * 4];
            c0 += h * w2[0]; c1 += h * w2[1]; c2 += h * w2[2];
        }
        if (cjh) {
            cp[crow * 4 + 0] = c0; cp[crow * 4 + 1] = c1; cp[crow * 4 + 2] = c2;
        }
    }

    // ---------------- N1: X @ Nw1(FWA) -> H ---------------------------------
    layer_wide8(sbase + FX, sbase + FWA, smem + FH0, smem + FH1, wid, lane);
    __syncthreads();

    // prefetch Fw1 -> FWA (overlaps N2), then N2: H @ Nw2(FWB) -> X cols 3..56
    {
        const uint4* s = (const uint4*)g_bf1; uint4* d = (uint4*)(smem + FWA);
#pragma unroll
        for (int i = 0; i < 4; ++i) d[tid + 256 * i] = s[tid + 256 * i];
    }
    layer_narrow8(sbase + FH0, sbase + FH1, sbase + FWB, bn2,
                  smem + FX, 3, 54, 7, wid, lane);
    if (!cjh) {     // c (combined) -> X cols 0..2
        float f0 = c0 + cp[crow * 4 + 0];
        float f1 = c1 + cp[crow * 4 + 1];
        float f2 = c2 + cp[crow * 4 + 2];
        *(__half*)(smem + FX + sw128((uint32_t)(crow * 128 + 0))) = __float2half(f0);
        *(__half*)(smem + FX + sw128((uint32_t)(crow * 128 + 2))) = __float2half(f1);
        *(__half*)(smem + FX + sw128((uint32_t)(crow * 128 + 4))) = __float2half(f2);
    }
    __syncthreads();

    // prefetch Fw2 -> FWB (overlaps F1), then F1: X @ Fw1(FWA) -> H
    {
        const uint4* s = (const uint4*)g_bf2; uint4* d = (uint4*)(smem + FWB);
#pragma unroll
        for (int i = 0; i < 4; ++i) d[tid + 256 * i] = s[tid + 256 * i];
    }
    layer_wide8(sbase + FX, sbase + FWA, smem + FH0, smem + FH1, wid, lane);
    __syncthreads();

    // F2: H @ Fw2(FWB) -> X cols 0..56 (col57 stays 1)
    layer_narrow8(sbase + FH0, sbase + FH1, sbase + FWB, bf2,
                  smem + FX, 0, 57, 8, wid, lane);
    __syncthreads();

    {
        const uint4* s = (const uint4*)(smem + FX);
        uint4* d = (uint4*)(g_fimg + (size_t)blockIdx.x * 8192);
#pragma unroll
        for (int i = 0; i < 4; ++i) d[tid + 256 * i] = s[tid + 256 * i];
    }
}

// ==================== O-kernel SMEM layout (106.5 KB, 2 CTAs/SM) ============
#define OG_A    0          // 32 KB: two A tile images
#define OG_B0   32768
#define OG_B1   49152
#define OG_B2   65536
#define OG_B3   81920
#define OG_W2S  98304      // 8 KB
#define OG_TOT  106496

// ============================================================================
// Kernel 2: O stage, 256 threads / 8 warps / 256 rows, 2 CTAs/SM.
// grid (256 row-tiles, 9 branch-groups); 3 branch-pairs per CTA. (R11 proven)
// ============================================================================
__global__ void __launch_bounds__(256, 2) k_ogemm(
    const float* __restrict__ Ob2, float* __restrict__ out)
{
    extern __shared__ char smem[];
    const uint32_t sbase = smem_u32(smem);

    const int tid  = threadIdx.x;
    const int wid  = tid >> 5;
    const int lane = tid & 31;
    const int row0 = blockIdx.x * 256;
    const int n0   = blockIdx.y * 6;

    {
        const uint4* sa = (const uint4*)(g_fimg + (size_t)blockIdx.x * 16384);
        uint4* dx = (uint4*)(smem + OG_A);
#pragma unroll
        for (int i = 0; i < 8; ++i) dx[tid + 256 * i] = sa[tid + 256 * i];
        const uint4* s0 = (const uint4*)(g_w1h + n0 * 8192);
        uint4* d0 = (uint4*)(smem + OG_B0);
#pragma unroll
        for (int i = 0; i < 8; ++i) d0[tid + 256 * i] = s0[tid + 256 * i];
        ((uint4*)(smem + OG_W2S))[tid] = ((const uint4*)(g_w2i + n0 * 1024))[tid];
    }
    __syncthreads();

    uint32_t a[2][4][4];
    {
        int m01 = (lane >> 3) & 1, kh = lane >> 4;
#pragma unroll
        for (int mt = 0; mt < 2; ++mt) {
            int rg = wid * 32 + mt * 16 + (lane & 7) + (m01 << 3);
            uint32_t base = sbase + OG_A + (uint32_t)(rg >> 7) * 16384;
            int rl = rg & 127;
#pragma unroll
            for (int kt = 0; kt < 4; ++kt) {
                uint32_t off = sw128((uint32_t)(rl * 128 + kt * 32 + kh * 16));
                ldsm_x4(base + off,
                        a[mt][kt][0], a[mt][kt][1], a[mt][kt][2], a[mt][kt][3]);
            }
        }
    }

    const int quad = lane & 3;
    const int qrow = lane >> 2;
    const int bjrow = lane & 7;
    const int bkt   = lane >> 4;
    const int bkh   = (lane >> 3) & 1;
    const uint32_t w2rowb = (uint32_t)((lane & 7) * 256 + (lane >> 3) * 16);

    for (int p = 0; p < 3; ++p) {
        const int buf = p & 1, nxt = buf ^ 1;
        const int nP = n0 + 2 * p, nQ = nP + 1;

        if (p < 2) {
            const uint4* s0 = (const uint4*)(g_w1h + (nP + 2) * 8192);
            uint4* d0 = (uint4*)(smem + (nxt ? OG_B2 : OG_B0));
#pragma unroll
            for (int i = 0; i < 8; ++i) d0[tid + 256 * i] = s0[tid + 256 * i];
            ((uint4*)(smem + OG_W2S + nxt * 4096))[tid] =
                ((const uint4*)(g_w2i + (nP + 2) * 1024))[tid];
        }

        const uint32_t sb0  = sbase + (buf ? OG_B2 : OG_B0);
        const uint32_t sb1  = sb0 + 16384;
        const uint32_t sw2P = sbase + OG_W2S + (uint32_t)buf * 4096;
        const uint32_t sw2Q = sw2P + 2048;

        float lgP[2][4], lgQ[2][4];
        {
            int cc0 = 2 * quad, cc1 = cc0 + 1;
            float p0 = (cc0 < 3) ? Ob2[nP * 3 + cc0] : 0.f;
            float p1 = (cc1 < 3) ? Ob2[nP * 3 + cc1] : 0.f;
            float q0 = (cc0 < 3) ? Ob2[nQ * 3 + cc0] : 0.f;
            float q1 = (cc1 < 3) ? Ob2[nQ * 3 + cc1] : 0.f;
#pragma unroll
            for (int mt = 0; mt < 2; ++mt) {
                lgP[mt][0] = p0; lgP[mt][1] = p1; lgP[mt][2] = p0; lgP[mt][3] = p1;
                lgQ[mt][0] = q0; lgQ[mt][1] = q1; lgQ[mt][2] = q0; lgQ[mt][3] = q1;
            }
        }

        uint32_t b2P[2][2], b2Q[2][2];
#pragma unroll
        for (int kt = 0; kt < 8; ++kt) {
            if ((kt & 1) == 0) {
                uint32_t off = sw128(w2rowb + (uint32_t)(kt >> 1) * 64);
                ldsm_x4(sw2P + off, b2P[0][0], b2P[0][1], b2P[1][0], b2P[1][1]);
                ldsm_x4(sw2Q + off, b2Q[0][0], b2Q[0][1], b2Q[1][0], b2Q[1][1]);
            }
            uint32_t a2P[2][4], a2Q[2][4];
#pragma unroll
            for (int e = 0; e < 2; ++e) {
                const int nt = 2 * kt + e;
                uint32_t off0 = sw128((uint32_t)((nt * 8 + bjrow) * 128 + bkt * 32 + bkh * 16));
                uint32_t off1 = sw128((uint32_t)((nt * 8 + bjrow) * 128 + (bkt + 2) * 32 + bkh * 16));
                uint32_t bP[4][2], bQ[4][2];
                ldsm_x4(sb0 + off0, bP[0][0], bP[0][1], bP[1][0], bP[1][1]);
                ldsm_x4(sb0 + off1, bP[2][0], bP[2][1], bP[3][0], bP[3][1]);
                ldsm_x4(sb1 + off0, bQ[0][0], bQ[0][1], bQ[1][0], bQ[1][1]);
                ldsm_x4(sb1 + off1, bQ[2][0], bQ[2][1], bQ[3][0], bQ[3][1]);
#pragma unroll
                for (int mt = 0; mt < 2; ++mt) {
                    float dP0 = 0.f, dP1 = 0.f, dP2 = 0.f, dP3 = 0.f;
                    float dQ0 = 0.f, dQ1 = 0.f, dQ2 = 0.f, dQ3 = 0.f;
#pragma unroll
                    for (int k4 = 0; k4 < 4; ++k4) {
                        mma16816(dP0, dP1, dP2, dP3,
                                 a[mt][k4][0], a[mt][k4][1], a[mt][k4][2], a[mt][k4][3],
                                 bP[k4][0], bP[k4][1]);
                        mma16816(dQ0, dQ1, dQ2, dQ3,
                                 a[mt][k4][0], a[mt][k4][1], a[mt][k4][2], a[mt][k4][3],
                                 bQ[k4][0], bQ[k4][1]);
                    }
                    a2P[mt][2 * e]     = packh2(fmaxf(dP0, 0.f), fmaxf(dP1, 0.f));
                    a2P[mt][2 * e + 1] = packh2(fmaxf(dP2, 0.f), fmaxf(dP3, 0.f));
                    a2Q[mt][2 * e]     = packh2(fmaxf(dQ0, 0.f), fmaxf(dQ1, 0.f));
                    a2Q[mt][2 * e + 1] = packh2(fmaxf(dQ2, 0.f), fmaxf(dQ3, 0.f));
                }
            }
#pragma unroll
            for (int mt = 0; mt < 2; ++mt) {
                mma16816(lgP[mt][0], lgP[mt][1], lgP[mt][2], lgP[mt][3],
                         a2P[mt][0], a2P[mt][1], a2P[mt][2], a2P[mt][3],
                         b2P[kt & 1][0], b2P[kt & 1][1]);
                mma16816(lgQ[mt][0], lgQ[mt][1], lgQ[mt][2], lgQ[mt][3],
                         a2Q[mt][0], a2Q[mt][1], a2Q[mt][2], a2Q[mt][3],
                         b2Q[kt & 1][0], b2Q[kt & 1][1]);
            }
        }

#pragma unroll
        for (int mt = 0; mt < 2; ++mt) {
            float tP0 = __shfl_xor_sync(0xffffffffu, lgP[mt][0], 1);
            float tP2 = __shfl_xor_sync(0xffffffffu, lgP[mt][2], 1);
            float tQ0 = __shfl_xor_sync(0xffffffffu, lgQ[mt][0], 1);
            float tQ2 = __shfl_xor_sync(0xffffffffu, lgQ[mt][2], 1);
            if (quad == 0) {
                size_t rA = (size_t)(row0 + wid * 32 + mt * 16 + qrow);
                size_t rB = rA + 8;
                softmax_store(out, rA, nP, lgP[mt][0], lgP[mt][1], tP0);
                softmax_store(out, rB, nP, lgP[mt][2], lgP[mt][3], tP2);
                softmax_store(out, rA, nQ, lgQ[mt][0], lgQ[mt][1], tQ0);
                softmax_store(out, rB, nQ, lgQ[mt][2], lgQ[mt][3], tQ2);
            }
        }
        __syncthreads();
    }
}

// ============================================================================
extern "C" void kernel_launch(void* const* d_in, const int* in_sizes, int n_in,
                              void* d_out, int out_size)
{
    const float* x   = (const float*)d_in[0];
    const float* Cw1 = (const float*)d_in[1];
    const float* Cb1 = (const float*)d_in[2];
    const float* Cw2 = (const float*)d_in[3];
    const float* Cb2 = (const float*)d_in[4];
    const float* Nw1 = (const float*)d_in[5];
    const float* Nb1 = (const float*)d_in[6];
    const float* Nw2 = (const float*)d_in[7];
    const float* Nb2 = (const float*)d_in[8];
    const float* Fw1 = (const float*)d_in[9];
    const float* Fb1 = (const float*)d_in[10];
    const float* Fw2 = (const float*)d_in[11];
    const float* Fb2 = (const float*)d_in[12];
    const float* Ow1 = (const float*)d_in[13];
    const float* Ob1 = (const float*)d_in[14];
    const float* Ow2 = (const float*)d_in[15];
    const float* Ob2 = (const float*)d_in[16];
    float* out = (float*)d_out;

    cudaFuncSetAttribute(k_features, cudaFuncAttributeMaxDynamicSharedMemorySize, F_TOT);
    cudaFuncSetAttribute(k_ogemm,    cudaFuncAttributeMaxDynamicSharedMemorySize, OG_TOT);

    const int conv_elems = NB * 8192 + 4 * 8192 + NB * 1024;
    k_convert<<<(conv_elems + 255) / 256, 256>>>(Ow1, Ob1, Ow2, Nw1, Nb1, Nw2,
                                                 Fw1, Fb1, Fw2);

    k_features<<<NTILES, 256, F_TOT>>>(x, Cw1, Cb1, Cw2, Cb2, Nb2, Fb2);

    dim3 grid2(NTILES / 2, 9);
    k_ogemm<<<grid2, 256, OG_TOT>>>(Ob2, out);
}